// round 4
// baseline (speedup 1.0000x reference)
#include <cuda_runtime.h>
#include <math.h>

#define NB 8
#define NL 1024
#define NS 1024
#define NG 64
#define ND 1024
#define NH 16
#define DH 64

// ---------------- scratch (device globals: no allocations allowed) ----------
__device__ float g_q  [NB*NH*NL*DH];   // (B,H,L,64)  -> becomes qe in-place
__device__ float g_k  [NB*NH*NS*DH];   // (B,H,S,64)
__device__ float g_v  [NB*NH*NS*DH];   // (B,H,S,64)
__device__ float g_rq [NB*NH*NG*DH];   // (B,H,G,64)
__device__ float g_rk [NB*NH*NG*DH];   // (B,H,G,64)
__device__ float g_wep[NB*NH*DH*DH];   // (B,H,64,64) (scale folded in)
__device__ float g_ot [NB*ND*NL];      // (B, H*64, L)  transposed attn output

// ---------------- generic 128x128x16 SGEMM, K=N=1024 ------------------------
// MODE 0: plain output Y[m*1024+n] + bias[n]
// MODE 1: head-split output: b=m/Ntok, t=m%Ntok, h=n/64, d=n%64
//         Y[((b*NH+h)*Ntok + t)*64 + d]
template<int MODE>
__global__ void __launch_bounds__(256) sgemm128(
    const float* __restrict__ A, const float* __restrict__ W,
    float* __restrict__ Y, const float* __restrict__ bias, int Ntok)
{
    __shared__ float As[16][128];
    __shared__ float Bs[16][128];
    const int tid = threadIdx.x;
    const int m0 = blockIdx.x * 128;
    const int n0 = blockIdx.y * 128;
    const int tx = tid & 15, ty = tid >> 4;

    float acc[8][8];
#pragma unroll
    for (int i = 0; i < 8; i++)
#pragma unroll
        for (int j = 0; j < 8; j++) acc[i][j] = 0.f;

    const int ar = tid >> 2;          // 0..63
    const int ac = (tid & 3) << 2;    // 0,4,8,12
    const int br = tid >> 5;          // 0..7
    const int bc = (tid & 31) << 2;   // 0..124

    for (int k0 = 0; k0 < 1024; k0 += 16) {
#pragma unroll
        for (int i = 0; i < 2; i++) {
            float4 va = *(const float4*)&A[(m0 + ar + i*64)*1024 + k0 + ac];
            As[ac+0][ar + i*64] = va.x;
            As[ac+1][ar + i*64] = va.y;
            As[ac+2][ar + i*64] = va.z;
            As[ac+3][ar + i*64] = va.w;
        }
#pragma unroll
        for (int i = 0; i < 2; i++) {
            *(float4*)&Bs[br + i*8][bc] =
                *(const float4*)&W[(k0 + br + i*8)*1024 + n0 + bc];
        }
        __syncthreads();
#pragma unroll
        for (int kk = 0; kk < 16; kk++) {
            float a[8], b[8];
            *(float4*)&a[0] = *(float4*)&As[kk][ty*8];
            *(float4*)&a[4] = *(float4*)&As[kk][ty*8+4];
            *(float4*)&b[0] = *(float4*)&Bs[kk][tx*8];
            *(float4*)&b[4] = *(float4*)&Bs[kk][tx*8+4];
#pragma unroll
            for (int i = 0; i < 8; i++)
#pragma unroll
                for (int j = 0; j < 8; j++)
                    acc[i][j] = fmaf(a[i], b[j], acc[i][j]);
        }
        __syncthreads();
    }

#pragma unroll
    for (int i = 0; i < 8; i++) {
        int m = m0 + ty*8 + i;
#pragma unroll
        for (int j4 = 0; j4 < 8; j4 += 4) {
            int n = n0 + tx*8 + j4;
            float4 r;
            r.x = acc[i][j4+0]; r.y = acc[i][j4+1];
            r.z = acc[i][j4+2]; r.w = acc[i][j4+3];
            if (MODE == 0) {
                float4 bb = *(const float4*)&bias[n];
                r.x += bb.x; r.y += bb.y; r.z += bb.z; r.w += bb.w;
                *(float4*)&Y[m*1024 + n] = r;
            } else {
                int b = m / Ntok, t = m - b*Ntok;
                int h = n >> 6, d = n & 63;
                *(float4*)&Y[(((b*NH + h)*Ntok + t) << 6) + d] = r;
            }
        }
    }
}

// ---------------- W_ep[b,h] = rq^T @ rk * scale ------------------------------
__global__ void __launch_bounds__(256) wep_kernel(
    const float* __restrict__ rq, const float* __restrict__ rk,
    float* __restrict__ wep)
{
    __shared__ float sq[64][65];
    __shared__ float sk[64][65];
    const int bh = blockIdx.x;
    const float* rqb = rq + (bh << 12);
    const float* rkb = rk + (bh << 12);
    const int tid = threadIdx.x;
#pragma unroll
    for (int i = 0; i < 4; i++) {
        int idx = (tid + i*256) << 2;
        int r = idx >> 6, c = idx & 63;
        float4 a = *(const float4*)&rqb[idx];
        float4 b = *(const float4*)&rkb[idx];
        sq[r][c] = a.x; sq[r][c+1] = a.y; sq[r][c+2] = a.z; sq[r][c+3] = a.w;
        sk[r][c] = b.x; sk[r][c+1] = b.y; sk[r][c+2] = b.z; sk[r][c+3] = b.w;
    }
    __syncthreads();
    const int tx = tid & 15, ty = tid >> 4;
    float acc[4][4];
#pragma unroll
    for (int i = 0; i < 4; i++)
#pragma unroll
        for (int j = 0; j < 4; j++) acc[i][j] = 0.f;
    for (int g = 0; g < 64; g++) {
        float a[4], b[4];
#pragma unroll
        for (int i = 0; i < 4; i++) a[i] = sq[g][ty*4+i];
#pragma unroll
        for (int j = 0; j < 4; j++) b[j] = sk[g][tx*4+j];
#pragma unroll
        for (int i = 0; i < 4; i++)
#pragma unroll
            for (int j = 0; j < 4; j++)
                acc[i][j] = fmaf(a[i], b[j], acc[i][j]);
    }
    const float scale = 0.125f;  // 1/sqrt(64)
#pragma unroll
    for (int i = 0; i < 4; i++) {
        float4 r4 = make_float4(acc[i][0]*scale, acc[i][1]*scale,
                                acc[i][2]*scale, acc[i][3]*scale);
        *(float4*)&wep[(bh << 12) + (ty*4+i)*64 + tx*4] = r4;
    }
}

// ---------------- q <- q @ W_ep (in place, per (b,h)) ------------------------
__global__ void __launch_bounds__(256) qfold_kernel(
    float* __restrict__ q, const float* __restrict__ wep)
{
    __shared__ float sq[64][65];
    __shared__ float sw[64][68];
    const int bh = blockIdx.y;
    const int l0 = blockIdx.x * 64;
    float* qb = q + (((size_t)bh * NL + l0) << 6);
    const float* wb = wep + (bh << 12);
    const int tid = threadIdx.x;
#pragma unroll
    for (int i = 0; i < 4; i++) {
        int idx = (tid + i*256) << 2;
        int r = idx >> 6, c = idx & 63;
        float4 vq = *(const float4*)&qb[idx];
        sq[r][c] = vq.x; sq[r][c+1] = vq.y; sq[r][c+2] = vq.z; sq[r][c+3] = vq.w;
        *(float4*)&sw[r][c] = *(const float4*)&wb[idx];
    }
    __syncthreads();
    const int tx = tid & 15, ty = tid >> 4;
    float acc[4][4];
#pragma unroll
    for (int i = 0; i < 4; i++)
#pragma unroll
        for (int j = 0; j < 4; j++) acc[i][j] = 0.f;
    for (int d = 0; d < 64; d++) {
        float a[4];
#pragma unroll
        for (int i = 0; i < 4; i++) a[i] = sq[ty*4+i][d];
        float4 wv = *(float4*)&sw[d][tx*4];
#pragma unroll
        for (int i = 0; i < 4; i++) {
            acc[i][0] = fmaf(a[i], wv.x, acc[i][0]);
            acc[i][1] = fmaf(a[i], wv.y, acc[i][1]);
            acc[i][2] = fmaf(a[i], wv.z, acc[i][2]);
            acc[i][3] = fmaf(a[i], wv.w, acc[i][3]);
        }
    }
    // all global reads are done (staged through smem) -> in-place write is safe
#pragma unroll
    for (int i = 0; i < 4; i++) {
        float4 r4 = make_float4(acc[i][0], acc[i][1], acc[i][2], acc[i][3]);
        *(float4*)&qb[((ty*4+i) << 6) + tx*4] = r4;
    }
}

// ---------------- flash attention: per (b,h), 64 q-rows per block -----------
// scores = qe @ k^T (scale already folded), online softmax, O = P @ V.
// Writes O transposed:  ot[b,h,d,l]  (layout (B, H*64, L)) for the final GEMM.
__global__ void __launch_bounds__(256) attn_kernel(
    const float* __restrict__ q, const float* __restrict__ k,
    const float* __restrict__ v, float* __restrict__ ot)
{
    __shared__ float s_qe[64][68];
    __shared__ float s_k [32][68];
    __shared__ float s_v [32][68];
    __shared__ float s_p [64][36];

    const int bh = blockIdx.y;
    const int l0 = blockIdx.x * 64;
    const float* qb = q + (((size_t)bh * NL + l0) << 6);
    const float* kb = k + (((size_t)bh * NS) << 6);
    const float* vb = v + (((size_t)bh * NS) << 6);
    float* otb = ot + (size_t)(bh << 6) * NL;

    const int tid = threadIdx.x;
    const int tx = tid & 15, ty = tid >> 4;

    // load qe tile (64x64)
#pragma unroll
    for (int i = 0; i < 4; i++) {
        int idx = (tid + i*256) << 2;
        int r = idx >> 6, c = idx & 63;
        *(float4*)&s_qe[r][c] = *(const float4*)&qb[idx];
    }

    float o[4][4];
#pragma unroll
    for (int i = 0; i < 4; i++)
#pragma unroll
        for (int j = 0; j < 4; j++) o[i][j] = 0.f;
    float mrow[4] = {-1e30f, -1e30f, -1e30f, -1e30f};
    float lrow[4] = {0.f, 0.f, 0.f, 0.f};

    for (int s0 = 0; s0 < NS; s0 += 32) {
        // load K,V chunk (32x64 each)
#pragma unroll
        for (int i = 0; i < 2; i++) {
            int idx = (tid + i*256) << 2;
            int r = idx >> 6, c = idx & 63;
            *(float4*)&s_k[r][c] = *(const float4*)&kb[(s0 << 6) + idx];
            *(float4*)&s_v[r][c] = *(const float4*)&vb[(s0 << 6) + idx];
        }
        __syncthreads();   // also orders the qe-tile stores on first iter

        // scores: rows ty*4+i (64), cols tx*2+j (32)
        float sc[4][2];
#pragma unroll
        for (int i = 0; i < 4; i++) { sc[i][0] = 0.f; sc[i][1] = 0.f; }
#pragma unroll
        for (int d4 = 0; d4 < 64; d4 += 4) {
            float qa[4][4], kk2[2][4];
#pragma unroll
            for (int i = 0; i < 4; i++)
                *(float4*)qa[i] = *(float4*)&s_qe[ty*4+i][d4];
#pragma unroll
            for (int j = 0; j < 2; j++)
                *(float4*)kk2[j] = *(float4*)&s_k[tx*2+j][d4];
#pragma unroll
            for (int i = 0; i < 4; i++)
#pragma unroll
                for (int j = 0; j < 2; j++)
#pragma unroll
                    for (int d = 0; d < 4; d++)
                        sc[i][j] = fmaf(qa[i][d], kk2[j][d], sc[i][j]);
        }

        // online softmax (row reductions across the 16 tx lanes)
#pragma unroll
        for (int i = 0; i < 4; i++) {
            float mx = fmaxf(sc[i][0], sc[i][1]);
#pragma unroll
            for (int off = 8; off >= 1; off >>= 1)
                mx = fmaxf(mx, __shfl_xor_sync(0xffffffffu, mx, off));
            float mnew = fmaxf(mrow[i], mx);
            float fac  = __expf(mrow[i] - mnew);
            mrow[i] = mnew;
            float rs = 0.f;
#pragma unroll
            for (int j = 0; j < 2; j++) {
                sc[i][j] = __expf(sc[i][j] - mnew);
                rs += sc[i][j];
            }
#pragma unroll
            for (int off = 8; off >= 1; off >>= 1)
                rs += __shfl_xor_sync(0xffffffffu, rs, off);
            lrow[i] = lrow[i]*fac + rs;
#pragma unroll
            for (int j = 0; j < 4; j++) o[i][j] *= fac;
            s_p[ty*4+i][tx*2+0] = sc[i][0];
            s_p[ty*4+i][tx*2+1] = sc[i][1];
        }
        __syncthreads();

        // O += P @ V : o[r=ty*4+i][d=tx*4+j]
#pragma unroll
        for (int c4 = 0; c4 < 32; c4 += 4) {
            float pa[4][4], vv[4][4];
#pragma unroll
            for (int i = 0; i < 4; i++)
                *(float4*)pa[i] = *(float4*)&s_p[ty*4+i][c4];
#pragma unroll
            for (int cc = 0; cc < 4; cc++)
                *(float4*)vv[cc] = *(float4*)&s_v[c4+cc][tx*4];
#pragma unroll
            for (int i = 0; i < 4; i++)
#pragma unroll
                for (int j = 0; j < 4; j++)
#pragma unroll
                    for (int cc = 0; cc < 4; cc++)
                        o[i][j] = fmaf(pa[i][cc], vv[cc][j], o[i][j]);
        }
        __syncthreads();
    }

    // normalize + transpose via smem staging (pitch 65 -> conflict-free)
    float* st = &s_qe[0][0];
#pragma unroll
    for (int i = 0; i < 4; i++) {
        float inv = 1.f / lrow[i];
#pragma unroll
        for (int j = 0; j < 4; j++)
            st[(ty*4+i)*65 + tx*4+j] = o[i][j] * inv;
    }
    __syncthreads();
#pragma unroll
    for (int it = 0; it < 16; it++) {
        int idx = tid + it*256;
        int d = idx >> 6, l = idx & 63;
        otb[d*NL + l0 + l] = st[l*65 + d];
    }
}

// ---------------- launch -----------------------------------------------------
extern "C" void kernel_launch(void* const* d_in, const int* in_sizes, int n_in,
                              void* d_out, int out_size)
{
    const float* queries = (const float*)d_in[0];
    const float* keys    = (const float*)d_in[1];
    const float* values  = (const float*)d_in[2];
    const float* routers = (const float*)d_in[3];
    const float* Wq  = (const float*)d_in[4];
    const float* Wk  = (const float*)d_in[5];
    const float* Wv  = (const float*)d_in[6];
    const float* Wlq = (const float*)d_in[7];
    const float* Wlk = (const float*)d_in[8];
    const float* Wo  = (const float*)d_in[9];
    const float* bo  = (const float*)d_in[10];

    float *q, *k, *v, *rq, *rk, *wep, *ot;
    cudaGetSymbolAddress((void**)&q,   g_q);
    cudaGetSymbolAddress((void**)&k,   g_k);
    cudaGetSymbolAddress((void**)&v,   g_v);
    cudaGetSymbolAddress((void**)&rq,  g_rq);
    cudaGetSymbolAddress((void**)&rk,  g_rk);
    cudaGetSymbolAddress((void**)&wep, g_wep);
    cudaGetSymbolAddress((void**)&ot,  g_ot);

    dim3 blk(256);
    sgemm128<1><<<dim3(64, 8), blk>>>(queries, Wq,  q,  nullptr, NL);
    sgemm128<1><<<dim3(64, 8), blk>>>(keys,    Wk,  k,  nullptr, NS);
    sgemm128<1><<<dim3(64, 8), blk>>>(values,  Wv,  v,  nullptr, NS);
    sgemm128<1><<<dim3(4, 8),  blk>>>(routers, Wlq, rq, nullptr, NG);
    sgemm128<1><<<dim3(4, 8),  blk>>>(routers, Wlk, rk, nullptr, NG);
    wep_kernel <<<128, blk>>>(rq, rk, wep);
    qfold_kernel<<<dim3(16, 128), blk>>>(q, wep);
    attn_kernel <<<dim3(16, 128), blk>>>(q, k, v, ot);
    sgemm128<0><<<dim3(64, 8), blk>>>(ot, Wo, (float*)d_out, bo, NL);
}

// round 5
// speedup vs baseline: 1.0015x; 1.0015x over previous
#include <cuda_runtime.h>
#include <math.h>

#define NB 8
#define NL 1024
#define NS 1024
#define NG 64
#define ND 1024
#define NH 16
#define DH 64

// ---------------- scratch (device globals: no allocations allowed) ----------
__device__ float g_q  [NB*NH*NL*DH];   // (B,H,L,64)  -> becomes qe in-place
__device__ float g_k  [NB*NH*NS*DH];   // (B,H,S,64)
__device__ float g_v  [NB*NH*NS*DH];   // (B,H,S,64)
__device__ float g_rq [NB*NH*NG*DH];   // (B,H,G,64)
__device__ float g_rk [NB*NH*NG*DH];   // (B,H,G,64)
__device__ float g_wep[NB*NH*DH*DH];   // (B,H,64,64) (scale folded in)
__device__ float g_ot [NB*ND*NL];      // (B, H*64, L)  transposed attn output

// ---------------- generic 128x128x16 SGEMM, K=N=1024 ------------------------
// MODE 0: plain output Y[m*1024+n] + bias[n]
// MODE 1: head-split output: b=m/Ntok, t=m%Ntok, h=n/64, d=n%64
//         Y[((b*NH+h)*Ntok + t)*64 + d]
template<int MODE>
__global__ void __launch_bounds__(256) sgemm128(
    const float* __restrict__ A, const float* __restrict__ W,
    float* __restrict__ Y, const float* __restrict__ bias, int Ntok)
{
    __shared__ float As[16][128];
    __shared__ float Bs[16][128];
    const int tid = threadIdx.x;
    const int m0 = blockIdx.x * 128;
    const int n0 = blockIdx.y * 128;
    const int tx = tid & 15, ty = tid >> 4;

    float acc[8][8];
#pragma unroll
    for (int i = 0; i < 8; i++)
#pragma unroll
        for (int j = 0; j < 8; j++) acc[i][j] = 0.f;

    const int ar = tid >> 2;          // 0..63
    const int ac = (tid & 3) << 2;    // 0,4,8,12
    const int br = tid >> 5;          // 0..7
    const int bc = (tid & 31) << 2;   // 0..124

    for (int k0 = 0; k0 < 1024; k0 += 16) {
#pragma unroll
        for (int i = 0; i < 2; i++) {
            float4 va = *(const float4*)&A[(m0 + ar + i*64)*1024 + k0 + ac];
            As[ac+0][ar + i*64] = va.x;
            As[ac+1][ar + i*64] = va.y;
            As[ac+2][ar + i*64] = va.z;
            As[ac+3][ar + i*64] = va.w;
        }
#pragma unroll
        for (int i = 0; i < 2; i++) {
            *(float4*)&Bs[br + i*8][bc] =
                *(const float4*)&W[(k0 + br + i*8)*1024 + n0 + bc];
        }
        __syncthreads();
#pragma unroll
        for (int kk = 0; kk < 16; kk++) {
            float a[8], b[8];
            *(float4*)&a[0] = *(float4*)&As[kk][ty*8];
            *(float4*)&a[4] = *(float4*)&As[kk][ty*8+4];
            *(float4*)&b[0] = *(float4*)&Bs[kk][tx*8];
            *(float4*)&b[4] = *(float4*)&Bs[kk][tx*8+4];
#pragma unroll
            for (int i = 0; i < 8; i++)
#pragma unroll
                for (int j = 0; j < 8; j++)
                    acc[i][j] = fmaf(a[i], b[j], acc[i][j]);
        }
        __syncthreads();
    }

#pragma unroll
    for (int i = 0; i < 8; i++) {
        int m = m0 + ty*8 + i;
#pragma unroll
        for (int j4 = 0; j4 < 8; j4 += 4) {
            int n = n0 + tx*8 + j4;
            float4 r;
            r.x = acc[i][j4+0]; r.y = acc[i][j4+1];
            r.z = acc[i][j4+2]; r.w = acc[i][j4+3];
            if (MODE == 0) {
                float4 bb = *(const float4*)&bias[n];
                r.x += bb.x; r.y += bb.y; r.z += bb.z; r.w += bb.w;
                *(float4*)&Y[m*1024 + n] = r;
            } else {
                int b = m / Ntok, t = m - b*Ntok;
                int h = n >> 6, d = n & 63;
                *(float4*)&Y[(((b*NH + h)*Ntok + t) << 6) + d] = r;
            }
        }
    }
}

// ---------------- W_ep[b,h] = rq^T @ rk * scale ------------------------------
__global__ void __launch_bounds__(256) wep_kernel(
    const float* __restrict__ rq, const float* __restrict__ rk,
    float* __restrict__ wep)
{
    __shared__ float sq[64][65];
    __shared__ float sk[64][65];
    const int bh = blockIdx.x;
    const float* rqb = rq + (bh << 12);
    const float* rkb = rk + (bh << 12);
    const int tid = threadIdx.x;
#pragma unroll
    for (int i = 0; i < 4; i++) {
        int idx = (tid + i*256) << 2;
        int r = idx >> 6, c = idx & 63;
        float4 a = *(const float4*)&rqb[idx];
        float4 b = *(const float4*)&rkb[idx];
        sq[r][c] = a.x; sq[r][c+1] = a.y; sq[r][c+2] = a.z; sq[r][c+3] = a.w;
        sk[r][c] = b.x; sk[r][c+1] = b.y; sk[r][c+2] = b.z; sk[r][c+3] = b.w;
    }
    __syncthreads();
    const int tx = tid & 15, ty = tid >> 4;
    float acc[4][4];
#pragma unroll
    for (int i = 0; i < 4; i++)
#pragma unroll
        for (int j = 0; j < 4; j++) acc[i][j] = 0.f;
    for (int g = 0; g < 64; g++) {
        float a[4], b[4];
#pragma unroll
        for (int i = 0; i < 4; i++) a[i] = sq[g][ty*4+i];
#pragma unroll
        for (int j = 0; j < 4; j++) b[j] = sk[g][tx*4+j];
#pragma unroll
        for (int i = 0; i < 4; i++)
#pragma unroll
            for (int j = 0; j < 4; j++)
                acc[i][j] = fmaf(a[i], b[j], acc[i][j]);
    }
    const float scale = 0.125f;  // 1/sqrt(64)
#pragma unroll
    for (int i = 0; i < 4; i++) {
        float4 r4 = make_float4(acc[i][0]*scale, acc[i][1]*scale,
                                acc[i][2]*scale, acc[i][3]*scale);
        *(float4*)&wep[(bh << 12) + (ty*4+i)*64 + tx*4] = r4;
    }
}

// ---------------- q <- q @ W_ep (in place, per (b,h)) ------------------------
__global__ void __launch_bounds__(256) qfold_kernel(
    float* __restrict__ q, const float* __restrict__ wep)
{
    __shared__ float sq[64][65];
    __shared__ float sw[64][68];
    const int bh = blockIdx.y;
    const int l0 = blockIdx.x * 64;
    float* qb = q + (((size_t)bh * NL + l0) << 6);
    const float* wb = wep + (bh << 12);
    const int tid = threadIdx.x;
#pragma unroll
    for (int i = 0; i < 4; i++) {
        int idx = (tid + i*256) << 2;
        int r = idx >> 6, c = idx & 63;
        float4 vq = *(const float4*)&qb[idx];
        sq[r][c] = vq.x; sq[r][c+1] = vq.y; sq[r][c+2] = vq.z; sq[r][c+3] = vq.w;
        *(float4*)&sw[r][c] = *(const float4*)&wb[idx];
    }
    __syncthreads();
    const int tx = tid & 15, ty = tid >> 4;
    float acc[4][4];
#pragma unroll
    for (int i = 0; i < 4; i++)
#pragma unroll
        for (int j = 0; j < 4; j++) acc[i][j] = 0.f;
    for (int d = 0; d < 64; d++) {
        float a[4];
#pragma unroll
        for (int i = 0; i < 4; i++) a[i] = sq[ty*4+i][d];
        float4 wv = *(float4*)&sw[d][tx*4];
#pragma unroll
        for (int i = 0; i < 4; i++) {
            acc[i][0] = fmaf(a[i], wv.x, acc[i][0]);
            acc[i][1] = fmaf(a[i], wv.y, acc[i][1]);
            acc[i][2] = fmaf(a[i], wv.z, acc[i][2]);
            acc[i][3] = fmaf(a[i], wv.w, acc[i][3]);
        }
    }
    // all global reads are done (staged through smem) -> in-place write is safe
#pragma unroll
    for (int i = 0; i < 4; i++) {
        float4 r4 = make_float4(acc[i][0], acc[i][1], acc[i][2], acc[i][3]);
        *(float4*)&qb[((ty*4+i) << 6) + tx*4] = r4;
    }
}

// ---------------- flash attention: per (b,h), 64 q-rows per block -----------
// scores = qe @ k^T (scale already folded), online softmax, O = P @ V.
// Writes O transposed:  ot[b,h,d,l]  (layout (B, H*64, L)) for the final GEMM.
__global__ void __launch_bounds__(256) attn_kernel(
    const float* __restrict__ q, const float* __restrict__ k,
    const float* __restrict__ v, float* __restrict__ ot)
{
    __shared__ float s_qe[64][68];
    __shared__ float s_k [32][68];
    __shared__ float s_v [32][68];
    __shared__ float s_p [64][36];

    const int bh = blockIdx.y;
    const int l0 = blockIdx.x * 64;
    const float* qb = q + (((size_t)bh * NL + l0) << 6);
    const float* kb = k + (((size_t)bh * NS) << 6);
    const float* vb = v + (((size_t)bh * NS) << 6);
    float* otb = ot + (size_t)(bh << 6) * NL;

    const int tid = threadIdx.x;
    const int tx = tid & 15, ty = tid >> 4;

    // load qe tile (64x64)
#pragma unroll
    for (int i = 0; i < 4; i++) {
        int idx = (tid + i*256) << 2;
        int r = idx >> 6, c = idx & 63;
        *(float4*)&s_qe[r][c] = *(const float4*)&qb[idx];
    }

    float o[4][4];
#pragma unroll
    for (int i = 0; i < 4; i++)
#pragma unroll
        for (int j = 0; j < 4; j++) o[i][j] = 0.f;
    float mrow[4] = {-1e30f, -1e30f, -1e30f, -1e30f};
    float lrow[4] = {0.f, 0.f, 0.f, 0.f};

    for (int s0 = 0; s0 < NS; s0 += 32) {
        // load K,V chunk (32x64 each)
#pragma unroll
        for (int i = 0; i < 2; i++) {
            int idx = (tid + i*256) << 2;
            int r = idx >> 6, c = idx & 63;
            *(float4*)&s_k[r][c] = *(const float4*)&kb[(s0 << 6) + idx];
            *(float4*)&s_v[r][c] = *(const float4*)&vb[(s0 << 6) + idx];
        }
        __syncthreads();   // also orders the qe-tile stores on first iter

        // scores: rows ty*4+i (64), cols tx*2+j (32)
        float sc[4][2];
#pragma unroll
        for (int i = 0; i < 4; i++) { sc[i][0] = 0.f; sc[i][1] = 0.f; }
#pragma unroll
        for (int d4 = 0; d4 < 64; d4 += 4) {
            float qa[4][4], kk2[2][4];
#pragma unroll
            for (int i = 0; i < 4; i++)
                *(float4*)qa[i] = *(float4*)&s_qe[ty*4+i][d4];
#pragma unroll
            for (int j = 0; j < 2; j++)
                *(float4*)kk2[j] = *(float4*)&s_k[tx*2+j][d4];
#pragma unroll
            for (int i = 0; i < 4; i++)
#pragma unroll
                for (int j = 0; j < 2; j++)
#pragma unroll
                    for (int d = 0; d < 4; d++)
                        sc[i][j] = fmaf(qa[i][d], kk2[j][d], sc[i][j]);
        }

        // online softmax (row reductions across the 16 tx lanes)
#pragma unroll
        for (int i = 0; i < 4; i++) {
            float mx = fmaxf(sc[i][0], sc[i][1]);
#pragma unroll
            for (int off = 8; off >= 1; off >>= 1)
                mx = fmaxf(mx, __shfl_xor_sync(0xffffffffu, mx, off));
            float mnew = fmaxf(mrow[i], mx);
            float fac  = __expf(mrow[i] - mnew);
            mrow[i] = mnew;
            float rs = 0.f;
#pragma unroll
            for (int j = 0; j < 2; j++) {
                sc[i][j] = __expf(sc[i][j] - mnew);
                rs += sc[i][j];
            }
#pragma unroll
            for (int off = 8; off >= 1; off >>= 1)
                rs += __shfl_xor_sync(0xffffffffu, rs, off);
            lrow[i] = lrow[i]*fac + rs;
#pragma unroll
            for (int j = 0; j < 4; j++) o[i][j] *= fac;
            s_p[ty*4+i][tx*2+0] = sc[i][0];
            s_p[ty*4+i][tx*2+1] = sc[i][1];
        }
        __syncthreads();

        // O += P @ V : o[r=ty*4+i][d=tx*4+j]
#pragma unroll
        for (int c4 = 0; c4 < 32; c4 += 4) {
            float pa[4][4], vv[4][4];
#pragma unroll
            for (int i = 0; i < 4; i++)
                *(float4*)pa[i] = *(float4*)&s_p[ty*4+i][c4];
#pragma unroll
            for (int cc = 0; cc < 4; cc++)
                *(float4*)vv[cc] = *(float4*)&s_v[c4+cc][tx*4];
#pragma unroll
            for (int i = 0; i < 4; i++)
#pragma unroll
                for (int j = 0; j < 4; j++)
#pragma unroll
                    for (int cc = 0; cc < 4; cc++)
                        o[i][j] = fmaf(pa[i][cc], vv[cc][j], o[i][j]);
        }
        __syncthreads();
    }

    // normalize + transpose via smem staging (pitch 65 -> conflict-free)
    float* st = &s_qe[0][0];
#pragma unroll
    for (int i = 0; i < 4; i++) {
        float inv = 1.f / lrow[i];
#pragma unroll
        for (int j = 0; j < 4; j++)
            st[(ty*4+i)*65 + tx*4+j] = o[i][j] * inv;
    }
    __syncthreads();
#pragma unroll
    for (int it = 0; it < 16; it++) {
        int idx = tid + it*256;
        int d = idx >> 6, l = idx & 63;
        otb[d*NL + l0 + l] = st[l*65 + d];
    }
}

// ---------------- launch -----------------------------------------------------
extern "C" void kernel_launch(void* const* d_in, const int* in_sizes, int n_in,
                              void* d_out, int out_size)
{
    const float* queries = (const float*)d_in[0];
    const float* keys    = (const float*)d_in[1];
    const float* values  = (const float*)d_in[2];
    const float* routers = (const float*)d_in[3];
    const float* Wq  = (const float*)d_in[4];
    const float* Wk  = (const float*)d_in[5];
    const float* Wv  = (const float*)d_in[6];
    const float* Wlq = (const float*)d_in[7];
    const float* Wlk = (const float*)d_in[8];
    const float* Wo  = (const float*)d_in[9];
    const float* bo  = (const float*)d_in[10];

    float *q, *k, *v, *rq, *rk, *wep, *ot;
    cudaGetSymbolAddress((void**)&q,   g_q);
    cudaGetSymbolAddress((void**)&k,   g_k);
    cudaGetSymbolAddress((void**)&v,   g_v);
    cudaGetSymbolAddress((void**)&rq,  g_rq);
    cudaGetSymbolAddress((void**)&rk,  g_rk);
    cudaGetSymbolAddress((void**)&wep, g_wep);
    cudaGetSymbolAddress((void**)&ot,  g_ot);

    dim3 blk(256);
    sgemm128<1><<<dim3(64, 8), blk>>>(queries, Wq,  q,  nullptr, NL);
    sgemm128<1><<<dim3(64, 8), blk>>>(keys,    Wk,  k,  nullptr, NS);
    sgemm128<1><<<dim3(64, 8), blk>>>(values,  Wv,  v,  nullptr, NS);
    sgemm128<1><<<dim3(4, 8),  blk>>>(routers, Wlq, rq, nullptr, NG);
    sgemm128<1><<<dim3(4, 8),  blk>>>(routers, Wlk, rk, nullptr, NG);
    wep_kernel <<<128, blk>>>(rq, rk, wep);
    qfold_kernel<<<dim3(16, 128), blk>>>(q, wep);
    attn_kernel <<<dim3(16, 128), blk>>>(q, k, v, ot);
    sgemm128<0><<<dim3(64, 8), blk>>>(ot, Wo, (float*)d_out, bo, NL);
}

// round 7
// speedup vs baseline: 1.7277x; 1.7251x over previous
#include <cuda_runtime.h>
#include <cuda_bf16.h>
#include <math.h>
#include <stdint.h>

#define NB 8
#define NL 1024
#define NS 1024
#define NG 64
#define ND 1024
#define NH 16
#define DH 64

// ---------------- scratch (device globals: no allocations allowed) ----------
__device__ float g_q  [NB*NH*NL*DH];   // (B,H,L,64)  -> becomes qe in-place
__device__ float g_k  [NB*NH*NS*DH];   // (B,H,S,64)
__device__ float g_v  [NB*NH*NS*DH];   // (B,H,S,64)
__device__ float g_rq [NB*NH*NG*DH];
__device__ float g_rk [NB*NH*NG*DH];
__device__ float g_wep[NB*NH*DH*DH];
__device__ float g_ot [NB*ND*NL];      // (B, H*64, L) transposed attn output
__device__ float g_S  [(size_t)NB*NH*NL*NS]; // scores -> probs in place

// ---------------- helpers ----------------------------------------------------
__device__ __forceinline__ uint32_t smem_u32(const void* p){
    uint32_t a;
    asm("{ .reg .u64 t; cvta.to.shared.u64 t, %1; cvt.u32.u64 %0, t; }"
        : "=r"(a) : "l"(p));
    return a;
}
#define SW128(o) ((o) ^ (((o) >> 3) & 0x70))

__device__ __forceinline__ void ldsm4(uint32_t* r, uint32_t a){
    asm volatile("ldmatrix.sync.aligned.m8n8.x4.shared.b16 {%0,%1,%2,%3}, [%4];"
        : "=r"(r[0]), "=r"(r[1]), "=r"(r[2]), "=r"(r[3]) : "r"(a));
}
__device__ __forceinline__ void mma_bf16(float* c, const uint32_t* a, const uint32_t* b){
    asm volatile("mma.sync.aligned.m16n8k16.row.col.f32.bf16.bf16.f32 "
        "{%0,%1,%2,%3}, {%4,%5,%6,%7}, {%8,%9}, {%0,%1,%2,%3};"
        : "+f"(c[0]), "+f"(c[1]), "+f"(c[2]), "+f"(c[3])
        : "r"(a[0]), "r"(a[1]), "r"(a[2]), "r"(a[3]), "r"(b[0]), "r"(b[1]));
}

// split floats (x,y) into packed bf16x2 hi and lo parts (x in low half)
__device__ __forceinline__ void split2(float x, float y, uint32_t& hi, uint32_t& lo){
    __nv_bfloat16 xh = __float2bfloat16(x);
    __nv_bfloat16 yh = __float2bfloat16(y);
    __nv_bfloat16 xl = __float2bfloat16(x - __bfloat162float(xh));
    __nv_bfloat16 yl = __float2bfloat16(y - __bfloat162float(yh));
    hi = (uint32_t)__bfloat16_as_ushort(xh) | ((uint32_t)__bfloat16_as_ushort(yh) << 16);
    lo = (uint32_t)__bfloat16_as_ushort(xl) | ((uint32_t)__bfloat16_as_ushort(yl) << 16);
}

// smem tile layout (bf16, K-major, 64 k = 128B rows, SW128):
//   A_hi @0, A_lo @16384, B_hi @32768, B_lo @(32768+Bbytes)

// ============= mm_proj: Y(Mx1024) = A(Mx1024) @ W(1024x1024) =================
// block 128x128, 8 warps (2x4) of 64x32 warp tiles, K chunked by 64.
// MODE 0: Y[m*1024+n]+bias[n].  MODE 1: head-split scatter (Ntok tokens/batch).
template<int MODE>
__global__ void __launch_bounds__(256,1) mm_proj(
    const float* __restrict__ A, const float* __restrict__ W,
    float* __restrict__ Y, const float* __restrict__ bias, int Ntok)
{
    extern __shared__ char smem[];
    const uint32_t sb = smem_u32(smem);
    const int tid = threadIdx.x, lid = tid & 31, wid = tid >> 5;
    const int m0 = blockIdx.x*128, n0 = blockIdx.y*128;
    const int m0w = (wid & 1)*64, n0w = (wid >> 1)*32;

    const int a_row = (lid & 7) + ((lid >> 3) & 1)*8;
    const int a_kb  = (lid >> 4)*16;
    const int b_row = (lid & 7) + ((lid >> 4) & 1)*8;
    const int b_kb  = ((lid >> 3) & 1)*16;

    float acc[4][4][4];
#pragma unroll
    for (int i = 0; i < 4; i++)
#pragma unroll
        for (int j = 0; j < 4; j++)
#pragma unroll
            for (int e = 0; e < 4; e++) acc[i][j][e] = 0.f;

    for (int s = 0; s < 16; s++) {
        const int k0 = s*64;
        __syncthreads();
        // ---- A tile: 128 rows x 64 k ----
        {
            const float* Ab = A + (size_t)m0*1024 + k0;
#pragma unroll
            for (int i = 0; i < 4; i++) {
                int f = tid + i*256;
                int row = f >> 3, c8 = f & 7;
                const float* p = Ab + (size_t)row*1024 + c8*8;
                float4 a = *(const float4*)p, c = *(const float4*)(p+4);
                uint32_t h0,l0v,h1,l1v,h2,l2v,h3,l3v;
                split2(a.x,a.y,h0,l0v); split2(a.z,a.w,h1,l1v);
                split2(c.x,c.y,h2,l2v); split2(c.z,c.w,h3,l3v);
                uint32_t swo = SW128((uint32_t)(row*128 + c8*16));
                *(uint4*)(smem + swo)         = make_uint4(h0,h1,h2,h3);
                *(uint4*)(smem + 16384 + swo) = make_uint4(l0v,l1v,l2v,l3v);
            }
        }
        // ---- B tile: B[n][k] = W[k][n], 128 n-rows x 64 k ----
        {
            const int bc = tid & 127, bg = tid >> 7;
#pragma unroll
            for (int it = 0; it < 8; it++) {
                int kk = (bg + it*2)*4;
                const float* p = W + (size_t)(k0+kk)*1024 + n0 + bc;
                float w0 = p[0], w1 = p[1024], w2 = p[2048], w3 = p[3072];
                uint32_t h0,l0v,h1,l1v;
                split2(w0,w1,h0,l0v); split2(w2,w3,h1,l1v);
                uint32_t swo = SW128((uint32_t)(bc*128 + kk*2));
                *(uint2*)(smem + 32768 + swo) = make_uint2(h0,h1);
                *(uint2*)(smem + 49152 + swo) = make_uint2(l0v,l1v);
            }
        }
        __syncthreads();
        // ---- compute: 4 ksteps of 16 ----
#pragma unroll
        for (int kk = 0; kk < 64; kk += 16) {
            uint32_t ah[4][4], al[4][4], bh[4][2], bl[4][2];
#pragma unroll
            for (int mt = 0; mt < 4; mt++) {
                uint32_t off = SW128((uint32_t)((m0w + mt*16 + a_row)*128 + kk*2 + a_kb));
                ldsm4(ah[mt], sb + off);
                ldsm4(al[mt], sb + 16384 + off);
            }
#pragma unroll
            for (int np = 0; np < 2; np++) {
                uint32_t off = SW128((uint32_t)((n0w + np*16 + b_row)*128 + kk*2 + b_kb));
                uint32_t t[4];
                ldsm4(t, sb + 32768 + off);
                bh[np*2][0]=t[0]; bh[np*2][1]=t[1]; bh[np*2+1][0]=t[2]; bh[np*2+1][1]=t[3];
                ldsm4(t, sb + 49152 + off);
                bl[np*2][0]=t[0]; bl[np*2][1]=t[1]; bl[np*2+1][0]=t[2]; bl[np*2+1][1]=t[3];
            }
#pragma unroll
            for (int mt = 0; mt < 4; mt++)
#pragma unroll
                for (int nt = 0; nt < 4; nt++) {
                    mma_bf16(acc[mt][nt], ah[mt], bh[nt]);
                    mma_bf16(acc[mt][nt], ah[mt], bl[nt]);
                    mma_bf16(acc[mt][nt], al[mt], bh[nt]);
                }
        }
    }
    __syncthreads();
    // ---- epilogue: stage fp32 (pitch 132) -> coalesced write ----
    float* stg = (float*)smem;
    const int g = lid >> 2, tg = lid & 3;
#pragma unroll
    for (int mt = 0; mt < 4; mt++)
#pragma unroll
        for (int nt = 0; nt < 4; nt++) {
            int r = m0w + mt*16 + g, c = n0w + nt*8 + tg*2;
            *(float2*)&stg[r*132 + c]     = make_float2(acc[mt][nt][0], acc[mt][nt][1]);
            *(float2*)&stg[(r+8)*132 + c] = make_float2(acc[mt][nt][2], acc[mt][nt][3]);
        }
    __syncthreads();
#pragma unroll
    for (int i = 0; i < 16; i++) {
        int f = tid + i*256;
        int r = f >> 5, c4 = f & 31;
        float4 val = *(float4*)&stg[r*132 + c4*4];
        int m = m0 + r, n = n0 + c4*4;
        if (MODE == 0) {
            float4 bb = *(const float4*)&bias[n];
            val.x += bb.x; val.y += bb.y; val.z += bb.z; val.w += bb.w;
            *(float4*)&Y[(size_t)m*1024 + n] = val;
        } else {
            int bq = m / Ntok, t = m - bq*Ntok;
            int h = n >> 6, d = n & 63;
            *(float4*)&Y[(size_t)((bq*NH + h)*Ntok + t)*64 + d] = val;
        }
    }
}

// ============= mm_scores: S tile (128x128) = qe(128x64) @ k(128x64)^T ========
__global__ void __launch_bounds__(256,1) mm_scores(
    const float* __restrict__ q, const float* __restrict__ k, float* __restrict__ S)
{
    extern __shared__ char smem[];
    const uint32_t sb = smem_u32(smem);
    const int tid = threadIdx.x, lid = tid & 31, wid = tid >> 5;
    const int l0 = blockIdx.x*128, s0 = blockIdx.y*128, bh = blockIdx.z;
    const int m0w = (wid & 1)*64, n0w = (wid >> 1)*32;

    const int a_row = (lid & 7) + ((lid >> 3) & 1)*8;
    const int a_kb  = (lid >> 4)*16;
    const int b_row = (lid & 7) + ((lid >> 4) & 1)*8;
    const int b_kb  = ((lid >> 3) & 1)*16;

    const float* qb = q + ((size_t)bh*NL + l0)*64;
    const float* kb = k + ((size_t)bh*NS + s0)*64;
#pragma unroll
    for (int i = 0; i < 4; i++) {
        int f = tid + i*256;
        int row = f >> 3, c8 = f & 7;
        uint32_t swo = SW128((uint32_t)(row*128 + c8*16));
        const float* pq = qb + (size_t)row*64 + c8*8;
        float4 a = *(const float4*)pq, c = *(const float4*)(pq+4);
        uint32_t h0,l0v,h1,l1v,h2,l2v,h3,l3v;
        split2(a.x,a.y,h0,l0v); split2(a.z,a.w,h1,l1v);
        split2(c.x,c.y,h2,l2v); split2(c.z,c.w,h3,l3v);
        *(uint4*)(smem + swo)         = make_uint4(h0,h1,h2,h3);
        *(uint4*)(smem + 16384 + swo) = make_uint4(l0v,l1v,l2v,l3v);
        const float* pk = kb + (size_t)row*64 + c8*8;
        float4 e = *(const float4*)pk, gg = *(const float4*)(pk+4);
        split2(e.x,e.y,h0,l0v); split2(e.z,e.w,h1,l1v);
        split2(gg.x,gg.y,h2,l2v); split2(gg.z,gg.w,h3,l3v);
        *(uint4*)(smem + 32768 + swo) = make_uint4(h0,h1,h2,h3);
        *(uint4*)(smem + 49152 + swo) = make_uint4(l0v,l1v,l2v,l3v);
    }
    __syncthreads();

    float acc[4][4][4];
#pragma unroll
    for (int i = 0; i < 4; i++)
#pragma unroll
        for (int j = 0; j < 4; j++)
#pragma unroll
            for (int e = 0; e < 4; e++) acc[i][j][e] = 0.f;

#pragma unroll
    for (int kk = 0; kk < 64; kk += 16) {
        uint32_t ah[4][4], al[4][4], bh[4][2], bl[4][2];
#pragma unroll
        for (int mt = 0; mt < 4; mt++) {
            uint32_t off = SW128((uint32_t)((m0w + mt*16 + a_row)*128 + kk*2 + a_kb));
            ldsm4(ah[mt], sb + off);
            ldsm4(al[mt], sb + 16384 + off);
        }
#pragma unroll
        for (int np = 0; np < 2; np++) {
            uint32_t off = SW128((uint32_t)((n0w + np*16 + b_row)*128 + kk*2 + b_kb));
            uint32_t t[4];
            ldsm4(t, sb + 32768 + off);
            bh[np*2][0]=t[0]; bh[np*2][1]=t[1]; bh[np*2+1][0]=t[2]; bh[np*2+1][1]=t[3];
            ldsm4(t, sb + 49152 + off);
            bl[np*2][0]=t[0]; bl[np*2][1]=t[1]; bl[np*2+1][0]=t[2]; bl[np*2+1][1]=t[3];
        }
#pragma unroll
        for (int mt = 0; mt < 4; mt++)
#pragma unroll
            for (int nt = 0; nt < 4; nt++) {
                mma_bf16(acc[mt][nt], ah[mt], bh[nt]);
                mma_bf16(acc[mt][nt], ah[mt], bl[nt]);
                mma_bf16(acc[mt][nt], al[mt], bh[nt]);
            }
    }
    __syncthreads();
    float* stg = (float*)smem;
    const int g = lid >> 2, tg = lid & 3;
#pragma unroll
    for (int mt = 0; mt < 4; mt++)
#pragma unroll
        for (int nt = 0; nt < 4; nt++) {
            int r = m0w + mt*16 + g, c = n0w + nt*8 + tg*2;
            *(float2*)&stg[r*132 + c]     = make_float2(acc[mt][nt][0], acc[mt][nt][1]);
            *(float2*)&stg[(r+8)*132 + c] = make_float2(acc[mt][nt][2], acc[mt][nt][3]);
        }
    __syncthreads();
    float* Sb = S + (size_t)bh*NL*NS;
#pragma unroll
    for (int i = 0; i < 16; i++) {
        int f = tid + i*256;
        int r = f >> 5, c4 = f & 31;
        *(float4*)&Sb[(size_t)(l0+r)*NS + s0 + c4*4] = *(float4*)&stg[r*132 + c4*4];
    }
}

// ============= softmax over rows of 1024, in place ===========================
__global__ void __launch_bounds__(256) softmax_kernel(float* __restrict__ S)
{
    const int wid = threadIdx.x >> 5, lid = threadIdx.x & 31;
    float* row = S + ((size_t)blockIdx.x*8 + wid)*1024;
    float4 v[8];
    float mx = -1e30f;
#pragma unroll
    for (int i = 0; i < 8; i++) {
        v[i] = *(float4*)&row[lid*4 + i*128];
        mx = fmaxf(mx, fmaxf(fmaxf(v[i].x, v[i].y), fmaxf(v[i].z, v[i].w)));
    }
#pragma unroll
    for (int o = 16; o >= 1; o >>= 1) mx = fmaxf(mx, __shfl_xor_sync(0xffffffffu, mx, o));
    float sum = 0.f;
#pragma unroll
    for (int i = 0; i < 8; i++) {
        v[i].x = __expf(v[i].x - mx); v[i].y = __expf(v[i].y - mx);
        v[i].z = __expf(v[i].z - mx); v[i].w = __expf(v[i].w - mx);
        sum += (v[i].x + v[i].y) + (v[i].z + v[i].w);
    }
#pragma unroll
    for (int o = 16; o >= 1; o >>= 1) sum += __shfl_xor_sync(0xffffffffu, sum, o);
    float inv = 1.f / sum;
#pragma unroll
    for (int i = 0; i < 8; i++) {
        v[i].x *= inv; v[i].y *= inv; v[i].z *= inv; v[i].w *= inv;
        *(float4*)&row[lid*4 + i*128] = v[i];
    }
}

// ============= mm_pv: O(128l x 64d) = P(128x1024) @ V(1024x64), transposed out
__global__ void __launch_bounds__(256,1) mm_pv(
    const float* __restrict__ P, const float* __restrict__ v, float* __restrict__ ot)
{
    extern __shared__ char smem[];
    const uint32_t sb = smem_u32(smem);
    const int tid = threadIdx.x, lid = tid & 31, wid = tid >> 5;
    const int l0 = blockIdx.x*128, bh = blockIdx.y;
    const int m0w = (wid & 3)*32, n0w = (wid >> 2)*32;

    const int a_row = (lid & 7) + ((lid >> 3) & 1)*8;
    const int a_kb  = (lid >> 4)*16;
    const int b_row = (lid & 7) + ((lid >> 4) & 1)*8;
    const int b_kb  = ((lid >> 3) & 1)*16;

    const float* Pb = P + (size_t)bh*NL*NS + (size_t)l0*NS;
    const float* vb = v + (size_t)bh*NS*64;

    float acc[2][4][4];
#pragma unroll
    for (int i = 0; i < 2; i++)
#pragma unroll
        for (int j = 0; j < 4; j++)
#pragma unroll
            for (int e = 0; e < 4; e++) acc[i][j][e] = 0.f;

    for (int s = 0; s < 16; s++) {
        const int s0 = s*64;
        __syncthreads();
        // ---- P tile: 128 l-rows x 64 s ----
#pragma unroll
        for (int i = 0; i < 4; i++) {
            int f = tid + i*256;
            int row = f >> 3, c8 = f & 7;
            const float* p = Pb + (size_t)row*NS + s0 + c8*8;
            float4 a = *(const float4*)p, c = *(const float4*)(p+4);
            uint32_t h0,l0v,h1,l1v,h2,l2v,h3,l3v;
            split2(a.x,a.y,h0,l0v); split2(a.z,a.w,h1,l1v);
            split2(c.x,c.y,h2,l2v); split2(c.z,c.w,h3,l3v);
            uint32_t swo = SW128((uint32_t)(row*128 + c8*16));
            *(uint4*)(smem + swo)         = make_uint4(h0,h1,h2,h3);
            *(uint4*)(smem + 16384 + swo) = make_uint4(l0v,l1v,l2v,l3v);
        }
        // ---- Vt tile: B[d][ss] = V[s0+ss][d], 64 d-rows x 64 s ----
        {
            const int d = tid & 63, gg = tid >> 6;
#pragma unroll
            for (int it = 0; it < 4; it++) {
                int kk = (gg + it*4)*4;
                const float* p = vb + (size_t)(s0+kk)*64 + d;
                float w0 = p[0], w1 = p[64], w2 = p[128], w3 = p[192];
                uint32_t h0,l0v,h1,l1v;
                split2(w0,w1,h0,l0v); split2(w2,w3,h1,l1v);
                uint32_t swo = SW128((uint32_t)(d*128 + kk*2));
                *(uint2*)(smem + 32768 + swo) = make_uint2(h0,h1);
                *(uint2*)(smem + 40960 + swo) = make_uint2(l0v,l1v);
            }
        }
        __syncthreads();
#pragma unroll
        for (int kk = 0; kk < 64; kk += 16) {
            uint32_t ah[2][4], al[2][4], bh[4][2], bl[4][2];
#pragma unroll
            for (int mt = 0; mt < 2; mt++) {
                uint32_t off = SW128((uint32_t)((m0w + mt*16 + a_row)*128 + kk*2 + a_kb));
                ldsm4(ah[mt], sb + off);
                ldsm4(al[mt], sb + 16384 + off);
            }
#pragma unroll
            for (int np = 0; np < 2; np++) {
                uint32_t off = SW128((uint32_t)((n0w + np*16 + b_row)*128 + kk*2 + b_kb));
                uint32_t t[4];
                ldsm4(t, sb + 32768 + off);
                bh[np*2][0]=t[0]; bh[np*2][1]=t[1]; bh[np*2+1][0]=t[2]; bh[np*2+1][1]=t[3];
                ldsm4(t, sb + 40960 + off);
                bl[np*2][0]=t[0]; bl[np*2][1]=t[1]; bl[np*2+1][0]=t[2]; bl[np*2+1][1]=t[3];
            }
#pragma unroll
            for (int mt = 0; mt < 2; mt++)
#pragma unroll
                for (int nt = 0; nt < 4; nt++) {
                    mma_bf16(acc[mt][nt], ah[mt], bh[nt]);
                    mma_bf16(acc[mt][nt], ah[mt], bl[nt]);
                    mma_bf16(acc[mt][nt], al[mt], bh[nt]);
                }
        }
    }
    __syncthreads();
    // ---- epilogue: stage (pitch 66) -> transposed ot write ----
    float* stg = (float*)smem;
    const int g = lid >> 2, tg = lid & 3;
#pragma unroll
    for (int mt = 0; mt < 2; mt++)
#pragma unroll
        for (int nt = 0; nt < 4; nt++) {
            int r = m0w + mt*16 + g, c = n0w + nt*8 + tg*2;
            *(float2*)&stg[r*66 + c]     = make_float2(acc[mt][nt][0], acc[mt][nt][1]);
            *(float2*)&stg[(r+8)*66 + c] = make_float2(acc[mt][nt][2], acc[mt][nt][3]);
        }
    __syncthreads();
    float* otb = ot + (size_t)bh*64*NL;
#pragma unroll
    for (int i = 0; i < 32; i++) {
        int f = tid + i*256;
        int d = f >> 7, l = f & 127;
        otb[(size_t)d*NL + l0 + l] = stg[l*66 + d];
    }
}

// ---------------- small fp32 kernels (verified in round 0) -------------------
__global__ void __launch_bounds__(256) wep_kernel(
    const float* __restrict__ rq, const float* __restrict__ rk,
    float* __restrict__ wep)
{
    __shared__ float sq[64][65];
    __shared__ float sk[64][65];
    const int bh = blockIdx.x;
    const float* rqb = rq + (bh << 12);
    const float* rkb = rk + (bh << 12);
    const int tid = threadIdx.x;
#pragma unroll
    for (int i = 0; i < 4; i++) {
        int idx = (tid + i*256) << 2;
        int r = idx >> 6, c = idx & 63;
        float4 a = *(const float4*)&rqb[idx];
        float4 b = *(const float4*)&rkb[idx];
        sq[r][c] = a.x; sq[r][c+1] = a.y; sq[r][c+2] = a.z; sq[r][c+3] = a.w;
        sk[r][c] = b.x; sk[r][c+1] = b.y; sk[r][c+2] = b.z; sk[r][c+3] = b.w;
    }
    __syncthreads();
    const int tx = tid & 15, ty = tid >> 4;
    float acc[4][4];
#pragma unroll
    for (int i = 0; i < 4; i++)
#pragma unroll
        for (int j = 0; j < 4; j++) acc[i][j] = 0.f;
    for (int g = 0; g < 64; g++) {
        float a[4], b[4];
#pragma unroll
        for (int i = 0; i < 4; i++) a[i] = sq[g][ty*4+i];
#pragma unroll
        for (int j = 0; j < 4; j++) b[j] = sk[g][tx*4+j];
#pragma unroll
        for (int i = 0; i < 4; i++)
#pragma unroll
            for (int j = 0; j < 4; j++)
                acc[i][j] = fmaf(a[i], b[j], acc[i][j]);
    }
    const float scale = 0.125f;
#pragma unroll
    for (int i = 0; i < 4; i++) {
        float4 r4 = make_float4(acc[i][0]*scale, acc[i][1]*scale,
                                acc[i][2]*scale, acc[i][3]*scale);
        *(float4*)&wep[(bh << 12) + (ty*4+i)*64 + tx*4] = r4;
    }
}

__global__ void __launch_bounds__(256) qfold_kernel(
    float* __restrict__ q, const float* __restrict__ wep)
{
    __shared__ float sq[64][65];
    __shared__ float sw[64][68];
    const int bh = blockIdx.y;
    const int l0 = blockIdx.x * 64;
    float* qb = q + (((size_t)bh * NL + l0) << 6);
    const float* wb = wep + (bh << 12);
    const int tid = threadIdx.x;
#pragma unroll
    for (int i = 0; i < 4; i++) {
        int idx = (tid + i*256) << 2;
        int r = idx >> 6, c = idx & 63;
        float4 vq = *(const float4*)&qb[idx];
        sq[r][c] = vq.x; sq[r][c+1] = vq.y; sq[r][c+2] = vq.z; sq[r][c+3] = vq.w;
        *(float4*)&sw[r][c] = *(const float4*)&wb[idx];
    }
    __syncthreads();
    const int tx = tid & 15, ty = tid >> 4;
    float acc[4][4];
#pragma unroll
    for (int i = 0; i < 4; i++)
#pragma unroll
        for (int j = 0; j < 4; j++) acc[i][j] = 0.f;
    for (int d = 0; d < 64; d++) {
        float a[4];
#pragma unroll
        for (int i = 0; i < 4; i++) a[i] = sq[ty*4+i][d];
        float4 wv = *(float4*)&sw[d][tx*4];
#pragma unroll
        for (int i = 0; i < 4; i++) {
            acc[i][0] = fmaf(a[i], wv.x, acc[i][0]);
            acc[i][1] = fmaf(a[i], wv.y, acc[i][1]);
            acc[i][2] = fmaf(a[i], wv.z, acc[i][2]);
            acc[i][3] = fmaf(a[i], wv.w, acc[i][3]);
        }
    }
#pragma unroll
    for (int i = 0; i < 4; i++) {
        float4 r4 = make_float4(acc[i][0], acc[i][1], acc[i][2], acc[i][3]);
        *(float4*)&qb[((ty*4+i) << 6) + tx*4] = r4;
    }
}

// ---------------- launch -----------------------------------------------------
extern "C" void kernel_launch(void* const* d_in, const int* in_sizes, int n_in,
                              void* d_out, int out_size)
{
    const float* queries = (const float*)d_in[0];
    const float* keys    = (const float*)d_in[1];
    const float* values  = (const float*)d_in[2];
    const float* routers = (const float*)d_in[3];
    const float* Wq  = (const float*)d_in[4];
    const float* Wk  = (const float*)d_in[5];
    const float* Wv  = (const float*)d_in[6];
    const float* Wlq = (const float*)d_in[7];
    const float* Wlk = (const float*)d_in[8];
    const float* Wo  = (const float*)d_in[9];
    const float* bo  = (const float*)d_in[10];

    float *q, *k, *v, *rq, *rk, *wep, *ot, *S;
    cudaGetSymbolAddress((void**)&q,   g_q);
    cudaGetSymbolAddress((void**)&k,   g_k);
    cudaGetSymbolAddress((void**)&v,   g_v);
    cudaGetSymbolAddress((void**)&rq,  g_rq);
    cudaGetSymbolAddress((void**)&rk,  g_rk);
    cudaGetSymbolAddress((void**)&wep, g_wep);
    cudaGetSymbolAddress((void**)&ot,  g_ot);
    cudaGetSymbolAddress((void**)&S,   g_S);

    static int attr_done = 0;
    if (!attr_done) {
        cudaFuncSetAttribute(mm_proj<0>, cudaFuncAttributeMaxDynamicSharedMemorySize, 67584);
        cudaFuncSetAttribute(mm_proj<1>, cudaFuncAttributeMaxDynamicSharedMemorySize, 67584);
        cudaFuncSetAttribute(mm_scores,  cudaFuncAttributeMaxDynamicSharedMemorySize, 67584);
        cudaFuncSetAttribute(mm_pv,      cudaFuncAttributeMaxDynamicSharedMemorySize, 49152);
        attr_done = 1;
    }

    dim3 blk(256);
    mm_proj<1><<<dim3(64, 8), blk, 67584>>>(queries, Wq, q, nullptr, NL);
    mm_proj<1><<<dim3(64, 8), blk, 67584>>>(keys,    Wk, k, nullptr, NS);
    mm_proj<1><<<dim3(64, 8), blk, 67584>>>(values,  Wv, v, nullptr, NS);
    mm_proj<1><<<dim3(4, 8),  blk, 67584>>>(routers, Wlq, rq, nullptr, NG);
    mm_proj<1><<<dim3(4, 8),  blk, 67584>>>(routers, Wlk, rk, nullptr, NG);
    wep_kernel <<<128, blk>>>(rq, rk, wep);
    qfold_kernel<<<dim3(16, 128), blk>>>(q, wep);
    mm_scores<<<dim3(8, 8, 128), blk, 67584>>>(q, k, S);
    softmax_kernel<<<16384, blk>>>(S);
    mm_pv<<<dim3(8, 128), blk, 49152>>>(S, v, ot);
    mm_proj<0><<<dim3(64, 8), blk, 67584>>>(ot, Wo, (float*)d_out, bo, NL);
}

// round 8
// speedup vs baseline: 2.1781x; 1.2607x over previous
#include <cuda_runtime.h>
#include <cuda_bf16.h>
#include <math.h>
#include <stdint.h>

#define NB 8
#define NL 1024
#define NS 1024
#define NG 64
#define ND 1024
#define NH 16
#define DH 64

// ---------------- scratch (device globals: no allocations allowed) ----------
__device__ float g_q  [NB*NH*NL*DH];   // (B,H,L,64)  -> becomes qe in-place
__device__ float g_k  [NB*NH*NS*DH];   // (B,H,S,64)
__device__ float g_v  [NB*NH*NS*DH];   // (B,H,S,64)
__device__ float g_rq [NB*NH*NG*DH];
__device__ float g_rk [NB*NH*NG*DH];
__device__ float g_wep[NB*NH*DH*DH];
__device__ float g_ot [NB*ND*NL];      // (B, H*64, L) transposed attn output

// ---------------- helpers ----------------------------------------------------
__device__ __forceinline__ uint32_t smem_u32(const void* p){
    uint32_t a;
    asm("{ .reg .u64 t; cvta.to.shared.u64 t, %1; cvt.u32.u64 %0, t; }"
        : "=r"(a) : "l"(p));
    return a;
}
#define SW128(o) ((o) ^ (((o) >> 3) & 0x70))

__device__ __forceinline__ void ldsm4(uint32_t* r, uint32_t a){
    asm volatile("ldmatrix.sync.aligned.m8n8.x4.shared.b16 {%0,%1,%2,%3}, [%4];"
        : "=r"(r[0]), "=r"(r[1]), "=r"(r[2]), "=r"(r[3]) : "r"(a));
}
__device__ __forceinline__ void mma_bf16(float* c, const uint32_t* a, const uint32_t* b){
    asm volatile("mma.sync.aligned.m16n8k16.row.col.f32.bf16.bf16.f32 "
        "{%0,%1,%2,%3}, {%4,%5,%6,%7}, {%8,%9}, {%0,%1,%2,%3};"
        : "+f"(c[0]), "+f"(c[1]), "+f"(c[2]), "+f"(c[3])
        : "r"(a[0]), "r"(a[1]), "r"(a[2]), "r"(a[3]), "r"(b[0]), "r"(b[1]));
}
__device__ __forceinline__ float ex2f(float x){
    float y; asm("ex2.approx.f32 %0, %1;" : "=f"(y) : "f"(x)); return y;
}

// split floats (x,y) into packed bf16x2 hi and lo parts (x in low half)
__device__ __forceinline__ void split2(float x, float y, uint32_t& hi, uint32_t& lo){
    __nv_bfloat16 xh = __float2bfloat16(x);
    __nv_bfloat16 yh = __float2bfloat16(y);
    __nv_bfloat16 xl = __float2bfloat16(x - __bfloat162float(xh));
    __nv_bfloat16 yl = __float2bfloat16(y - __bfloat162float(yh));
    hi = (uint32_t)__bfloat16_as_ushort(xh) | ((uint32_t)__bfloat16_as_ushort(yh) << 16);
    lo = (uint32_t)__bfloat16_as_ushort(xl) | ((uint32_t)__bfloat16_as_ushort(yl) << 16);
}

// ============= mm_proj: Y(Mx1024) = A(Mx1024) @ W(1024x1024) =================
// block 128x128, 8 warps (2x4) of 64x32 warp tiles, K chunked by 64.
// MODE 0: Y[m*1024+n]+bias[n].  MODE 1: head-split scatter (Ntok tokens/batch).
template<int MODE>
__global__ void __launch_bounds__(256,1) mm_proj(
    const float* __restrict__ A, const float* __restrict__ W,
    float* __restrict__ Y, const float* __restrict__ bias, int Ntok)
{
    extern __shared__ char smem[];
    const uint32_t sb = smem_u32(smem);
    const int tid = threadIdx.x, lid = tid & 31, wid = tid >> 5;
    const int m0 = blockIdx.x*128, n0 = blockIdx.y*128;
    const int m0w = (wid & 1)*64, n0w = (wid >> 1)*32;

    const int a_row = (lid & 7) + ((lid >> 3) & 1)*8;
    const int a_kb  = (lid >> 4)*16;
    const int b_row = (lid & 7) + ((lid >> 4) & 1)*8;
    const int b_kb  = ((lid >> 3) & 1)*16;

    float acc[4][4][4];
#pragma unroll
    for (int i = 0; i < 4; i++)
#pragma unroll
        for (int j = 0; j < 4; j++)
#pragma unroll
            for (int e = 0; e < 4; e++) acc[i][j][e] = 0.f;

    for (int s = 0; s < 16; s++) {
        const int k0 = s*64;
        __syncthreads();
        // ---- A tile: 128 rows x 64 k ----
        {
            const float* Ab = A + (size_t)m0*1024 + k0;
#pragma unroll
            for (int i = 0; i < 4; i++) {
                int f = tid + i*256;
                int row = f >> 3, c8 = f & 7;
                const float* p = Ab + (size_t)row*1024 + c8*8;
                float4 a = *(const float4*)p, c = *(const float4*)(p+4);
                uint32_t h0,l0v,h1,l1v,h2,l2v,h3,l3v;
                split2(a.x,a.y,h0,l0v); split2(a.z,a.w,h1,l1v);
                split2(c.x,c.y,h2,l2v); split2(c.z,c.w,h3,l3v);
                uint32_t swo = SW128((uint32_t)(row*128 + c8*16));
                *(uint4*)(smem + swo)         = make_uint4(h0,h1,h2,h3);
                *(uint4*)(smem + 16384 + swo) = make_uint4(l0v,l1v,l2v,l3v);
            }
        }
        // ---- B tile: B[n][k] = W[k][n], 128 n-rows x 64 k ----
        {
            const int bc = tid & 127, bg = tid >> 7;
#pragma unroll
            for (int it = 0; it < 8; it++) {
                int kk = (bg + it*2)*4;
                const float* p = W + (size_t)(k0+kk)*1024 + n0 + bc;
                float w0 = p[0], w1 = p[1024], w2 = p[2048], w3 = p[3072];
                uint32_t h0,l0v,h1,l1v;
                split2(w0,w1,h0,l0v); split2(w2,w3,h1,l1v);
                uint32_t swo = SW128((uint32_t)(bc*128 + kk*2));
                *(uint2*)(smem + 32768 + swo) = make_uint2(h0,h1);
                *(uint2*)(smem + 49152 + swo) = make_uint2(l0v,l1v);
            }
        }
        __syncthreads();
        // ---- compute: 4 ksteps of 16 ----
#pragma unroll
        for (int kk = 0; kk < 64; kk += 16) {
            uint32_t ah[4][4], al[4][4], bh[4][2], bl[4][2];
#pragma unroll
            for (int mt = 0; mt < 4; mt++) {
                uint32_t off = SW128((uint32_t)((m0w + mt*16 + a_row)*128 + kk*2 + a_kb));
                ldsm4(ah[mt], sb + off);
                ldsm4(al[mt], sb + 16384 + off);
            }
#pragma unroll
            for (int np = 0; np < 2; np++) {
                uint32_t off = SW128((uint32_t)((n0w + np*16 + b_row)*128 + kk*2 + b_kb));
                uint32_t t[4];
                ldsm4(t, sb + 32768 + off);
                bh[np*2][0]=t[0]; bh[np*2][1]=t[1]; bh[np*2+1][0]=t[2]; bh[np*2+1][1]=t[3];
                ldsm4(t, sb + 49152 + off);
                bl[np*2][0]=t[0]; bl[np*2][1]=t[1]; bl[np*2+1][0]=t[2]; bl[np*2+1][1]=t[3];
            }
#pragma unroll
            for (int mt = 0; mt < 4; mt++)
#pragma unroll
                for (int nt = 0; nt < 4; nt++) {
                    mma_bf16(acc[mt][nt], ah[mt], bh[nt]);
                    mma_bf16(acc[mt][nt], ah[mt], bl[nt]);
                    mma_bf16(acc[mt][nt], al[mt], bh[nt]);
                }
        }
    }
    __syncthreads();
    // ---- epilogue: stage fp32 (pitch 132) -> coalesced write ----
    float* stg = (float*)smem;
    const int g = lid >> 2, tg = lid & 3;
#pragma unroll
    for (int mt = 0; mt < 4; mt++)
#pragma unroll
        for (int nt = 0; nt < 4; nt++) {
            int r = m0w + mt*16 + g, c = n0w + nt*8 + tg*2;
            *(float2*)&stg[r*132 + c]     = make_float2(acc[mt][nt][0], acc[mt][nt][1]);
            *(float2*)&stg[(r+8)*132 + c] = make_float2(acc[mt][nt][2], acc[mt][nt][3]);
        }
    __syncthreads();
#pragma unroll
    for (int i = 0; i < 16; i++) {
        int f = tid + i*256;
        int r = f >> 5, c4 = f & 31;
        float4 val = *(float4*)&stg[r*132 + c4*4];
        int m = m0 + r, n = n0 + c4*4;
        if (MODE == 0) {
            float4 bb = *(const float4*)&bias[n];
            val.x += bb.x; val.y += bb.y; val.z += bb.z; val.w += bb.w;
            *(float4*)&Y[(size_t)m*1024 + n] = val;
        } else {
            int bq = m / Ntok, t = m - bq*Ntok;
            int h = n >> 6, d = n & 63;
            *(float4*)&Y[(size_t)((bq*NH + h)*Ntok + t)*64 + d] = val;
        }
    }
}

// ============= fused flash attention =========================================
// Per CTA: 128 q-rows of one (b,h). 8 warps x 16 rows. S chunked by 64.
// qe (scale*log2e folded) tile loaded once; scores -> online softmax in regs
// (C-frag quad layout, shfl_xor 1,2) -> P repacked C->A frags (hi/lo split)
// -> PV MMA. Output normalized + written transposed: ot[bh*64+d][l].
// smem: qe_hi@0(16K) qe_lo@16384 | K_hi@32768(8K) K_lo@40960 | Vt_hi@49152 Vt_lo@57344
__global__ void __launch_bounds__(256,1) flash_kernel(
    const float* __restrict__ q, const float* __restrict__ k,
    const float* __restrict__ v, float* __restrict__ ot)
{
    extern __shared__ char smem[];
    const uint32_t sb = smem_u32(smem);
    const int tid = threadIdx.x, lid = tid & 31, wid = tid >> 5;
    const int l0 = blockIdx.x*128, bh = blockIdx.y;
    const int m0w = wid*16;

    const int a_row = (lid & 7) + ((lid >> 3) & 1)*8;
    const int a_kb  = (lid >> 4)*16;
    const int b_row = (lid & 7) + ((lid >> 4) & 1)*8;
    const int b_kb  = ((lid >> 3) & 1)*16;

    const float* qb = q + ((size_t)bh*NL + l0)*64;
    const float* kb = k + (size_t)bh*NS*64;
    const float* vb = v + (size_t)bh*NS*64;

    // qe tile 128x64 (hi/lo), loaded once
#pragma unroll
    for (int i = 0; i < 4; i++) {
        int f = tid + i*256;
        int row = f >> 3, c8 = f & 7;
        const float* p = qb + (size_t)row*64 + c8*8;
        float4 a = *(const float4*)p, c = *(const float4*)(p+4);
        uint32_t h0,l0v,h1,l1v,h2,l2v,h3,l3v;
        split2(a.x,a.y,h0,l0v); split2(a.z,a.w,h1,l1v);
        split2(c.x,c.y,h2,l2v); split2(c.z,c.w,h3,l3v);
        uint32_t swo = SW128((uint32_t)(row*128 + c8*16));
        *(uint4*)(smem + swo)         = make_uint4(h0,h1,h2,h3);
        *(uint4*)(smem + 16384 + swo) = make_uint4(l0v,l1v,l2v,l3v);
    }

    float o[8][4];
#pragma unroll
    for (int nt = 0; nt < 8; nt++)
#pragma unroll
        for (int e = 0; e < 4; e++) o[nt][e] = 0.f;
    float m_a = -1e30f, m_b = -1e30f, l_a = 0.f, l_b = 0.f;

    for (int s0 = 0; s0 < NS; s0 += 64) {
        __syncthreads();   // previous chunk's compute done before overwrite
        // ---- K chunk: 64 s-rows x 64 d ----
#pragma unroll
        for (int i = 0; i < 2; i++) {
            int f = tid + i*256;
            int row = f >> 3, c8 = f & 7;
            const float* p = kb + (size_t)(s0+row)*64 + c8*8;
            float4 a = *(const float4*)p, c = *(const float4*)(p+4);
            uint32_t h0,l0v,h1,l1v,h2,l2v,h3,l3v;
            split2(a.x,a.y,h0,l0v); split2(a.z,a.w,h1,l1v);
            split2(c.x,c.y,h2,l2v); split2(c.z,c.w,h3,l3v);
            uint32_t swo = SW128((uint32_t)(row*128 + c8*16));
            *(uint4*)(smem + 32768 + swo) = make_uint4(h0,h1,h2,h3);
            *(uint4*)(smem + 40960 + swo) = make_uint4(l0v,l1v,l2v,l3v);
        }
        // ---- Vt chunk: B[d][ss] = V[s0+ss][d], 64 d-rows x 64 s ----
        {
            const int d = tid & 63, gg = tid >> 6;
#pragma unroll
            for (int it = 0; it < 4; it++) {
                int kk = (gg + it*4)*4;
                const float* p = vb + (size_t)(s0+kk)*64 + d;
                float w0 = p[0], w1 = p[64], w2 = p[128], w3 = p[192];
                uint32_t h0,l0v,h1,l1v;
                split2(w0,w1,h0,l0v); split2(w2,w3,h1,l1v);
                uint32_t swo = SW128((uint32_t)(d*128 + kk*2));
                *(uint2*)(smem + 49152 + swo) = make_uint2(h0,h1);
                *(uint2*)(smem + 57344 + swo) = make_uint2(l0v,l1v);
            }
        }
        __syncthreads();

        // ---- scores: 16 rows x 64 cols per warp ----
        float sc[8][4];
#pragma unroll
        for (int nt = 0; nt < 8; nt++)
#pragma unroll
            for (int e = 0; e < 4; e++) sc[nt][e] = 0.f;
#pragma unroll
        for (int kk = 0; kk < 64; kk += 16) {
            uint32_t ah[4], al[4];
            uint32_t offA = SW128((uint32_t)((m0w + a_row)*128 + kk*2 + a_kb));
            ldsm4(ah, sb + offA);
            ldsm4(al, sb + 16384 + offA);
#pragma unroll
            for (int np = 0; np < 4; np++) {
                uint32_t offB = SW128((uint32_t)((np*16 + b_row)*128 + kk*2 + b_kb));
                uint32_t th[4], tl[4];
                ldsm4(th, sb + 32768 + offB);
                ldsm4(tl, sb + 40960 + offB);
                uint32_t bh0[2] = {th[0], th[1]}, bh1[2] = {th[2], th[3]};
                uint32_t bl0[2] = {tl[0], tl[1]}, bl1[2] = {tl[2], tl[3]};
                mma_bf16(sc[2*np],   ah, bh0);
                mma_bf16(sc[2*np+1], ah, bh1);
                mma_bf16(sc[2*np],   ah, bl0);
                mma_bf16(sc[2*np+1], ah, bl1);
                mma_bf16(sc[2*np],   al, bh0);
                mma_bf16(sc[2*np+1], al, bh1);
            }
        }

        // ---- online softmax (scores already in log2 domain) ----
        float mxa = -1e30f, mxb = -1e30f;
#pragma unroll
        for (int nt = 0; nt < 8; nt++) {
            mxa = fmaxf(mxa, fmaxf(sc[nt][0], sc[nt][1]));
            mxb = fmaxf(mxb, fmaxf(sc[nt][2], sc[nt][3]));
        }
        mxa = fmaxf(mxa, __shfl_xor_sync(0xffffffffu, mxa, 1));
        mxa = fmaxf(mxa, __shfl_xor_sync(0xffffffffu, mxa, 2));
        mxb = fmaxf(mxb, __shfl_xor_sync(0xffffffffu, mxb, 1));
        mxb = fmaxf(mxb, __shfl_xor_sync(0xffffffffu, mxb, 2));
        float na = fmaxf(m_a, mxa), nb = fmaxf(m_b, mxb);
        float fa = ex2f(m_a - na), fb = ex2f(m_b - nb);
        m_a = na; m_b = nb;
        float sa = 0.f, sbv = 0.f;
#pragma unroll
        for (int nt = 0; nt < 8; nt++) {
            sc[nt][0] = ex2f(sc[nt][0] - na);
            sc[nt][1] = ex2f(sc[nt][1] - na);
            sc[nt][2] = ex2f(sc[nt][2] - nb);
            sc[nt][3] = ex2f(sc[nt][3] - nb);
            sa  += sc[nt][0] + sc[nt][1];
            sbv += sc[nt][2] + sc[nt][3];
        }
        sa  += __shfl_xor_sync(0xffffffffu, sa, 1);
        sa  += __shfl_xor_sync(0xffffffffu, sa, 2);
        sbv += __shfl_xor_sync(0xffffffffu, sbv, 1);
        sbv += __shfl_xor_sync(0xffffffffu, sbv, 2);
        l_a = l_a*fa + sa;
        l_b = l_b*fb + sbv;
#pragma unroll
        for (int nt = 0; nt < 8; nt++) {
            o[nt][0] *= fa; o[nt][1] *= fa;
            o[nt][2] *= fb; o[nt][3] *= fb;
        }

        // ---- PV: P (C-frags) -> A-frags (hi/lo), B = Vt ----
#pragma unroll
        for (int j = 0; j < 4; j++) {
            uint32_t pah[4], pal[4];
            split2(sc[2*j][0],   sc[2*j][1],   pah[0], pal[0]);
            split2(sc[2*j][2],   sc[2*j][3],   pah[1], pal[1]);
            split2(sc[2*j+1][0], sc[2*j+1][1], pah[2], pal[2]);
            split2(sc[2*j+1][2], sc[2*j+1][3], pah[3], pal[3]);
#pragma unroll
            for (int ng = 0; ng < 4; ng++) {
                uint32_t offV = SW128((uint32_t)((ng*16 + b_row)*128 + j*32 + b_kb));
                uint32_t th[4], tl[4];
                ldsm4(th, sb + 49152 + offV);
                ldsm4(tl, sb + 57344 + offV);
                uint32_t vh0[2] = {th[0], th[1]}, vh1[2] = {th[2], th[3]};
                uint32_t vl0[2] = {tl[0], tl[1]}, vl1[2] = {tl[2], tl[3]};
                mma_bf16(o[2*ng],   pah, vh0);
                mma_bf16(o[2*ng+1], pah, vh1);
                mma_bf16(o[2*ng],   pah, vl0);
                mma_bf16(o[2*ng+1], pah, vl1);
                mma_bf16(o[2*ng],   pal, vh0);
                mma_bf16(o[2*ng+1], pal, vh1);
            }
        }
    }

    // ---- epilogue: normalize, stage (pitch 66), transposed write ----
    __syncthreads();
    float* stg = (float*)smem;
    {
        float inva = 1.f / l_a, invb = 1.f / l_b;
        const int g = lid >> 2, tg = lid & 3;
#pragma unroll
        for (int nt = 0; nt < 8; nt++) {
            int r = m0w + g, c = nt*8 + tg*2;
            *(float2*)&stg[r*66 + c]     = make_float2(o[nt][0]*inva, o[nt][1]*inva);
            *(float2*)&stg[(r+8)*66 + c] = make_float2(o[nt][2]*invb, o[nt][3]*invb);
        }
    }
    __syncthreads();
    float* otb = ot + (size_t)bh*64*NL;
#pragma unroll
    for (int i = 0; i < 32; i++) {
        int f = tid + i*256;
        int d = f >> 7, l = f & 127;
        otb[(size_t)d*NL + l0 + l] = stg[l*66 + d];
    }
}

// ---------------- small fp32 kernels -----------------------------------------
__global__ void __launch_bounds__(256) wep_kernel(
    const float* __restrict__ rq, const float* __restrict__ rk,
    float* __restrict__ wep)
{
    __shared__ float sq[64][65];
    __shared__ float sk[64][65];
    const int bh = blockIdx.x;
    const float* rqb = rq + (bh << 12);
    const float* rkb = rk + (bh << 12);
    const int tid = threadIdx.x;
#pragma unroll
    for (int i = 0; i < 4; i++) {
        int idx = (tid + i*256) << 2;
        int r = idx >> 6, c = idx & 63;
        float4 a = *(const float4*)&rqb[idx];
        float4 b = *(const float4*)&rkb[idx];
        sq[r][c] = a.x; sq[r][c+1] = a.y; sq[r][c+2] = a.z; sq[r][c+3] = a.w;
        sk[r][c] = b.x; sk[r][c+1] = b.y; sk[r][c+2] = b.z; sk[r][c+3] = b.w;
    }
    __syncthreads();
    const int tx = tid & 15, ty = tid >> 4;
    float acc[4][4];
#pragma unroll
    for (int i = 0; i < 4; i++)
#pragma unroll
        for (int j = 0; j < 4; j++) acc[i][j] = 0.f;
    for (int g = 0; g < 64; g++) {
        float a[4], b[4];
#pragma unroll
        for (int i = 0; i < 4; i++) a[i] = sq[g][ty*4+i];
#pragma unroll
        for (int j = 0; j < 4; j++) b[j] = sk[g][tx*4+j];
#pragma unroll
        for (int i = 0; i < 4; i++)
#pragma unroll
            for (int j = 0; j < 4; j++)
                acc[i][j] = fmaf(a[i], b[j], acc[i][j]);
    }
    // scale = 1/sqrt(64) * log2(e)  (softmax runs in log2 domain via ex2)
    const float scale = 0.125f * 1.4426950408889634f;
#pragma unroll
    for (int i = 0; i < 4; i++) {
        float4 r4 = make_float4(acc[i][0]*scale, acc[i][1]*scale,
                                acc[i][2]*scale, acc[i][3]*scale);
        *(float4*)&wep[(bh << 12) + (ty*4+i)*64 + tx*4] = r4;
    }
}

__global__ void __launch_bounds__(256) qfold_kernel(
    float* __restrict__ q, const float* __restrict__ wep)
{
    __shared__ float sq[64][65];
    __shared__ float sw[64][68];
    const int bh = blockIdx.y;
    const int l0 = blockIdx.x * 64;
    float* qb = q + (((size_t)bh * NL + l0) << 6);
    const float* wb = wep + (bh << 12);
    const int tid = threadIdx.x;
#pragma unroll
    for (int i = 0; i < 4; i++) {
        int idx = (tid + i*256) << 2;
        int r = idx >> 6, c = idx & 63;
        float4 vq = *(const float4*)&qb[idx];
        sq[r][c] = vq.x; sq[r][c+1] = vq.y; sq[r][c+2] = vq.z; sq[r][c+3] = vq.w;
        *(float4*)&sw[r][c] = *(const float4*)&wb[idx];
    }
    __syncthreads();
    const int tx = tid & 15, ty = tid >> 4;
    float acc[4][4];
#pragma unroll
    for (int i = 0; i < 4; i++)
#pragma unroll
        for (int j = 0; j < 4; j++) acc[i][j] = 0.f;
    for (int d = 0; d < 64; d++) {
        float a[4];
#pragma unroll
        for (int i = 0; i < 4; i++) a[i] = sq[ty*4+i][d];
        float4 wv = *(float4*)&sw[d][tx*4];
#pragma unroll
        for (int i = 0; i < 4; i++) {
            acc[i][0] = fmaf(a[i], wv.x, acc[i][0]);
            acc[i][1] = fmaf(a[i], wv.y, acc[i][1]);
            acc[i][2] = fmaf(a[i], wv.z, acc[i][2]);
            acc[i][3] = fmaf(a[i], wv.w, acc[i][3]);
        }
    }
#pragma unroll
    for (int i = 0; i < 4; i++) {
        float4 r4 = make_float4(acc[i][0], acc[i][1], acc[i][2], acc[i][3]);
        *(float4*)&qb[((ty*4+i) << 6) + tx*4] = r4;
    }
}

// ---------------- launch -----------------------------------------------------
extern "C" void kernel_launch(void* const* d_in, const int* in_sizes, int n_in,
                              void* d_out, int out_size)
{
    const float* queries = (const float*)d_in[0];
    const float* keys    = (const float*)d_in[1];
    const float* values  = (const float*)d_in[2];
    const float* routers = (const float*)d_in[3];
    const float* Wq  = (const float*)d_in[4];
    const float* Wk  = (const float*)d_in[5];
    const float* Wv  = (const float*)d_in[6];
    const float* Wlq = (const float*)d_in[7];
    const float* Wlk = (const float*)d_in[8];
    const float* Wo  = (const float*)d_in[9];
    const float* bo  = (const float*)d_in[10];

    float *q, *k, *v, *rq, *rk, *wep, *ot;
    cudaGetSymbolAddress((void**)&q,   g_q);
    cudaGetSymbolAddress((void**)&k,   g_k);
    cudaGetSymbolAddress((void**)&v,   g_v);
    cudaGetSymbolAddress((void**)&rq,  g_rq);
    cudaGetSymbolAddress((void**)&rk,  g_rk);
    cudaGetSymbolAddress((void**)&wep, g_wep);
    cudaGetSymbolAddress((void**)&ot,  g_ot);

    static int attr_done = 0;
    if (!attr_done) {
        cudaFuncSetAttribute(mm_proj<0>,  cudaFuncAttributeMaxDynamicSharedMemorySize, 67584);
        cudaFuncSetAttribute(mm_proj<1>,  cudaFuncAttributeMaxDynamicSharedMemorySize, 67584);
        cudaFuncSetAttribute(flash_kernel, cudaFuncAttributeMaxDynamicSharedMemorySize, 65536);
        attr_done = 1;
    }

    dim3 blk(256);
    mm_proj<1><<<dim3(64, 8), blk, 67584>>>(queries, Wq, q, nullptr, NL);
    mm_proj<1><<<dim3(64, 8), blk, 67584>>>(keys,    Wk, k, nullptr, NS);
    mm_proj<1><<<dim3(64, 8), blk, 67584>>>(values,  Wv, v, nullptr, NS);
    mm_proj<1><<<dim3(4, 8),  blk, 67584>>>(routers, Wlq, rq, nullptr, NG);
    mm_proj<1><<<dim3(4, 8),  blk, 67584>>>(routers, Wlk, rk, nullptr, NG);
    wep_kernel <<<128, blk>>>(rq, rk, wep);
    qfold_kernel<<<dim3(16, 128), blk>>>(q, wep);
    flash_kernel<<<dim3(8, 128), blk, 65536>>>(q, k, v, ot);
    mm_proj<0><<<dim3(64, 8), blk, 67584>>>(ot, Wo, (float*)d_out, bo, NL);
}

// round 11
// speedup vs baseline: 3.4303x; 1.5749x over previous
#include <cuda_runtime.h>
#include <cuda_bf16.h>
#include <math.h>
#include <stdint.h>

#define NB 8
#define NL 1024
#define NS 1024
#define NG 64
#define ND 1024
#define NH 16
#define DH 64

// ---------------- scratch (device globals) -----------------------------------
__device__ float    g_q  [NB*NH*NL*DH];
__device__ float    g_rq [NB*NH*NG*DH];
__device__ float    g_rk [NB*NH*NG*DH];
__device__ float    g_wep[NB*NH*DH*DH];
__device__ uint32_t g_inh[NB*NL*ND/2],    g_inl[NB*NL*ND/2];
__device__ uint32_t g_wth[ND*ND/2],       g_wtl[ND*ND/2];
__device__ uint32_t g_wth2[ND*ND/2],      g_wtl2[ND*ND/2];
__device__ uint32_t g_qh [NB*NH*NL*DH/2], g_ql [NB*NH*NL*DH/2];
__device__ uint32_t g_kh [NB*NH*NS*DH/2], g_kl [NB*NH*NS*DH/2];
__device__ uint32_t g_vth[NB*NH*DH*NS/2], g_vtl[NB*NH*DH*NS/2];
__device__ uint32_t g_oth[NB*ND*NL/2],    g_otl[NB*ND*NL/2];

// ---------------- helpers ----------------------------------------------------
__device__ __forceinline__ uint32_t smem_u32(const void* p){
    uint32_t a;
    asm("{ .reg .u64 t; cvta.to.shared.u64 t, %1; cvt.u32.u64 %0, t; }"
        : "=r"(a) : "l"(p));
    return a;
}
#define SW128(o) ((o) ^ (((o) >> 3) & 0x70))

__device__ __forceinline__ void ldsm4(uint32_t* r, uint32_t a){
    asm volatile("ldmatrix.sync.aligned.m8n8.x4.shared.b16 {%0,%1,%2,%3}, [%4];"
        : "=r"(r[0]), "=r"(r[1]), "=r"(r[2]), "=r"(r[3]) : "r"(a));
}
__device__ __forceinline__ void mma_bf16(float* c, const uint32_t* a, const uint32_t* b){
    asm volatile("mma.sync.aligned.m16n8k16.row.col.f32.bf16.bf16.f32 "
        "{%0,%1,%2,%3}, {%4,%5,%6,%7}, {%8,%9}, {%0,%1,%2,%3};"
        : "+f"(c[0]), "+f"(c[1]), "+f"(c[2]), "+f"(c[3])
        : "r"(a[0]), "r"(a[1]), "r"(a[2]), "r"(a[3]), "r"(b[0]), "r"(b[1]));
}
__device__ __forceinline__ float ex2f(float x){
    float y; asm("ex2.approx.f32 %0, %1;" : "=f"(y) : "f"(x)); return y;
}
__device__ __forceinline__ void cpa16(uint32_t d, const void* s){
    asm volatile("cp.async.cg.shared.global [%0], [%1], 16;" :: "r"(d), "l"(s));
}
__device__ __forceinline__ void cp_commit(){ asm volatile("cp.async.commit_group;"); }
__device__ __forceinline__ void cp_wait1(){ asm volatile("cp.async.wait_group 1;"); }
__device__ __forceinline__ void cp_wait0(){ asm volatile("cp.async.wait_group 0;"); }

__device__ __forceinline__ void split2(float x, float y, uint32_t& hi, uint32_t& lo){
    __nv_bfloat16 xh = __float2bfloat16(x);
    __nv_bfloat16 yh = __float2bfloat16(y);
    __nv_bfloat16 xl = __float2bfloat16(x - __bfloat162float(xh));
    __nv_bfloat16 yl = __float2bfloat16(y - __bfloat162float(yh));
    hi = (uint32_t)__bfloat16_as_ushort(xh) | ((uint32_t)__bfloat16_as_ushort(yh) << 16);
    lo = (uint32_t)__bfloat16_as_ushort(xl) | ((uint32_t)__bfloat16_as_ushort(yl) << 16);
}

// ---------------- split kernels ----------------------------------------------
__global__ void __launch_bounds__(256) split_a(
    const float* __restrict__ A, uint32_t* __restrict__ hi,
    uint32_t* __restrict__ lo, int n8)
{
    int g = blockIdx.x*256 + threadIdx.x;
    if (g >= n8) return;
    float4 a = ((const float4*)A)[g*2];
    float4 b = ((const float4*)A)[g*2+1];
    uint32_t h[4], l[4];
    split2(a.x,a.y,h[0],l[0]); split2(a.z,a.w,h[1],l[1]);
    split2(b.x,b.y,h[2],l[2]); split2(b.z,b.w,h[3],l[3]);
    ((uint4*)hi)[g] = make_uint4(h[0],h[1],h[2],h[3]);
    ((uint4*)lo)[g] = make_uint4(l[0],l[1],l[2],l[3]);
}

// W[k][n] fp32 -> Wt hi/lo packed bf16x2 [n][k/2]
__global__ void __launch_bounds__(256) split_w(
    const float* __restrict__ W, uint32_t* __restrict__ th, uint32_t* __restrict__ tl)
{
    __shared__ float t[32][33];
    const int k0 = blockIdx.x*32, n0 = blockIdx.y*32;
    const int tid = threadIdx.x;
    const int c = tid & 31, r = tid >> 5;
#pragma unroll
    for (int i = 0; i < 4; i++)
        t[r + i*8][c] = W[(size_t)(k0 + r + i*8)*1024 + n0 + c];
    __syncthreads();
    const int nl = tid >> 3, kp = (tid & 7)*2;
    uint32_t h0,l0v,h1,l1v;
    split2(t[kp*2][nl],   t[kp*2+1][nl], h0, l0v);
    split2(t[kp*2+2][nl], t[kp*2+3][nl], h1, l1v);
    size_t o = (size_t)(n0+nl)*512 + k0/2 + kp;
    *(uint2*)&th[o] = make_uint2(h0,h1);
    *(uint2*)&tl[o] = make_uint2(l0v,l1v);
}

// ============= mm_projb: Y(Mx1024) = A @ W, pre-split operands ===============
// MODE 0: fp32 +bias.  1: head-scatter fp32.  2: head-scatter packed (K-style).
// MODE 3: head-scatter transposed packed (V-style).
// smem: 2 bufs x { Ah 16K | Al 16K | Bh 16K | Bl 16K } = 131072 bytes.
template<int MODE>
__global__ void __launch_bounds__(256,1) mm_projb(
    const uint32_t* __restrict__ Ah, const uint32_t* __restrict__ Al,
    const uint32_t* __restrict__ Bh_, const uint32_t* __restrict__ Bl_,
    float* __restrict__ Yf_, uint32_t* __restrict__ Yh, uint32_t* __restrict__ Yl,
    const float* __restrict__ bias, int Ntok,
    const uint32_t* __restrict__ B2h, const uint32_t* __restrict__ B2l,
    float* __restrict__ Y2f)
{
    extern __shared__ char smem[];
    const uint32_t sb = smem_u32(smem);
    const int tid = threadIdx.x, lid = tid & 31, wid = tid >> 5;
    const int m0 = blockIdx.x*128, n0 = blockIdx.y*128;
    const uint32_t* Bh = blockIdx.z ? B2h : Bh_;
    const uint32_t* Bl = blockIdx.z ? B2l : Bl_;
    float* Yf = blockIdx.z ? Y2f : Yf_;

    const int m0w = (wid & 1)*64, n0w = (wid >> 1)*32;
    const int a_row = (lid & 7) + ((lid >> 3) & 1)*8;
    const int a_kb  = (lid >> 4)*16;
    const int b_row = (lid & 7) + ((lid >> 4) & 1)*8;
    const int b_kb  = ((lid >> 3) & 1)*16;

    float acc[4][4][4];
#pragma unroll
    for (int i = 0; i < 4; i++)
#pragma unroll
        for (int j = 0; j < 4; j++)
#pragma unroll
            for (int e = 0; e < 4; e++) acc[i][j][e] = 0.f;

#define PROJ_ISSUE(s) do { \
    const uint32_t base_ = (uint32_t)((s) & 1)*65536u; \
    const int k0h_ = (s)*32; \
    _Pragma("unroll") \
    for (int i_ = 0; i_ < 4; i_++) { \
        int f_ = tid + i_*256; \
        int row_ = f_ >> 3, c_ = f_ & 7; \
        uint32_t swo_ = SW128((uint32_t)(row_*128 + c_*16)); \
        cpa16(sb + base_ + swo_,         Ah + (size_t)(m0+row_)*512 + k0h_ + c_*4); \
        cpa16(sb + base_ + 16384 + swo_, Al + (size_t)(m0+row_)*512 + k0h_ + c_*4); \
        cpa16(sb + base_ + 32768 + swo_, Bh + (size_t)(n0+row_)*512 + k0h_ + c_*4); \
        cpa16(sb + base_ + 49152 + swo_, Bl + (size_t)(n0+row_)*512 + k0h_ + c_*4); \
    } \
    cp_commit(); \
} while(0)

    PROJ_ISSUE(0);
    for (int s = 0; s < 16; s++) {
        if (s < 15) { PROJ_ISSUE(s+1); cp_wait1(); } else cp_wait0();
        __syncthreads();
        const uint32_t base = (uint32_t)(s & 1)*65536u;
#pragma unroll
        for (int kk = 0; kk < 64; kk += 16) {
            uint32_t ahf[4][4], alf[4][4], bhf[4][2], blf[4][2];
#pragma unroll
            for (int mt = 0; mt < 4; mt++) {
                uint32_t off = SW128((uint32_t)((m0w + mt*16 + a_row)*128 + kk*2 + a_kb));
                ldsm4(ahf[mt], sb + base + off);
                ldsm4(alf[mt], sb + base + 16384 + off);
            }
#pragma unroll
            for (int np = 0; np < 2; np++) {
                uint32_t off = SW128((uint32_t)((n0w + np*16 + b_row)*128 + kk*2 + b_kb));
                uint32_t t[4];
                ldsm4(t, sb + base + 32768 + off);
                bhf[np*2][0]=t[0]; bhf[np*2][1]=t[1]; bhf[np*2+1][0]=t[2]; bhf[np*2+1][1]=t[3];
                ldsm4(t, sb + base + 49152 + off);
                blf[np*2][0]=t[0]; blf[np*2][1]=t[1]; blf[np*2+1][0]=t[2]; blf[np*2+1][1]=t[3];
            }
#pragma unroll
            for (int mt = 0; mt < 4; mt++)
#pragma unroll
                for (int nt = 0; nt < 4; nt++) {
                    mma_bf16(acc[mt][nt], ahf[mt], bhf[nt]);
                    mma_bf16(acc[mt][nt], ahf[mt], blf[nt]);
                    mma_bf16(acc[mt][nt], alf[mt], bhf[nt]);
                }
        }
        __syncthreads();
    }

    // ---- epilogue: stage fp32 (pitch 132) ----
    float* stg = (float*)smem;
    {
        const int g = lid >> 2, tg = lid & 3;
#pragma unroll
        for (int mt = 0; mt < 4; mt++)
#pragma unroll
            for (int nt = 0; nt < 4; nt++) {
                int r = m0w + mt*16 + g, c = n0w + nt*8 + tg*2;
                *(float2*)&stg[r*132 + c]     = make_float2(acc[mt][nt][0], acc[mt][nt][1]);
                *(float2*)&stg[(r+8)*132 + c] = make_float2(acc[mt][nt][2], acc[mt][nt][3]);
            }
    }
    __syncthreads();

    if (MODE <= 1) {
#pragma unroll
        for (int i = 0; i < 16; i++) {
            int f = tid + i*256;
            int r = f >> 5, c4 = f & 31;
            float4 val = *(float4*)&stg[r*132 + c4*4];
            int m = m0 + r, n = n0 + c4*4;
            if (MODE == 0) {
                float4 bb = *(const float4*)&bias[n];
                val.x += bb.x; val.y += bb.y; val.z += bb.z; val.w += bb.w;
                *(float4*)&Yf[(size_t)m*1024 + n] = val;
            } else {
                int bq = m / Ntok, t = m - bq*Ntok;
                int h = n >> 6, d = n & 63;
                *(float4*)&Yf[(size_t)((bq*NH + h)*Ntok + t)*64 + d] = val;
            }
        }
    } else if (MODE == 2) {
#pragma unroll
        for (int i = 0; i < 16; i++) {
            int f = tid + i*256;
            int r = f >> 5, c4 = f & 31;
            float4 val = *(float4*)&stg[r*132 + c4*4];
            int m = m0 + r, n = n0 + c4*4;
            int bq = m >> 10, t = m & 1023;
            int h = n >> 6, d = n & 63;
            uint32_t h0,l0v,h1,l1v;
            split2(val.x,val.y,h0,l0v); split2(val.z,val.w,h1,l1v);
            size_t o = ((size_t)(bq*NH + h)*1024 + t)*32 + (d >> 1);
            *(uint2*)&Yh[o] = make_uint2(h0,h1);
            *(uint2*)&Yl[o] = make_uint2(l0v,l1v);
        }
    } else {
        const int nl = tid & 127, half = tid >> 7;
        const int n = n0 + nl;              // FIX: global column (was missing n0)
        const int hh = n >> 6, d = n & 63;
        const int bq = m0 >> 10;
        const size_t rowv = ((size_t)(bq*NH + hh)*64 + d)*512;
        const int tbase = (m0 & 1023) + half*64;
#pragma unroll
        for (int j = 0; j < 8; j++) {
            float x[8];
#pragma unroll
            for (int e = 0; e < 8; e++) x[e] = stg[(half*64 + j*8 + e)*132 + nl];
            uint32_t h[4], l[4];
            split2(x[0],x[1],h[0],l[0]); split2(x[2],x[3],h[1],l[1]);
            split2(x[4],x[5],h[2],l[2]); split2(x[6],x[7],h[3],l[3]);
            size_t o = rowv + (size_t)(tbase + j*8)/2;
            *(uint4*)&Yh[o] = make_uint4(h[0],h[1],h[2],h[3]);
            *(uint4*)&Yl[o] = make_uint4(l[0],l[1],l[2],l[3]);
        }
    }
}

// ============= flash2: fused attention, pre-split inputs =====================
// smem: Qh@0 16K | Ql@16384 | bufs@32768: 2 x { Kh 8K | Kl 8K | Vh 8K | Vl 8K }
__global__ void __launch_bounds__(256,1) flash2(
    const uint32_t* __restrict__ qh, const uint32_t* __restrict__ ql,
    const uint32_t* __restrict__ kh, const uint32_t* __restrict__ kl,
    const uint32_t* __restrict__ vh, const uint32_t* __restrict__ vl,
    uint32_t* __restrict__ oth, uint32_t* __restrict__ otl)
{
    extern __shared__ char smem[];
    const uint32_t sb = smem_u32(smem);
    const int tid = threadIdx.x, lid = tid & 31, wid = tid >> 5;
    const int l0 = blockIdx.x*128, bh = blockIdx.y;
    const int m0w = wid*16;

    const int a_row = (lid & 7) + ((lid >> 3) & 1)*8;
    const int a_kb  = (lid >> 4)*16;
    const int b_row = (lid & 7) + ((lid >> 4) & 1)*8;
    const int b_kb  = ((lid >> 3) & 1)*16;

    // Q tile (direct loads)
#pragma unroll
    for (int i = 0; i < 4; i++) {
        int f = tid + i*256;
        int row = f >> 3, c = f & 7;
        uint32_t swo = SW128((uint32_t)(row*128 + c*16));
        size_t src = (size_t)(bh*NL + l0 + row)*32 + c*4;
        *(uint4*)(smem + swo)         = *(const uint4*)(qh + src);
        *(uint4*)(smem + 16384 + swo) = *(const uint4*)(ql + src);
    }

#define FL_ISSUE(s) do { \
    const uint32_t base_ = 32768u + (uint32_t)((s) & 1)*32768u; \
    const int s0h_ = (s)*32; \
    _Pragma("unroll") \
    for (int i_ = 0; i_ < 2; i_++) { \
        int f_ = tid + i_*256; \
        int row_ = f_ >> 3, c_ = f_ & 7; \
        uint32_t swo_ = SW128((uint32_t)(row_*128 + c_*16)); \
        size_t ks_ = (size_t)(bh*NS + (s)*64 + row_)*32 + c_*4; \
        size_t vs_ = ((size_t)bh*64 + row_)*512 + s0h_ + c_*4; \
        cpa16(sb + base_ + swo_,         kh + ks_); \
        cpa16(sb + base_ + 8192 + swo_,  kl + ks_); \
        cpa16(sb + base_ + 16384 + swo_, vh + vs_); \
        cpa16(sb + base_ + 24576 + swo_, vl + vs_); \
    } \
    cp_commit(); \
} while(0)

    float o[8][4];
#pragma unroll
    for (int nt = 0; nt < 8; nt++)
#pragma unroll
        for (int e = 0; e < 4; e++) o[nt][e] = 0.f;
    float m_a = -1e30f, m_b = -1e30f, l_a = 0.f, l_b = 0.f;

    FL_ISSUE(0);
    for (int s = 0; s < 16; s++) {
        if (s < 15) { FL_ISSUE(s+1); cp_wait1(); } else cp_wait0();
        __syncthreads();
        const uint32_t base = 32768u + (uint32_t)(s & 1)*32768u;

        // ---- scores ----
        float sc[8][4];
#pragma unroll
        for (int nt = 0; nt < 8; nt++)
#pragma unroll
            for (int e = 0; e < 4; e++) sc[nt][e] = 0.f;
#pragma unroll
        for (int kk = 0; kk < 64; kk += 16) {
            uint32_t ahf[4], alf[4];
            uint32_t offA = SW128((uint32_t)((m0w + a_row)*128 + kk*2 + a_kb));
            ldsm4(ahf, sb + offA);
            ldsm4(alf, sb + 16384 + offA);
#pragma unroll
            for (int np = 0; np < 4; np++) {
                uint32_t offB = SW128((uint32_t)((np*16 + b_row)*128 + kk*2 + b_kb));
                uint32_t th[4], tl[4];
                ldsm4(th, sb + base + offB);
                ldsm4(tl, sb + base + 8192 + offB);
                uint32_t bh0[2] = {th[0], th[1]}, bh1[2] = {th[2], th[3]};
                uint32_t bl0[2] = {tl[0], tl[1]}, bl1[2] = {tl[2], tl[3]};
                mma_bf16(sc[2*np],   ahf, bh0);
                mma_bf16(sc[2*np+1], ahf, bh1);
                mma_bf16(sc[2*np],   ahf, bl0);
                mma_bf16(sc[2*np+1], ahf, bl1);
                mma_bf16(sc[2*np],   alf, bh0);
                mma_bf16(sc[2*np+1], alf, bh1);
            }
        }

        // ---- online softmax (log2 domain) ----
        float mxa = -1e30f, mxb = -1e30f;
#pragma unroll
        for (int nt = 0; nt < 8; nt++) {
            mxa = fmaxf(mxa, fmaxf(sc[nt][0], sc[nt][1]));
            mxb = fmaxf(mxb, fmaxf(sc[nt][2], sc[nt][3]));
        }
        mxa = fmaxf(mxa, __shfl_xor_sync(0xffffffffu, mxa, 1));
        mxa = fmaxf(mxa, __shfl_xor_sync(0xffffffffu, mxa, 2));
        mxb = fmaxf(mxb, __shfl_xor_sync(0xffffffffu, mxb, 1));
        mxb = fmaxf(mxb, __shfl_xor_sync(0xffffffffu, mxb, 2));
        float na = fmaxf(m_a, mxa), nb = fmaxf(m_b, mxb);
        float fa = ex2f(m_a - na), fb = ex2f(m_b - nb);
        m_a = na; m_b = nb;
        float sa = 0.f, sbv = 0.f;
#pragma unroll
        for (int nt = 0; nt < 8; nt++) {
            sc[nt][0] = ex2f(sc[nt][0] - na);
            sc[nt][1] = ex2f(sc[nt][1] - na);
            sc[nt][2] = ex2f(sc[nt][2] - nb);
            sc[nt][3] = ex2f(sc[nt][3] - nb);
            sa  += sc[nt][0] + sc[nt][1];
            sbv += sc[nt][2] + sc[nt][3];
        }
        sa  += __shfl_xor_sync(0xffffffffu, sa, 1);
        sa  += __shfl_xor_sync(0xffffffffu, sa, 2);
        sbv += __shfl_xor_sync(0xffffffffu, sbv, 1);
        sbv += __shfl_xor_sync(0xffffffffu, sbv, 2);
        l_a = l_a*fa + sa;
        l_b = l_b*fb + sbv;
#pragma unroll
        for (int nt = 0; nt < 8; nt++) {
            o[nt][0] *= fa; o[nt][1] *= fa;
            o[nt][2] *= fb; o[nt][3] *= fb;
        }

        // ---- PV ----
#pragma unroll
        for (int j = 0; j < 4; j++) {
            uint32_t pah[4], pal[4];
            split2(sc[2*j][0],   sc[2*j][1],   pah[0], pal[0]);
            split2(sc[2*j][2],   sc[2*j][3],   pah[1], pal[1]);
            split2(sc[2*j+1][0], sc[2*j+1][1], pah[2], pal[2]);
            split2(sc[2*j+1][2], sc[2*j+1][3], pah[3], pal[3]);
#pragma unroll
            for (int ng = 0; ng < 4; ng++) {
                uint32_t offV = SW128((uint32_t)((ng*16 + b_row)*128 + j*32 + b_kb));
                uint32_t th[4], tl[4];
                ldsm4(th, sb + base + 16384 + offV);
                ldsm4(tl, sb + base + 24576 + offV);
                uint32_t vh0[2] = {th[0], th[1]}, vh1[2] = {th[2], th[3]};
                uint32_t vl0[2] = {tl[0], tl[1]}, vl1[2] = {tl[2], tl[3]};
                mma_bf16(o[2*ng],   pah, vh0);
                mma_bf16(o[2*ng+1], pah, vh1);
                mma_bf16(o[2*ng],   pah, vl0);
                mma_bf16(o[2*ng+1], pah, vl1);
                mma_bf16(o[2*ng],   pal, vh0);
                mma_bf16(o[2*ng+1], pal, vh1);
            }
        }
        __syncthreads();
    }

    // ---- epilogue: normalize, stage (pitch 66), packed transposed write ----
    float* stg = (float*)smem;
    {
        float inva = 1.f / l_a, invb = 1.f / l_b;
        const int g = lid >> 2, tg = lid & 3;
#pragma unroll
        for (int nt = 0; nt < 8; nt++) {
            int r = m0w + g, c = nt*8 + tg*2;
            *(float2*)&stg[r*66 + c]     = make_float2(o[nt][0]*inva, o[nt][1]*inva);
            *(float2*)&stg[(r+8)*66 + c] = make_float2(o[nt][2]*invb, o[nt][3]*invb);
        }
    }
    __syncthreads();
    {
        const int d = tid & 63, quarter = tid >> 6;
        const size_t rowo = ((size_t)bh*64 + d)*512;
        const int lbase = l0 + quarter*32;
#pragma unroll
        for (int j = 0; j < 4; j++) {
            float x[8];
#pragma unroll
            for (int e = 0; e < 8; e++) x[e] = stg[(quarter*32 + j*8 + e)*66 + d];
            uint32_t h[4], l[4];
            split2(x[0],x[1],h[0],l[0]); split2(x[2],x[3],h[1],l[1]);
            split2(x[4],x[5],h[2],l[2]); split2(x[6],x[7],h[3],l[3]);
            size_t oo = rowo + (size_t)(lbase + j*8)/2;
            *(uint4*)&oth[oo] = make_uint4(h[0],h[1],h[2],h[3]);
            *(uint4*)&otl[oo] = make_uint4(l[0],l[1],l[2],l[3]);
        }
    }
}

// ---------------- small fp32 kernels -----------------------------------------
__global__ void __launch_bounds__(256) wep_kernel(
    const float* __restrict__ rq, const float* __restrict__ rk,
    float* __restrict__ wep)
{
    __shared__ float sq[64][65];
    __shared__ float sk[64][65];
    const int bh = blockIdx.x;
    const float* rqb = rq + (bh << 12);
    const float* rkb = rk + (bh << 12);
    const int tid = threadIdx.x;
#pragma unroll
    for (int i = 0; i < 4; i++) {
        int idx = (tid + i*256) << 2;
        int r = idx >> 6, c = idx & 63;
        float4 a = *(const float4*)&rqb[idx];
        float4 b = *(const float4*)&rkb[idx];
        sq[r][c] = a.x; sq[r][c+1] = a.y; sq[r][c+2] = a.z; sq[r][c+3] = a.w;
        sk[r][c] = b.x; sk[r][c+1] = b.y; sk[r][c+2] = b.z; sk[r][c+3] = b.w;
    }
    __syncthreads();
    const int tx = tid & 15, ty = tid >> 4;
    float acc[4][4];
#pragma unroll
    for (int i = 0; i < 4; i++)
#pragma unroll
        for (int j = 0; j < 4; j++) acc[i][j] = 0.f;
    for (int g = 0; g < 64; g++) {
        float a[4], b[4];
#pragma unroll
        for (int i = 0; i < 4; i++) a[i] = sq[g][ty*4+i];
#pragma unroll
        for (int j = 0; j < 4; j++) b[j] = sk[g][tx*4+j];
#pragma unroll
        for (int i = 0; i < 4; i++)
#pragma unroll
            for (int j = 0; j < 4; j++)
                acc[i][j] = fmaf(a[i], b[j], acc[i][j]);
    }
    const float scale = 0.125f * 1.4426950408889634f;  // 1/sqrt(64) * log2(e)
#pragma unroll
    for (int i = 0; i < 4; i++) {
        float4 r4 = make_float4(acc[i][0]*scale, acc[i][1]*scale,
                                acc[i][2]*scale, acc[i][3]*scale);
        *(float4*)&wep[(bh << 12) + (ty*4+i)*64 + tx*4] = r4;
    }
}

// qe = q @ W_ep, output packed hi/lo bf16
__global__ void __launch_bounds__(256) qfold_b(
    const float* __restrict__ q, const float* __restrict__ wep,
    uint32_t* __restrict__ qh, uint32_t* __restrict__ ql)
{
    __shared__ float sq[64][65];
    __shared__ float sw[64][68];
    const int bh = blockIdx.y;
    const int l0 = blockIdx.x * 64;
    const float* qb = q + (((size_t)bh * NL + l0) << 6);
    const float* wb = wep + (bh << 12);
    const int tid = threadIdx.x;
#pragma unroll
    for (int i = 0; i < 4; i++) {
        int idx = (tid + i*256) << 2;
        int r = idx >> 6, c = idx & 63;
        float4 vq = *(const float4*)&qb[idx];
        sq[r][c] = vq.x; sq[r][c+1] = vq.y; sq[r][c+2] = vq.z; sq[r][c+3] = vq.w;
        *(float4*)&sw[r][c] = *(const float4*)&wb[idx];
    }
    __syncthreads();
    const int tx = tid & 15, ty = tid >> 4;
    float acc[4][4];
#pragma unroll
    for (int i = 0; i < 4; i++)
#pragma unroll
        for (int j = 0; j < 4; j++) acc[i][j] = 0.f;
    for (int d = 0; d < 64; d++) {
        float a[4];
#pragma unroll
        for (int i = 0; i < 4; i++) a[i] = sq[ty*4+i][d];
        float4 wv = *(float4*)&sw[d][tx*4];
#pragma unroll
        for (int i = 0; i < 4; i++) {
            acc[i][0] = fmaf(a[i], wv.x, acc[i][0]);
            acc[i][1] = fmaf(a[i], wv.y, acc[i][1]);
            acc[i][2] = fmaf(a[i], wv.z, acc[i][2]);
            acc[i][3] = fmaf(a[i], wv.w, acc[i][3]);
        }
    }
#pragma unroll
    for (int i = 0; i < 4; i++) {
        uint32_t h0,l0v,h1,l1v;
        split2(acc[i][0],acc[i][1],h0,l0v);
        split2(acc[i][2],acc[i][3],h1,l1v);
        size_t row = (size_t)bh*NL + l0 + ty*4 + i;
        *(uint2*)&qh[row*32 + tx*2] = make_uint2(h0,h1);
        *(uint2*)&ql[row*32 + tx*2] = make_uint2(l0v,l1v);
    }
}

// ---------------- launch -----------------------------------------------------
extern "C" void kernel_launch(void* const* d_in, const int* in_sizes, int n_in,
                              void* d_out, int out_size)
{
    const float* queries = (const float*)d_in[0];
    const float* keys    = (const float*)d_in[1];
    const float* values  = (const float*)d_in[2];
    const float* routers = (const float*)d_in[3];
    const float* Wq  = (const float*)d_in[4];
    const float* Wk  = (const float*)d_in[5];
    const float* Wv  = (const float*)d_in[6];
    const float* Wlq = (const float*)d_in[7];
    const float* Wlk = (const float*)d_in[8];
    const float* Wo  = (const float*)d_in[9];
    const float* bo  = (const float*)d_in[10];

    float *q, *rq, *rk, *wep;
    uint32_t *inh, *inl, *wth, *wtl, *wth2, *wtl2;
    uint32_t *qh, *ql, *kh, *kl, *vth, *vtl, *oth, *otl;
    cudaGetSymbolAddress((void**)&q,    g_q);
    cudaGetSymbolAddress((void**)&rq,   g_rq);
    cudaGetSymbolAddress((void**)&rk,   g_rk);
    cudaGetSymbolAddress((void**)&wep,  g_wep);
    cudaGetSymbolAddress((void**)&inh,  g_inh);
    cudaGetSymbolAddress((void**)&inl,  g_inl);
    cudaGetSymbolAddress((void**)&wth,  g_wth);
    cudaGetSymbolAddress((void**)&wtl,  g_wtl);
    cudaGetSymbolAddress((void**)&wth2, g_wth2);
    cudaGetSymbolAddress((void**)&wtl2, g_wtl2);
    cudaGetSymbolAddress((void**)&qh,   g_qh);
    cudaGetSymbolAddress((void**)&ql,   g_ql);
    cudaGetSymbolAddress((void**)&kh,   g_kh);
    cudaGetSymbolAddress((void**)&kl,   g_kl);
    cudaGetSymbolAddress((void**)&vth,  g_vth);
    cudaGetSymbolAddress((void**)&vtl,  g_vtl);
    cudaGetSymbolAddress((void**)&oth,  g_oth);
    cudaGetSymbolAddress((void**)&otl,  g_otl);

    static int attr_done = 0;
    if (!attr_done) {
        cudaFuncSetAttribute(mm_projb<0>, cudaFuncAttributeMaxDynamicSharedMemorySize, 131072);
        cudaFuncSetAttribute(mm_projb<1>, cudaFuncAttributeMaxDynamicSharedMemorySize, 131072);
        cudaFuncSetAttribute(mm_projb<2>, cudaFuncAttributeMaxDynamicSharedMemorySize, 131072);
        cudaFuncSetAttribute(mm_projb<3>, cudaFuncAttributeMaxDynamicSharedMemorySize, 131072);
        cudaFuncSetAttribute(flash2,      cudaFuncAttributeMaxDynamicSharedMemorySize, 98304);
        attr_done = 1;
    }

    dim3 blk(256);
    dim3 wgrid(32, 32);
    const int n8_big = NB*NL*ND/8;       // 1,048,576
    const int n8_rt  = NB*NG*ND/8;       // 65,536

    // Q projection -> fp32 head-split (consumed by qfold)
    split_a<<<n8_big/256, blk>>>(queries, inh, inl, n8_big);
    split_w<<<wgrid, blk>>>(Wq, wth, wtl);
    mm_projb<1><<<dim3(64,8), blk, 131072>>>(inh, inl, wth, wtl,
        q, nullptr, nullptr, nullptr, NL, nullptr, nullptr, nullptr);

    // K projection -> packed hi/lo
    split_a<<<n8_big/256, blk>>>(keys, inh, inl, n8_big);
    split_w<<<wgrid, blk>>>(Wk, wth, wtl);
    mm_projb<2><<<dim3(64,8), blk, 131072>>>(inh, inl, wth, wtl,
        nullptr, kh, kl, nullptr, NS, nullptr, nullptr, nullptr);

    // V projection -> packed transposed hi/lo
    split_a<<<n8_big/256, blk>>>(values, inh, inl, n8_big);
    split_w<<<wgrid, blk>>>(Wv, wth, wtl);
    mm_projb<3><<<dim3(64,8), blk, 131072>>>(inh, inl, wth, wtl,
        nullptr, vth, vtl, nullptr, NS, nullptr, nullptr, nullptr);

    // router projections (both in one launch via blockIdx.z)
    split_a<<<n8_rt/256, blk>>>(routers, inh, inl, n8_rt);
    split_w<<<wgrid, blk>>>(Wlq, wth, wtl);
    split_w<<<wgrid, blk>>>(Wlk, wth2, wtl2);
    mm_projb<1><<<dim3(4,8,2), blk, 131072>>>(inh, inl, wth, wtl,
        rq, nullptr, nullptr, nullptr, NG, wth2, wtl2, rk);

    wep_kernel<<<128, blk>>>(rq, rk, wep);
    qfold_b<<<dim3(16,128), blk>>>(q, wep, qh, ql);

    flash2<<<dim3(8,128), blk, 98304>>>(qh, ql, kh, kl, vth, vtl, oth, otl);

    // final projection
    split_w<<<wgrid, blk>>>(Wo, wth, wtl);
    mm_projb<0><<<dim3(64,8), blk, 131072>>>(oth, otl, wth, wtl,
        (float*)d_out, nullptr, nullptr, bo, NL, nullptr, nullptr, nullptr);
}

// round 12
// speedup vs baseline: 3.4798x; 1.0144x over previous
#include <cuda_runtime.h>
#include <cuda_bf16.h>
#include <math.h>
#include <stdint.h>

#define NB 8
#define NL 1024
#define NS 1024
#define NG 64
#define ND 1024
#define NH 16
#define DH 64

#define INOFS  (NB*NL*ND/2)   /* 4194304 uint32 per split buffer */
#define RINOFS (NB*NG*ND/2)   /* 262144 */
#define WOFS   (ND*ND/2)      /* 524288 */

// ---------------- scratch (device globals) -----------------------------------
__device__ float    g_q  [NB*NH*NL*DH];
__device__ float    g_rq [NB*NH*NG*DH];
__device__ float    g_rk [NB*NH*NG*DH];
__device__ float    g_wep[NB*NH*DH*DH];
__device__ uint32_t g_inh[3*INOFS],  g_inl[3*INOFS];
__device__ uint32_t g_rinh[RINOFS], g_rinl[RINOFS];
__device__ uint32_t g_wh [6*WOFS],  g_wl [6*WOFS];
__device__ uint32_t g_qh [NB*NH*NL*DH/2], g_ql [NB*NH*NL*DH/2];
__device__ uint32_t g_kh [NB*NH*NS*DH/2], g_kl [NB*NH*NS*DH/2];
__device__ uint32_t g_vth[NB*NH*DH*NS/2], g_vtl[NB*NH*DH*NS/2];
__device__ uint32_t g_oth[NB*ND*NL/2],    g_otl[NB*ND*NL/2];

// ---------------- helpers ----------------------------------------------------
__device__ __forceinline__ uint32_t smem_u32(const void* p){
    uint32_t a;
    asm("{ .reg .u64 t; cvta.to.shared.u64 t, %1; cvt.u32.u64 %0, t; }"
        : "=r"(a) : "l"(p));
    return a;
}
#define SW128(o) ((o) ^ (((o) >> 3) & 0x70))

__device__ __forceinline__ void ldsm4(uint32_t* r, uint32_t a){
    asm volatile("ldmatrix.sync.aligned.m8n8.x4.shared.b16 {%0,%1,%2,%3}, [%4];"
        : "=r"(r[0]), "=r"(r[1]), "=r"(r[2]), "=r"(r[3]) : "r"(a));
}
__device__ __forceinline__ void mma_bf16(float* c, const uint32_t* a, const uint32_t* b){
    asm volatile("mma.sync.aligned.m16n8k16.row.col.f32.bf16.bf16.f32 "
        "{%0,%1,%2,%3}, {%4,%5,%6,%7}, {%8,%9}, {%0,%1,%2,%3};"
        : "+f"(c[0]), "+f"(c[1]), "+f"(c[2]), "+f"(c[3])
        : "r"(a[0]), "r"(a[1]), "r"(a[2]), "r"(a[3]), "r"(b[0]), "r"(b[1]));
}
__device__ __forceinline__ float ex2f(float x){
    float y; asm("ex2.approx.f32 %0, %1;" : "=f"(y) : "f"(x)); return y;
}
__device__ __forceinline__ void cpa16(uint32_t d, const void* s){
    asm volatile("cp.async.cg.shared.global [%0], [%1], 16;" :: "r"(d), "l"(s));
}
__device__ __forceinline__ void cp_commit(){ asm volatile("cp.async.commit_group;"); }
__device__ __forceinline__ void cp_wait2(){ asm volatile("cp.async.wait_group 2;"); }
__device__ __forceinline__ void cp_wait1(){ asm volatile("cp.async.wait_group 1;"); }
__device__ __forceinline__ void cp_wait0(){ asm volatile("cp.async.wait_group 0;"); }

__device__ __forceinline__ void split2(float x, float y, uint32_t& hi, uint32_t& lo){
    __nv_bfloat16 xh = __float2bfloat16(x);
    __nv_bfloat16 yh = __float2bfloat16(y);
    __nv_bfloat16 xl = __float2bfloat16(x - __bfloat162float(xh));
    __nv_bfloat16 yl = __float2bfloat16(y - __bfloat162float(yh));
    hi = (uint32_t)__bfloat16_as_ushort(xh) | ((uint32_t)__bfloat16_as_ushort(yh) << 16);
    lo = (uint32_t)__bfloat16_as_ushort(xl) | ((uint32_t)__bfloat16_as_ushort(yl) << 16);
}

// ---------------- split kernels ----------------------------------------------
// 3 big inputs in one launch: blockIdx.y selects src, writes buffer y
__global__ void __launch_bounds__(256) split_a3(
    const float* __restrict__ q, const float* __restrict__ k,
    const float* __restrict__ v,
    uint32_t* __restrict__ hi, uint32_t* __restrict__ lo, int n8)
{
    int g = blockIdx.x*256 + threadIdx.x;
    if (g >= n8) return;
    const float* src = (blockIdx.y == 0) ? q : ((blockIdx.y == 1) ? k : v);
    uint32_t* H = hi + (size_t)blockIdx.y*INOFS;
    uint32_t* L = lo + (size_t)blockIdx.y*INOFS;
    float4 a = ((const float4*)src)[g*2];
    float4 b = ((const float4*)src)[g*2+1];
    uint32_t h[4], l[4];
    split2(a.x,a.y,h[0],l[0]); split2(a.z,a.w,h[1],l[1]);
    split2(b.x,b.y,h[2],l[2]); split2(b.z,b.w,h[3],l[3]);
    ((uint4*)H)[g] = make_uint4(h[0],h[1],h[2],h[3]);
    ((uint4*)L)[g] = make_uint4(l[0],l[1],l[2],l[3]);
}

__global__ void __launch_bounds__(256) split_a(
    const float* __restrict__ A, uint32_t* __restrict__ hi,
    uint32_t* __restrict__ lo, int n8)
{
    int g = blockIdx.x*256 + threadIdx.x;
    if (g >= n8) return;
    float4 a = ((const float4*)A)[g*2];
    float4 b = ((const float4*)A)[g*2+1];
    uint32_t h[4], l[4];
    split2(a.x,a.y,h[0],l[0]); split2(a.z,a.w,h[1],l[1]);
    split2(b.x,b.y,h[2],l[2]); split2(b.z,b.w,h[3],l[3]);
    ((uint4*)hi)[g] = make_uint4(h[0],h[1],h[2],h[3]);
    ((uint4*)lo)[g] = make_uint4(l[0],l[1],l[2],l[3]);
}

// all 6 weights in one launch; blockIdx.z selects
__global__ void __launch_bounds__(256) split_w6(
    const float* __restrict__ W0, const float* __restrict__ W1,
    const float* __restrict__ W2, const float* __restrict__ W3,
    const float* __restrict__ W4, const float* __restrict__ W5,
    uint32_t* __restrict__ th, uint32_t* __restrict__ tl)
{
    __shared__ float t[32][33];
    const int z = blockIdx.z;
    const float* W = (z==0)?W0:(z==1)?W1:(z==2)?W2:(z==3)?W3:(z==4)?W4:W5;
    uint32_t* TH = th + (size_t)z*WOFS;
    uint32_t* TL = tl + (size_t)z*WOFS;
    const int k0 = blockIdx.x*32, n0 = blockIdx.y*32;
    const int tid = threadIdx.x;
    const int c = tid & 31, r = tid >> 5;
#pragma unroll
    for (int i = 0; i < 4; i++)
        t[r + i*8][c] = W[(size_t)(k0 + r + i*8)*1024 + n0 + c];
    __syncthreads();
    const int nl = tid >> 3, kp = (tid & 7)*2;
    uint32_t h0,l0v,h1,l1v;
    split2(t[kp*2][nl],   t[kp*2+1][nl], h0, l0v);
    split2(t[kp*2+2][nl], t[kp*2+3][nl], h1, l1v);
    size_t o = (size_t)(n0+nl)*512 + k0/2 + kp;
    *(uint2*)&TH[o] = make_uint2(h0,h1);
    *(uint2*)&TL[o] = make_uint2(l0v,l1v);
}

// ---------------- shared mainloop macros (3-stage pipeline) ------------------
#define GEMM_ISSUE(s, Ah, Al, Bh, Bl) do { \
    const uint32_t base_ = (uint32_t)((s)%3)*65536u; \
    const int k0h_ = (s)*32; \
    _Pragma("unroll") \
    for (int i_ = 0; i_ < 4; i_++) { \
        int f_ = tid + i_*256; \
        int row_ = f_ >> 3, c_ = f_ & 7; \
        uint32_t swo_ = SW128((uint32_t)(row_*128 + c_*16)); \
        cpa16(sb + base_ + swo_,         (Ah) + (size_t)(m0+row_)*512 + k0h_ + c_*4); \
        cpa16(sb + base_ + 16384 + swo_, (Al) + (size_t)(m0+row_)*512 + k0h_ + c_*4); \
        cpa16(sb + base_ + 32768 + swo_, (Bh) + (size_t)(n0+row_)*512 + k0h_ + c_*4); \
        cpa16(sb + base_ + 49152 + swo_, (Bl) + (size_t)(n0+row_)*512 + k0h_ + c_*4); \
    } \
    cp_commit(); \
} while(0)

#define GEMM_COMPUTE(base) do { \
    _Pragma("unroll") \
    for (int kk = 0; kk < 64; kk += 16) { \
        uint32_t ahf[4][4], alf[4][4], bhf[4][2], blf[4][2]; \
        _Pragma("unroll") \
        for (int mt = 0; mt < 4; mt++) { \
            uint32_t off = SW128((uint32_t)((m0w + mt*16 + a_row)*128 + kk*2 + a_kb)); \
            ldsm4(ahf[mt], sb + (base) + off); \
            ldsm4(alf[mt], sb + (base) + 16384 + off); \
        } \
        _Pragma("unroll") \
        for (int np = 0; np < 2; np++) { \
            uint32_t off = SW128((uint32_t)((n0w + np*16 + b_row)*128 + kk*2 + b_kb)); \
            uint32_t t[4]; \
            ldsm4(t, sb + (base) + 32768 + off); \
            bhf[np*2][0]=t[0]; bhf[np*2][1]=t[1]; bhf[np*2+1][0]=t[2]; bhf[np*2+1][1]=t[3]; \
            ldsm4(t, sb + (base) + 49152 + off); \
            blf[np*2][0]=t[0]; blf[np*2][1]=t[1]; blf[np*2+1][0]=t[2]; blf[np*2+1][1]=t[3]; \
        } \
        _Pragma("unroll") \
        for (int mt = 0; mt < 4; mt++) \
            _Pragma("unroll") \
            for (int nt = 0; nt < 4; nt++) { \
                mma_bf16(acc[mt][nt], ahf[mt], bhf[nt]); \
                mma_bf16(acc[mt][nt], ahf[mt], blf[nt]); \
                mma_bf16(acc[mt][nt], alf[mt], bhf[nt]); \
            } \
    } \
} while(0)

#define GEMM_STAGE_ACC() do { \
    const int g = lid >> 2, tg = lid & 3; \
    _Pragma("unroll") \
    for (int mt = 0; mt < 4; mt++) \
        _Pragma("unroll") \
        for (int nt = 0; nt < 4; nt++) { \
            int r = m0w + mt*16 + g, c = n0w + nt*8 + tg*2; \
            *(float2*)&stg[r*132 + c]     = make_float2(acc[mt][nt][0], acc[mt][nt][1]); \
            *(float2*)&stg[(r+8)*132 + c] = make_float2(acc[mt][nt][2], acc[mt][nt][3]); \
        } \
} while(0)

// ============= mm_qkv: all three QKV projections in one launch ===============
// z=0: Q -> fp32 head-split. z=1: K -> packed hi/lo. z=2: V -> packed transposed.
__global__ void __launch_bounds__(256,1) mm_qkv(
    const uint32_t* __restrict__ inh, const uint32_t* __restrict__ inl,
    const uint32_t* __restrict__ wh, const uint32_t* __restrict__ wl,
    float* __restrict__ qout,
    uint32_t* __restrict__ kh, uint32_t* __restrict__ kl,
    uint32_t* __restrict__ vth, uint32_t* __restrict__ vtl)
{
    extern __shared__ char smem[];
    const uint32_t sb = smem_u32(smem);
    const int tid = threadIdx.x, lid = tid & 31, wid = tid >> 5;
    const int m0 = blockIdx.x*128, n0 = blockIdx.y*128;
    const int z = blockIdx.z;
    const uint32_t* Ah = inh + (size_t)z*INOFS;
    const uint32_t* Al = inl + (size_t)z*INOFS;
    const uint32_t* Bh = wh + (size_t)z*WOFS;
    const uint32_t* Bl = wl + (size_t)z*WOFS;

    const int m0w = (wid & 1)*64, n0w = (wid >> 1)*32;
    const int a_row = (lid & 7) + ((lid >> 3) & 1)*8;
    const int a_kb  = (lid >> 4)*16;
    const int b_row = (lid & 7) + ((lid >> 4) & 1)*8;
    const int b_kb  = ((lid >> 3) & 1)*16;

    float acc[4][4][4];
#pragma unroll
    for (int i = 0; i < 4; i++)
#pragma unroll
        for (int j = 0; j < 4; j++)
#pragma unroll
            for (int e = 0; e < 4; e++) acc[i][j][e] = 0.f;

    GEMM_ISSUE(0, Ah, Al, Bh, Bl);
    GEMM_ISSUE(1, Ah, Al, Bh, Bl);
    for (int s = 0; s < 16; s++) {
        if (s <= 13) { GEMM_ISSUE(s+2, Ah, Al, Bh, Bl); cp_wait2(); }
        else if (s == 14) cp_wait1();
        else cp_wait0();
        __syncthreads();
        const uint32_t base = (uint32_t)(s % 3)*65536u;
        GEMM_COMPUTE(base);
        __syncthreads();
    }

    float* stg = (float*)smem;
    GEMM_STAGE_ACC();
    __syncthreads();

    if (z == 0) {
#pragma unroll
        for (int i = 0; i < 16; i++) {
            int f = tid + i*256;
            int r = f >> 5, c4 = f & 31;
            float4 val = *(float4*)&stg[r*132 + c4*4];
            int m = m0 + r, n = n0 + c4*4;
            int bq = m >> 10, t = m & 1023;
            int h = n >> 6, d = n & 63;
            *(float4*)&qout[(size_t)((bq*NH + h)*1024 + t)*64 + d] = val;
        }
    } else if (z == 1) {
#pragma unroll
        for (int i = 0; i < 16; i++) {
            int f = tid + i*256;
            int r = f >> 5, c4 = f & 31;
            float4 val = *(float4*)&stg[r*132 + c4*4];
            int m = m0 + r, n = n0 + c4*4;
            int bq = m >> 10, t = m & 1023;
            int h = n >> 6, d = n & 63;
            uint32_t h0,l0v,h1,l1v;
            split2(val.x,val.y,h0,l0v); split2(val.z,val.w,h1,l1v);
            size_t o = ((size_t)(bq*NH + h)*1024 + t)*32 + (d >> 1);
            *(uint2*)&kh[o] = make_uint2(h0,h1);
            *(uint2*)&kl[o] = make_uint2(l0v,l1v);
        }
    } else {
        const int nl = tid & 127, half = tid >> 7;
        const int n = n0 + nl;
        const int hh = n >> 6, d = n & 63;
        const int bq = m0 >> 10;
        const size_t rowv = ((size_t)(bq*NH + hh)*64 + d)*512;
        const int tbase = (m0 & 1023) + half*64;
#pragma unroll
        for (int j = 0; j < 8; j++) {
            float x[8];
#pragma unroll
            for (int e = 0; e < 8; e++) x[e] = stg[(half*64 + j*8 + e)*132 + nl];
            uint32_t h[4], l[4];
            split2(x[0],x[1],h[0],l[0]); split2(x[2],x[3],h[1],l[1]);
            split2(x[4],x[5],h[2],l[2]); split2(x[6],x[7],h[3],l[3]);
            size_t o = rowv + (size_t)(tbase + j*8)/2;
            *(uint4*)&vth[o] = make_uint4(h[0],h[1],h[2],h[3]);
            *(uint4*)&vtl[o] = make_uint4(l[0],l[1],l[2],l[3]);
        }
    }
}

// ============= mm_projb: generic GEMM (router MODE 1, final MODE 0) ==========
template<int MODE>
__global__ void __launch_bounds__(256,1) mm_projb(
    const uint32_t* __restrict__ Ah, const uint32_t* __restrict__ Al,
    const uint32_t* __restrict__ Bh_, const uint32_t* __restrict__ Bl_,
    float* __restrict__ Yf_, const float* __restrict__ bias, int Ntok,
    const uint32_t* __restrict__ B2h, const uint32_t* __restrict__ B2l,
    float* __restrict__ Y2f)
{
    extern __shared__ char smem[];
    const uint32_t sb = smem_u32(smem);
    const int tid = threadIdx.x, lid = tid & 31, wid = tid >> 5;
    const int m0 = blockIdx.x*128, n0 = blockIdx.y*128;
    const uint32_t* Bh = blockIdx.z ? B2h : Bh_;
    const uint32_t* Bl = blockIdx.z ? B2l : Bl_;
    float* Yf = blockIdx.z ? Y2f : Yf_;

    const int m0w = (wid & 1)*64, n0w = (wid >> 1)*32;
    const int a_row = (lid & 7) + ((lid >> 3) & 1)*8;
    const int a_kb  = (lid >> 4)*16;
    const int b_row = (lid & 7) + ((lid >> 4) & 1)*8;
    const int b_kb  = ((lid >> 3) & 1)*16;

    float acc[4][4][4];
#pragma unroll
    for (int i = 0; i < 4; i++)
#pragma unroll
        for (int j = 0; j < 4; j++)
#pragma unroll
            for (int e = 0; e < 4; e++) acc[i][j][e] = 0.f;

    GEMM_ISSUE(0, Ah, Al, Bh, Bl);
    GEMM_ISSUE(1, Ah, Al, Bh, Bl);
    for (int s = 0; s < 16; s++) {
        if (s <= 13) { GEMM_ISSUE(s+2, Ah, Al, Bh, Bl); cp_wait2(); }
        else if (s == 14) cp_wait1();
        else cp_wait0();
        __syncthreads();
        const uint32_t base = (uint32_t)(s % 3)*65536u;
        GEMM_COMPUTE(base);
        __syncthreads();
    }

    float* stg = (float*)smem;
    GEMM_STAGE_ACC();
    __syncthreads();

#pragma unroll
    for (int i = 0; i < 16; i++) {
        int f = tid + i*256;
        int r = f >> 5, c4 = f & 31;
        float4 val = *(float4*)&stg[r*132 + c4*4];
        int m = m0 + r, n = n0 + c4*4;
        if (MODE == 0) {
            float4 bb = *(const float4*)&bias[n];
            val.x += bb.x; val.y += bb.y; val.z += bb.z; val.w += bb.w;
            *(float4*)&Yf[(size_t)m*1024 + n] = val;
        } else {
            int bq = m / Ntok, t = m - bq*Ntok;
            int h = n >> 6, d = n & 63;
            *(float4*)&Yf[(size_t)((bq*NH + h)*Ntok + t)*64 + d] = val;
        }
    }
}

// ============= flash2: fused attention, 3-stage pipeline =====================
// smem: Qh@0 16K | Ql@16384 | 3 bufs @32768: { Kh 8K | Kl 8K | Vh 8K | Vl 8K }
__global__ void __launch_bounds__(256,1) flash2(
    const uint32_t* __restrict__ qh, const uint32_t* __restrict__ ql,
    const uint32_t* __restrict__ kh, const uint32_t* __restrict__ kl,
    const uint32_t* __restrict__ vh, const uint32_t* __restrict__ vl,
    uint32_t* __restrict__ oth, uint32_t* __restrict__ otl)
{
    extern __shared__ char smem[];
    const uint32_t sb = smem_u32(smem);
    const int tid = threadIdx.x, lid = tid & 31, wid = tid >> 5;
    const int l0 = blockIdx.x*128, bh = blockIdx.y;
    const int m0w = wid*16;

    const int a_row = (lid & 7) + ((lid >> 3) & 1)*8;
    const int a_kb  = (lid >> 4)*16;
    const int b_row = (lid & 7) + ((lid >> 4) & 1)*8;
    const int b_kb  = ((lid >> 3) & 1)*16;

    // Q tile (direct loads)
#pragma unroll
    for (int i = 0; i < 4; i++) {
        int f = tid + i*256;
        int row = f >> 3, c = f & 7;
        uint32_t swo = SW128((uint32_t)(row*128 + c*16));
        size_t src = (size_t)(bh*NL + l0 + row)*32 + c*4;
        *(uint4*)(smem + swo)         = *(const uint4*)(qh + src);
        *(uint4*)(smem + 16384 + swo) = *(const uint4*)(ql + src);
    }

#define FL_ISSUE(s) do { \
    const uint32_t base_ = 32768u + (uint32_t)((s) % 3)*32768u; \
    const int s0h_ = (s)*32; \
    _Pragma("unroll") \
    for (int i_ = 0; i_ < 2; i_++) { \
        int f_ = tid + i_*256; \
        int row_ = f_ >> 3, c_ = f_ & 7; \
        uint32_t swo_ = SW128((uint32_t)(row_*128 + c_*16)); \
        size_t ks_ = (size_t)(bh*NS + (s)*64 + row_)*32 + c_*4; \
        size_t vs_ = ((size_t)bh*64 + row_)*512 + s0h_ + c_*4; \
        cpa16(sb + base_ + swo_,         kh + ks_); \
        cpa16(sb + base_ + 8192 + swo_,  kl + ks_); \
        cpa16(sb + base_ + 16384 + swo_, vh + vs_); \
        cpa16(sb + base_ + 24576 + swo_, vl + vs_); \
    } \
    cp_commit(); \
} while(0)

    float o[8][4];
#pragma unroll
    for (int nt = 0; nt < 8; nt++)
#pragma unroll
        for (int e = 0; e < 4; e++) o[nt][e] = 0.f;
    float m_a = -1e30f, m_b = -1e30f, l_a = 0.f, l_b = 0.f;

    FL_ISSUE(0);
    FL_ISSUE(1);
    for (int s = 0; s < 16; s++) {
        if (s <= 13) { FL_ISSUE(s+2); cp_wait2(); }
        else if (s == 14) cp_wait1();
        else cp_wait0();
        __syncthreads();
        const uint32_t base = 32768u + (uint32_t)(s % 3)*32768u;

        // ---- scores ----
        float sc[8][4];
#pragma unroll
        for (int nt = 0; nt < 8; nt++)
#pragma unroll
            for (int e = 0; e < 4; e++) sc[nt][e] = 0.f;
#pragma unroll
        for (int kk = 0; kk < 64; kk += 16) {
            uint32_t ahf[4], alf[4];
            uint32_t offA = SW128((uint32_t)((m0w + a_row)*128 + kk*2 + a_kb));
            ldsm4(ahf, sb + offA);
            ldsm4(alf, sb + 16384 + offA);
#pragma unroll
            for (int np = 0; np < 4; np++) {
                uint32_t offB = SW128((uint32_t)((np*16 + b_row)*128 + kk*2 + b_kb));
                uint32_t th[4], tl[4];
                ldsm4(th, sb + base + offB);
                ldsm4(tl, sb + base + 8192 + offB);
                uint32_t bh0[2] = {th[0], th[1]}, bh1[2] = {th[2], th[3]};
                uint32_t bl0[2] = {tl[0], tl[1]}, bl1[2] = {tl[2], tl[3]};
                mma_bf16(sc[2*np],   ahf, bh0);
                mma_bf16(sc[2*np+1], ahf, bh1);
                mma_bf16(sc[2*np],   ahf, bl0);
                mma_bf16(sc[2*np+1], ahf, bl1);
                mma_bf16(sc[2*np],   alf, bh0);
                mma_bf16(sc[2*np+1], alf, bh1);
            }
        }

        // ---- online softmax (log2 domain) ----
        float mxa = -1e30f, mxb = -1e30f;
#pragma unroll
        for (int nt = 0; nt < 8; nt++) {
            mxa = fmaxf(mxa, fmaxf(sc[nt][0], sc[nt][1]));
            mxb = fmaxf(mxb, fmaxf(sc[nt][2], sc[nt][3]));
        }
        mxa = fmaxf(mxa, __shfl_xor_sync(0xffffffffu, mxa, 1));
        mxa = fmaxf(mxa, __shfl_xor_sync(0xffffffffu, mxa, 2));
        mxb = fmaxf(mxb, __shfl_xor_sync(0xffffffffu, mxb, 1));
        mxb = fmaxf(mxb, __shfl_xor_sync(0xffffffffu, mxb, 2));
        float na = fmaxf(m_a, mxa), nb = fmaxf(m_b, mxb);
        float fa = ex2f(m_a - na), fb = ex2f(m_b - nb);
        m_a = na; m_b = nb;
        float sa = 0.f, sbv = 0.f;
#pragma unroll
        for (int nt = 0; nt < 8; nt++) {
            sc[nt][0] = ex2f(sc[nt][0] - na);
            sc[nt][1] = ex2f(sc[nt][1] - na);
            sc[nt][2] = ex2f(sc[nt][2] - nb);
            sc[nt][3] = ex2f(sc[nt][3] - nb);
            sa  += sc[nt][0] + sc[nt][1];
            sbv += sc[nt][2] + sc[nt][3];
        }
        sa  += __shfl_xor_sync(0xffffffffu, sa, 1);
        sa  += __shfl_xor_sync(0xffffffffu, sa, 2);
        sbv += __shfl_xor_sync(0xffffffffu, sbv, 1);
        sbv += __shfl_xor_sync(0xffffffffu, sbv, 2);
        l_a = l_a*fa + sa;
        l_b = l_b*fb + sbv;
#pragma unroll
        for (int nt = 0; nt < 8; nt++) {
            o[nt][0] *= fa; o[nt][1] *= fa;
            o[nt][2] *= fb; o[nt][3] *= fb;
        }

        // ---- PV ----
#pragma unroll
        for (int j = 0; j < 4; j++) {
            uint32_t pah[4], pal[4];
            split2(sc[2*j][0],   sc[2*j][1],   pah[0], pal[0]);
            split2(sc[2*j][2],   sc[2*j][3],   pah[1], pal[1]);
            split2(sc[2*j+1][0], sc[2*j+1][1], pah[2], pal[2]);
            split2(sc[2*j+1][2], sc[2*j+1][3], pah[3], pal[3]);
#pragma unroll
            for (int ng = 0; ng < 4; ng++) {
                uint32_t offV = SW128((uint32_t)((ng*16 + b_row)*128 + j*32 + b_kb));
                uint32_t th[4], tl[4];
                ldsm4(th, sb + base + 16384 + offV);
                ldsm4(tl, sb + base + 24576 + offV);
                uint32_t vh0[2] = {th[0], th[1]}, vh1[2] = {th[2], th[3]};
                uint32_t vl0[2] = {tl[0], tl[1]}, vl1[2] = {tl[2], tl[3]};
                mma_bf16(o[2*ng],   pah, vh0);
                mma_bf16(o[2*ng+1], pah, vh1);
                mma_bf16(o[2*ng],   pah, vl0);
                mma_bf16(o[2*ng+1], pah, vl1);
                mma_bf16(o[2*ng],   pal, vh0);
                mma_bf16(o[2*ng+1], pal, vh1);
            }
        }
        __syncthreads();
    }

    // ---- epilogue: normalize, stage (pitch 66), packed transposed write ----
    float* stg = (float*)smem;
    {
        float inva = 1.f / l_a, invb = 1.f / l_b;
        const int g = lid >> 2, tg = lid & 3;
#pragma unroll
        for (int nt = 0; nt < 8; nt++) {
            int r = m0w + g, c = nt*8 + tg*2;
            *(float2*)&stg[r*66 + c]     = make_float2(o[nt][0]*inva, o[nt][1]*inva);
            *(float2*)&stg[(r+8)*66 + c] = make_float2(o[nt][2]*invb, o[nt][3]*invb);
        }
    }
    __syncthreads();
    {
        const int d = tid & 63, quarter = tid >> 6;
        const size_t rowo = ((size_t)bh*64 + d)*512;
        const int lbase = l0 + quarter*32;
#pragma unroll
        for (int j = 0; j < 4; j++) {
            float x[8];
#pragma unroll
            for (int e = 0; e < 8; e++) x[e] = stg[(quarter*32 + j*8 + e)*66 + d];
            uint32_t h[4], l[4];
            split2(x[0],x[1],h[0],l[0]); split2(x[2],x[3],h[1],l[1]);
            split2(x[4],x[5],h[2],l[2]); split2(x[6],x[7],h[3],l[3]);
            size_t oo = rowo + (size_t)(lbase + j*8)/2;
            *(uint4*)&oth[oo] = make_uint4(h[0],h[1],h[2],h[3]);
            *(uint4*)&otl[oo] = make_uint4(l[0],l[1],l[2],l[3]);
        }
    }
}

// ---------------- small fp32 kernels -----------------------------------------
__global__ void __launch_bounds__(256) wep_kernel(
    const float* __restrict__ rq, const float* __restrict__ rk,
    float* __restrict__ wep)
{
    __shared__ float sq[64][65];
    __shared__ float sk[64][65];
    const int bh = blockIdx.x;
    const float* rqb = rq + (bh << 12);
    const float* rkb = rk + (bh << 12);
    const int tid = threadIdx.x;
#pragma unroll
    for (int i = 0; i < 4; i++) {
        int idx = (tid + i*256) << 2;
        int r = idx >> 6, c = idx & 63;
        float4 a = *(const float4*)&rqb[idx];
        float4 b = *(const float4*)&rkb[idx];
        sq[r][c] = a.x; sq[r][c+1] = a.y; sq[r][c+2] = a.z; sq[r][c+3] = a.w;
        sk[r][c] = b.x; sk[r][c+1] = b.y; sk[r][c+2] = b.z; sk[r][c+3] = b.w;
    }
    __syncthreads();
    const int tx = tid & 15, ty = tid >> 4;
    float acc[4][4];
#pragma unroll
    for (int i = 0; i < 4; i++)
#pragma unroll
        for (int j = 0; j < 4; j++) acc[i][j] = 0.f;
    for (int g = 0; g < 64; g++) {
        float a[4], b[4];
#pragma unroll
        for (int i = 0; i < 4; i++) a[i] = sq[g][ty*4+i];
#pragma unroll
        for (int j = 0; j < 4; j++) b[j] = sk[g][tx*4+j];
#pragma unroll
        for (int i = 0; i < 4; i++)
#pragma unroll
            for (int j = 0; j < 4; j++)
                acc[i][j] = fmaf(a[i], b[j], acc[i][j]);
    }
    const float scale = 0.125f * 1.4426950408889634f;  // 1/sqrt(64) * log2(e)
#pragma unroll
    for (int i = 0; i < 4; i++) {
        float4 r4 = make_float4(acc[i][0]*scale, acc[i][1]*scale,
                                acc[i][2]*scale, acc[i][3]*scale);
        *(float4*)&wep[(bh << 12) + (ty*4+i)*64 + tx*4] = r4;
    }
}

// qe = q @ W_ep, output packed hi/lo bf16
__global__ void __launch_bounds__(256) qfold_b(
    const float* __restrict__ q, const float* __restrict__ wep,
    uint32_t* __restrict__ qh, uint32_t* __restrict__ ql)
{
    __shared__ float sq[64][65];
    __shared__ float sw[64][68];
    const int bh = blockIdx.y;
    const int l0 = blockIdx.x * 64;
    const float* qb = q + (((size_t)bh * NL + l0) << 6);
    const float* wb = wep + (bh << 12);
    const int tid = threadIdx.x;
#pragma unroll
    for (int i = 0; i < 4; i++) {
        int idx = (tid + i*256) << 2;
        int r = idx >> 6, c = idx & 63;
        float4 vq = *(const float4*)&qb[idx];
        sq[r][c] = vq.x; sq[r][c+1] = vq.y; sq[r][c+2] = vq.z; sq[r][c+3] = vq.w;
        *(float4*)&sw[r][c] = *(const float4*)&wb[idx];
    }
    __syncthreads();
    const int tx = tid & 15, ty = tid >> 4;
    float acc[4][4];
#pragma unroll
    for (int i = 0; i < 4; i++)
#pragma unroll
        for (int j = 0; j < 4; j++) acc[i][j] = 0.f;
    for (int d = 0; d < 64; d++) {
        float a[4];
#pragma unroll
        for (int i = 0; i < 4; i++) a[i] = sq[ty*4+i][d];
        float4 wv = *(float4*)&sw[d][tx*4];
#pragma unroll
        for (int i = 0; i < 4; i++) {
            acc[i][0] = fmaf(a[i], wv.x, acc[i][0]);
            acc[i][1] = fmaf(a[i], wv.y, acc[i][1]);
            acc[i][2] = fmaf(a[i], wv.z, acc[i][2]);
            acc[i][3] = fmaf(a[i], wv.w, acc[i][3]);
        }
    }
#pragma unroll
    for (int i = 0; i < 4; i++) {
        uint32_t h0,l0v,h1,l1v;
        split2(acc[i][0],acc[i][1],h0,l0v);
        split2(acc[i][2],acc[i][3],h1,l1v);
        size_t row = (size_t)bh*NL + l0 + ty*4 + i;
        *(uint2*)&qh[row*32 + tx*2] = make_uint2(h0,h1);
        *(uint2*)&ql[row*32 + tx*2] = make_uint2(l0v,l1v);
    }
}

// ---------------- launch -----------------------------------------------------
extern "C" void kernel_launch(void* const* d_in, const int* in_sizes, int n_in,
                              void* d_out, int out_size)
{
    const float* queries = (const float*)d_in[0];
    const float* keys    = (const float*)d_in[1];
    const float* values  = (const float*)d_in[2];
    const float* routers = (const float*)d_in[3];
    const float* Wq  = (const float*)d_in[4];
    const float* Wk  = (const float*)d_in[5];
    const float* Wv  = (const float*)d_in[6];
    const float* Wlq = (const float*)d_in[7];
    const float* Wlk = (const float*)d_in[8];
    const float* Wo  = (const float*)d_in[9];
    const float* bo  = (const float*)d_in[10];

    float *q, *rq, *rk, *wep;
    uint32_t *inh, *inl, *rinh, *rinl, *wh, *wl;
    uint32_t *qh, *ql, *kh, *kl, *vth, *vtl, *oth, *otl;
    cudaGetSymbolAddress((void**)&q,    g_q);
    cudaGetSymbolAddress((void**)&rq,   g_rq);
    cudaGetSymbolAddress((void**)&rk,   g_rk);
    cudaGetSymbolAddress((void**)&wep,  g_wep);
    cudaGetSymbolAddress((void**)&inh,  g_inh);
    cudaGetSymbolAddress((void**)&inl,  g_inl);
    cudaGetSymbolAddress((void**)&rinh, g_rinh);
    cudaGetSymbolAddress((void**)&rinl, g_rinl);
    cudaGetSymbolAddress((void**)&wh,   g_wh);
    cudaGetSymbolAddress((void**)&wl,   g_wl);
    cudaGetSymbolAddress((void**)&qh,   g_qh);
    cudaGetSymbolAddress((void**)&ql,   g_ql);
    cudaGetSymbolAddress((void**)&kh,   g_kh);
    cudaGetSymbolAddress((void**)&kl,   g_kl);
    cudaGetSymbolAddress((void**)&vth,  g_vth);
    cudaGetSymbolAddress((void**)&vtl,  g_vtl);
    cudaGetSymbolAddress((void**)&oth,  g_oth);
    cudaGetSymbolAddress((void**)&otl,  g_otl);

    static int attr_done = 0;
    if (!attr_done) {
        cudaFuncSetAttribute(mm_qkv,      cudaFuncAttributeMaxDynamicSharedMemorySize, 196608);
        cudaFuncSetAttribute(mm_projb<0>, cudaFuncAttributeMaxDynamicSharedMemorySize, 196608);
        cudaFuncSetAttribute(mm_projb<1>, cudaFuncAttributeMaxDynamicSharedMemorySize, 196608);
        cudaFuncSetAttribute(flash2,      cudaFuncAttributeMaxDynamicSharedMemorySize, 131072);
        attr_done = 1;
    }

    dim3 blk(256);
    const int n8_big = NB*NL*ND/8;       // 1,048,576
    const int n8_rt  = NB*NG*ND/8;       // 65,536

    // --- all splits up-front (independent buffers, no interleaving) ---
    split_a3<<<dim3(n8_big/256, 3), blk>>>(queries, keys, values, inh, inl, n8_big);
    split_a <<<n8_rt/256, blk>>>(routers, rinh, rinl, n8_rt);
    split_w6<<<dim3(32, 32, 6), blk>>>(Wq, Wk, Wv, Wo, Wlq, Wlk, wh, wl);

    // --- Q/K/V projections in one launch ---
    mm_qkv<<<dim3(64, 8, 3), blk, 196608>>>(inh, inl, wh, wl, q, kh, kl, vth, vtl);

    // --- router projections (both via blockIdx.z) ---
    mm_projb<1><<<dim3(4, 8, 2), blk, 196608>>>(rinh, rinl,
        wh + (size_t)4*WOFS, wl + (size_t)4*WOFS, rq, nullptr, NG,
        wh + (size_t)5*WOFS, wl + (size_t)5*WOFS, rk);

    wep_kernel<<<128, blk>>>(rq, rk, wep);
    qfold_b<<<dim3(16, 128), blk>>>(q, wep, qh, ql);

    flash2<<<dim3(8, 128), blk, 131072>>>(qh, ql, kh, kl, vth, vtl, oth, otl);

    // --- final projection ---
    mm_projb<0><<<dim3(64, 8), blk, 196608>>>(oth, otl,
        wh + (size_t)3*WOFS, wl + (size_t)3*WOFS, (float*)d_out, bo, NL,
        nullptr, nullptr, nullptr);
}

// round 14
// speedup vs baseline: 4.1312x; 1.1872x over previous
#include <cuda_runtime.h>
#include <cuda_fp16.h>
#include <math.h>
#include <stdint.h>

#define NB 8
#define NL 1024
#define NS 1024
#define NG 64
#define ND 1024
#define NH 16
#define DH 64

#define INOFS  (NB*NL*ND/2)
#define RINOFS (NB*NG*ND/2)
#define WOFS   (ND*ND/2)

// ---------------- scratch (device globals) -----------------------------------
__device__ float    g_q  [NB*NH*NL*DH];
__device__ float    g_rq [NB*NH*NG*DH];
__device__ float    g_rk [NB*NH*NG*DH];
__device__ float    g_wep[NB*NH*DH*DH];
__device__ uint32_t g_ah [2*INOFS], g_al [2*INOFS];   // queries,keys hi/lo
__device__ uint32_t g_v1 [INOFS];                      // values single
__device__ uint32_t g_rh [RINOFS],  g_rl [RINOFS];     // routers hi/lo
__device__ uint32_t g_wh [4*WOFS],  g_wl [4*WOFS];     // Wq,Wk,Wlq,Wlk hi/lo
__device__ uint32_t g_w1 [2*WOFS];                     // Wv,Wo single
__device__ uint32_t g_qeh[NB*NH*NL*DH/2], g_qel[NB*NH*NL*DH/2];
__device__ uint32_t g_kh16[NB*NH*NS*DH/2], g_kl16[NB*NH*NS*DH/2];
__device__ uint32_t g_vt16[NB*NH*DH*NS/2];
__device__ uint32_t g_oth16[NB*ND*NL/2],  g_otl16[NB*ND*NL/2];

// ---------------- helpers ----------------------------------------------------
__device__ __forceinline__ uint32_t smem_u32(const void* p){
    uint32_t a;
    asm("{ .reg .u64 t; cvta.to.shared.u64 t, %1; cvt.u32.u64 %0, t; }"
        : "=r"(a) : "l"(p));
    return a;
}
#define SW128(o) ((o) ^ (((o) >> 3) & 0x70))

__device__ __forceinline__ void ldsm4(uint32_t* r, uint32_t a){
    asm volatile("ldmatrix.sync.aligned.m8n8.x4.shared.b16 {%0,%1,%2,%3}, [%4];"
        : "=r"(r[0]), "=r"(r[1]), "=r"(r[2]), "=r"(r[3]) : "r"(a));
}
__device__ __forceinline__ void mma_fp16(float* c, const uint32_t* a, const uint32_t* b){
    asm volatile("mma.sync.aligned.m16n8k16.row.col.f32.f16.f16.f32 "
        "{%0,%1,%2,%3}, {%4,%5,%6,%7}, {%8,%9}, {%0,%1,%2,%3};"
        : "+f"(c[0]), "+f"(c[1]), "+f"(c[2]), "+f"(c[3])
        : "r"(a[0]), "r"(a[1]), "r"(a[2]), "r"(a[3]), "r"(b[0]), "r"(b[1]));
}
__device__ __forceinline__ float ex2f(float x){
    float y; asm("ex2.approx.f32 %0, %1;" : "=f"(y) : "f"(x)); return y;
}
__device__ __forceinline__ void cpa16(uint32_t d, const void* s){
    asm volatile("cp.async.cg.shared.global [%0], [%1], 16;" :: "r"(d), "l"(s));
}
__device__ __forceinline__ void cp_commit(){ asm volatile("cp.async.commit_group;"); }
__device__ __forceinline__ void cp_wait2(){ asm volatile("cp.async.wait_group 2;"); }
__device__ __forceinline__ void cp_wait1(){ asm volatile("cp.async.wait_group 1;"); }
__device__ __forceinline__ void cp_wait0(){ asm volatile("cp.async.wait_group 0;"); }

__device__ __forceinline__ uint32_t pack_h2(float x, float y){
    __half2 h = __floats2half2_rn(x, y);
    return *reinterpret_cast<uint32_t*>(&h);
}
// fp16 hi/lo split of a float pair
__device__ __forceinline__ void split2h(float x, float y, uint32_t& hi, uint32_t& lo){
    __half xh = __float2half_rn(x), yh = __float2half_rn(y);
    __half xl = __float2half_rn(x - __half2float(xh));
    __half yl = __float2half_rn(y - __half2float(yh));
    hi = (uint32_t)__half_as_ushort(xh) | ((uint32_t)__half_as_ushort(yh) << 16);
    lo = (uint32_t)__half_as_ushort(xl) | ((uint32_t)__half_as_ushort(yl) << 16);
}

// ---------------- split kernels ----------------------------------------------
__global__ void __launch_bounds__(256) split_qk(
    const float* __restrict__ q, const float* __restrict__ k,
    uint32_t* __restrict__ hi, uint32_t* __restrict__ lo, int n8)
{
    int g = blockIdx.x*256 + threadIdx.x;
    if (g >= n8) return;
    const float* src = blockIdx.y ? k : q;
    uint32_t* H = hi + (size_t)blockIdx.y*INOFS;
    uint32_t* L = lo + (size_t)blockIdx.y*INOFS;
    float4 a = ((const float4*)src)[g*2];
    float4 b = ((const float4*)src)[g*2+1];
    uint32_t h[4], l[4];
    split2h(a.x,a.y,h[0],l[0]); split2h(a.z,a.w,h[1],l[1]);
    split2h(b.x,b.y,h[2],l[2]); split2h(b.z,b.w,h[3],l[3]);
    ((uint4*)H)[g] = make_uint4(h[0],h[1],h[2],h[3]);
    ((uint4*)L)[g] = make_uint4(l[0],l[1],l[2],l[3]);
}

__global__ void __launch_bounds__(256) split_v(
    const float* __restrict__ A, uint32_t* __restrict__ out, int n8)
{
    int g = blockIdx.x*256 + threadIdx.x;
    if (g >= n8) return;
    float4 a = ((const float4*)A)[g*2];
    float4 b = ((const float4*)A)[g*2+1];
    ((uint4*)out)[g] = make_uint4(pack_h2(a.x,a.y), pack_h2(a.z,a.w),
                                  pack_h2(b.x,b.y), pack_h2(b.z,b.w));
}

__global__ void __launch_bounds__(256) split_r(
    const float* __restrict__ A, uint32_t* __restrict__ hi,
    uint32_t* __restrict__ lo, int n8)
{
    int g = blockIdx.x*256 + threadIdx.x;
    if (g >= n8) return;
    float4 a = ((const float4*)A)[g*2];
    float4 b = ((const float4*)A)[g*2+1];
    uint32_t h[4], l[4];
    split2h(a.x,a.y,h[0],l[0]); split2h(a.z,a.w,h[1],l[1]);
    split2h(b.x,b.y,h[2],l[2]); split2h(b.z,b.w,h[3],l[3]);
    ((uint4*)hi)[g] = make_uint4(h[0],h[1],h[2],h[3]);
    ((uint4*)lo)[g] = make_uint4(l[0],l[1],l[2],l[3]);
}

// transpose + hi/lo split of 4 weights (Wq,Wk,Wlq,Wlk), z selects
__global__ void __launch_bounds__(256) split_w4(
    const float* __restrict__ W0, const float* __restrict__ W1,
    const float* __restrict__ W2, const float* __restrict__ W3,
    uint32_t* __restrict__ th, uint32_t* __restrict__ tl)
{
    __shared__ float t[32][33];
    const int z = blockIdx.z;
    const float* W = (z==0)?W0:(z==1)?W1:(z==2)?W2:W3;
    uint32_t* TH = th + (size_t)z*WOFS;
    uint32_t* TL = tl + (size_t)z*WOFS;
    const int k0 = blockIdx.x*32, n0 = blockIdx.y*32;
    const int tid = threadIdx.x;
    const int c = tid & 31, r = tid >> 5;
#pragma unroll
    for (int i = 0; i < 4; i++)
        t[r + i*8][c] = W[(size_t)(k0 + r + i*8)*1024 + n0 + c];
    __syncthreads();
    const int nl = tid >> 3, kp = (tid & 7)*2;
    uint32_t h0,l0v,h1,l1v;
    split2h(t[kp*2][nl],   t[kp*2+1][nl], h0, l0v);
    split2h(t[kp*2+2][nl], t[kp*2+3][nl], h1, l1v);
    size_t o = (size_t)(n0+nl)*512 + k0/2 + kp;
    *(uint2*)&TH[o] = make_uint2(h0,h1);
    *(uint2*)&TL[o] = make_uint2(l0v,l1v);
}

// transpose + single split of Wv, Wo
__global__ void __launch_bounds__(256) split_w2(
    const float* __restrict__ W0, const float* __restrict__ W1,
    uint32_t* __restrict__ out)
{
    __shared__ float t[32][33];
    const int z = blockIdx.z;
    const float* W = z ? W1 : W0;
    uint32_t* O = out + (size_t)z*WOFS;
    const int k0 = blockIdx.x*32, n0 = blockIdx.y*32;
    const int tid = threadIdx.x;
    const int c = tid & 31, r = tid >> 5;
#pragma unroll
    for (int i = 0; i < 4; i++)
        t[r + i*8][c] = W[(size_t)(k0 + r + i*8)*1024 + n0 + c];
    __syncthreads();
    const int nl = tid >> 3, kp = (tid & 7)*2;
    size_t o = (size_t)(n0+nl)*512 + k0/2 + kp;
    *(uint2*)&O[o] = make_uint2(pack_h2(t[kp*2][nl],   t[kp*2+1][nl]),
                                pack_h2(t[kp*2+2][nl], t[kp*2+3][nl]));
}

// ---------------- GEMM macros ------------------------------------------------
// 3-term (A hi/lo, B hi/lo): stage 64KB x3
#define G3_ISSUE(s, Ah, Al, Bh, Bl) do { \
    const uint32_t base_ = (uint32_t)((s)%3)*65536u; \
    const int k0h_ = (s)*32; \
    _Pragma("unroll") \
    for (int i_ = 0; i_ < 4; i_++) { \
        int f_ = tid + i_*256; \
        int row_ = f_ >> 3, c_ = f_ & 7; \
        uint32_t swo_ = SW128((uint32_t)(row_*128 + c_*16)); \
        cpa16(sb + base_ + swo_,         (Ah) + (size_t)(m0+row_)*512 + k0h_ + c_*4); \
        cpa16(sb + base_ + 16384 + swo_, (Al) + (size_t)(m0+row_)*512 + k0h_ + c_*4); \
        cpa16(sb + base_ + 32768 + swo_, (Bh) + (size_t)(n0+row_)*512 + k0h_ + c_*4); \
        cpa16(sb + base_ + 49152 + swo_, (Bl) + (size_t)(n0+row_)*512 + k0h_ + c_*4); \
    } \
    cp_commit(); \
} while(0)

#define G3_COMPUTE(base) do { \
    _Pragma("unroll") \
    for (int kk = 0; kk < 64; kk += 16) { \
        uint32_t ahf[4][4], alf[4][4], bhf[4][2], blf[4][2]; \
        _Pragma("unroll") \
        for (int mt = 0; mt < 4; mt++) { \
            uint32_t off = SW128((uint32_t)((m0w + mt*16 + a_row)*128 + kk*2 + a_kb)); \
            ldsm4(ahf[mt], sb + (base) + off); \
            ldsm4(alf[mt], sb + (base) + 16384 + off); \
        } \
        _Pragma("unroll") \
        for (int np = 0; np < 2; np++) { \
            uint32_t off = SW128((uint32_t)((n0w + np*16 + b_row)*128 + kk*2 + b_kb)); \
            uint32_t t[4]; \
            ldsm4(t, sb + (base) + 32768 + off); \
            bhf[np*2][0]=t[0]; bhf[np*2][1]=t[1]; bhf[np*2+1][0]=t[2]; bhf[np*2+1][1]=t[3]; \
            ldsm4(t, sb + (base) + 49152 + off); \
            blf[np*2][0]=t[0]; blf[np*2][1]=t[1]; blf[np*2+1][0]=t[2]; blf[np*2+1][1]=t[3]; \
        } \
        _Pragma("unroll") \
        for (int mt = 0; mt < 4; mt++) \
            _Pragma("unroll") \
            for (int nt = 0; nt < 4; nt++) { \
                mma_fp16(acc[mt][nt], ahf[mt], bhf[nt]); \
                mma_fp16(acc[mt][nt], ahf[mt], blf[nt]); \
                mma_fp16(acc[mt][nt], alf[mt], bhf[nt]); \
            } \
    } \
} while(0)

// 1-term: stage 32KB x3
#define G1_ISSUE(s, A16, B16) do { \
    const uint32_t base_ = (uint32_t)((s)%3)*32768u; \
    const int k0h_ = (s)*32; \
    _Pragma("unroll") \
    for (int i_ = 0; i_ < 4; i_++) { \
        int f_ = tid + i_*256; \
        int row_ = f_ >> 3, c_ = f_ & 7; \
        uint32_t swo_ = SW128((uint32_t)(row_*128 + c_*16)); \
        cpa16(sb + base_ + swo_,         (A16) + (size_t)(m0+row_)*512 + k0h_ + c_*4); \
        cpa16(sb + base_ + 16384 + swo_, (B16) + (size_t)(n0+row_)*512 + k0h_ + c_*4); \
    } \
    cp_commit(); \
} while(0)

#define G1_COMPUTE(base) do { \
    _Pragma("unroll") \
    for (int kk = 0; kk < 64; kk += 16) { \
        uint32_t af[4][4], bf[4][2]; \
        _Pragma("unroll") \
        for (int mt = 0; mt < 4; mt++) \
            ldsm4(af[mt], sb + (base) + SW128((uint32_t)((m0w + mt*16 + a_row)*128 + kk*2 + a_kb))); \
        _Pragma("unroll") \
        for (int np = 0; np < 2; np++) { \
            uint32_t t[4]; \
            ldsm4(t, sb + (base) + 16384 + SW128((uint32_t)((n0w + np*16 + b_row)*128 + kk*2 + b_kb))); \
            bf[np*2][0]=t[0]; bf[np*2][1]=t[1]; bf[np*2+1][0]=t[2]; bf[np*2+1][1]=t[3]; \
        } \
        _Pragma("unroll") \
        for (int mt = 0; mt < 4; mt++) \
            _Pragma("unroll") \
            for (int nt = 0; nt < 4; nt++) \
                mma_fp16(acc[mt][nt], af[mt], bf[nt]); \
    } \
} while(0)

// 2-term (A hi/lo, B single): stage 48KB x3
#define G2_ISSUE(s, Ah, Al, B16) do { \
    const uint32_t base_ = (uint32_t)((s)%3)*49152u; \
    const int k0h_ = (s)*32; \
    _Pragma("unroll") \
    for (int i_ = 0; i_ < 4; i_++) { \
        int f_ = tid + i_*256; \
        int row_ = f_ >> 3, c_ = f_ & 7; \
        uint32_t swo_ = SW128((uint32_t)(row_*128 + c_*16)); \
        cpa16(sb + base_ + swo_,         (Ah) + (size_t)(m0+row_)*512 + k0h_ + c_*4); \
        cpa16(sb + base_ + 16384 + swo_, (Al) + (size_t)(m0+row_)*512 + k0h_ + c_*4); \
        cpa16(sb + base_ + 32768 + swo_, (B16) + (size_t)(n0+row_)*512 + k0h_ + c_*4); \
    } \
    cp_commit(); \
} while(0)

#define G2_COMPUTE(base) do { \
    _Pragma("unroll") \
    for (int kk = 0; kk < 64; kk += 16) { \
        uint32_t ahf[4][4], alf[4][4], bf[4][2]; \
        _Pragma("unroll") \
        for (int mt = 0; mt < 4; mt++) { \
            uint32_t off = SW128((uint32_t)((m0w + mt*16 + a_row)*128 + kk*2 + a_kb)); \
            ldsm4(ahf[mt], sb + (base) + off); \
            ldsm4(alf[mt], sb + (base) + 16384 + off); \
        } \
        _Pragma("unroll") \
        for (int np = 0; np < 2; np++) { \
            uint32_t t[4]; \
            ldsm4(t, sb + (base) + 32768 + SW128((uint32_t)((n0w + np*16 + b_row)*128 + kk*2 + b_kb))); \
            bf[np*2][0]=t[0]; bf[np*2][1]=t[1]; bf[np*2+1][0]=t[2]; bf[np*2+1][1]=t[3]; \
        } \
        _Pragma("unroll") \
        for (int mt = 0; mt < 4; mt++) \
            _Pragma("unroll") \
            for (int nt = 0; nt < 4; nt++) { \
                mma_fp16(acc[mt][nt], ahf[mt], bf[nt]); \
                mma_fp16(acc[mt][nt], alf[mt], bf[nt]); \
            } \
    } \
} while(0)

#define STAGE_ACC() do { \
    const int g = lid >> 2, tg = lid & 3; \
    _Pragma("unroll") \
    for (int mt = 0; mt < 4; mt++) \
        _Pragma("unroll") \
        for (int nt = 0; nt < 4; nt++) { \
            int r = m0w + mt*16 + g, c = n0w + nt*8 + tg*2; \
            *(float2*)&stg[r*132 + c]     = make_float2(acc[mt][nt][0], acc[mt][nt][1]); \
            *(float2*)&stg[(r+8)*132 + c] = make_float2(acc[mt][nt][2], acc[mt][nt][3]); \
        } \
} while(0)

#define WARP_COORDS() \
    const int m0w = (wid & 1)*64, n0w = (wid >> 1)*32; \
    const int a_row = (lid & 7) + ((lid >> 3) & 1)*8; \
    const int a_kb  = (lid >> 4)*16; \
    const int b_row = (lid & 7) + ((lid >> 4) & 1)*8; \
    const int b_kb  = ((lid >> 3) & 1)*16

#define ACC_INIT() \
    float acc[4][4][4]; \
    _Pragma("unroll") \
    for (int i = 0; i < 4; i++) \
        _Pragma("unroll") \
        for (int j = 0; j < 4; j++) \
            _Pragma("unroll") \
            for (int e = 0; e < 4; e++) acc[i][j][e] = 0.f

// ============= mm_qk: Q and K projections (3-term) ===========================
// z=0: Q -> fp32 head-split. z=1: K -> hi/lo packed head-split.
__global__ void __launch_bounds__(256,1) mm_qk(
    const uint32_t* __restrict__ ah, const uint32_t* __restrict__ al,
    const uint32_t* __restrict__ wh, const uint32_t* __restrict__ wl,
    float* __restrict__ qout,
    uint32_t* __restrict__ kh16, uint32_t* __restrict__ kl16)
{
    extern __shared__ char smem[];
    const uint32_t sb = smem_u32(smem);
    const int tid = threadIdx.x, lid = tid & 31, wid = tid >> 5;
    const int m0 = blockIdx.x*128, n0 = blockIdx.y*128;
    const int z = blockIdx.z;
    const uint32_t* Ah = ah + (size_t)z*INOFS;
    const uint32_t* Al = al + (size_t)z*INOFS;
    const uint32_t* Bh = wh + (size_t)z*WOFS;
    const uint32_t* Bl = wl + (size_t)z*WOFS;
    WARP_COORDS();
    ACC_INIT();

    G3_ISSUE(0, Ah, Al, Bh, Bl);
    G3_ISSUE(1, Ah, Al, Bh, Bl);
    for (int s = 0; s < 16; s++) {
        if (s <= 13) { G3_ISSUE(s+2, Ah, Al, Bh, Bl); cp_wait2(); }
        else if (s == 14) cp_wait1();
        else cp_wait0();
        __syncthreads();
        G3_COMPUTE((uint32_t)(s % 3)*65536u);
        __syncthreads();
    }

    float* stg = (float*)smem;
    STAGE_ACC();
    __syncthreads();

    if (z == 0) {
#pragma unroll
        for (int i = 0; i < 16; i++) {
            int f = tid + i*256;
            int r = f >> 5, c4 = f & 31;
            float4 val = *(float4*)&stg[r*132 + c4*4];
            int m = m0 + r, n = n0 + c4*4;
            int bq = m >> 10, t = m & 1023;
            int h = n >> 6, d = n & 63;
            *(float4*)&qout[(size_t)((bq*NH + h)*1024 + t)*64 + d] = val;
        }
    } else {
#pragma unroll
        for (int i = 0; i < 16; i++) {
            int f = tid + i*256;
            int r = f >> 5, c4 = f & 31;
            float4 val = *(float4*)&stg[r*132 + c4*4];
            int m = m0 + r, n = n0 + c4*4;
            int bq = m >> 10, t = m & 1023;
            int h = n >> 6, d = n & 63;
            uint32_t h0,l0v,h1,l1v;
            split2h(val.x,val.y,h0,l0v); split2h(val.z,val.w,h1,l1v);
            size_t o = ((size_t)(bq*NH + h)*1024 + t)*32 + (d >> 1);
            *(uint2*)&kh16[o] = make_uint2(h0,h1);
            *(uint2*)&kl16[o] = make_uint2(l0v,l1v);
        }
    }
}

// ============= mm_rt: router projections (3-term, tiny) ======================
__global__ void __launch_bounds__(256,1) mm_rt(
    const uint32_t* __restrict__ rh, const uint32_t* __restrict__ rl,
    const uint32_t* __restrict__ wh, const uint32_t* __restrict__ wl,
    float* __restrict__ rqout, float* __restrict__ rkout)
{
    extern __shared__ char smem[];
    const uint32_t sb = smem_u32(smem);
    const int tid = threadIdx.x, lid = tid & 31, wid = tid >> 5;
    const int m0 = blockIdx.x*128, n0 = blockIdx.y*128;
    const int z = blockIdx.z;
    const uint32_t* Ah = rh;
    const uint32_t* Al = rl;
    const uint32_t* Bh = wh + (size_t)(2+z)*WOFS;
    const uint32_t* Bl = wl + (size_t)(2+z)*WOFS;
    float* Yf = z ? rkout : rqout;
    WARP_COORDS();
    ACC_INIT();

    G3_ISSUE(0, Ah, Al, Bh, Bl);
    G3_ISSUE(1, Ah, Al, Bh, Bl);
    for (int s = 0; s < 16; s++) {
        if (s <= 13) { G3_ISSUE(s+2, Ah, Al, Bh, Bl); cp_wait2(); }
        else if (s == 14) cp_wait1();
        else cp_wait0();
        __syncthreads();
        G3_COMPUTE((uint32_t)(s % 3)*65536u);
        __syncthreads();
    }

    float* stg = (float*)smem;
    STAGE_ACC();
    __syncthreads();
#pragma unroll
    for (int i = 0; i < 16; i++) {
        int f = tid + i*256;
        int r = f >> 5, c4 = f & 31;
        float4 val = *(float4*)&stg[r*132 + c4*4];
        int m = m0 + r, n = n0 + c4*4;
        int bq = m / NG, t = m - bq*NG;
        int h = n >> 6, d = n & 63;
        *(float4*)&Yf[(size_t)((bq*NH + h)*NG + t)*64 + d] = val;
    }
}

// ============= mm_v: V projection (1-term) -> transposed packed fp16 =========
__global__ void __launch_bounds__(256,1) mm_v(
    const uint32_t* __restrict__ A16, const uint32_t* __restrict__ B16,
    uint32_t* __restrict__ vt16)
{
    extern __shared__ char smem[];
    const uint32_t sb = smem_u32(smem);
    const int tid = threadIdx.x, lid = tid & 31, wid = tid >> 5;
    const int m0 = blockIdx.x*128, n0 = blockIdx.y*128;
    WARP_COORDS();
    ACC_INIT();

    G1_ISSUE(0, A16, B16);
    G1_ISSUE(1, A16, B16);
    for (int s = 0; s < 16; s++) {
        if (s <= 13) { G1_ISSUE(s+2, A16, B16); cp_wait2(); }
        else if (s == 14) cp_wait1();
        else cp_wait0();
        __syncthreads();
        G1_COMPUTE((uint32_t)(s % 3)*32768u);
        __syncthreads();
    }

    float* stg = (float*)smem;
    STAGE_ACC();
    __syncthreads();
    {
        const int nl = tid & 127, half = tid >> 7;
        const int n = n0 + nl;
        const int hh = n >> 6, d = n & 63;
        const int bq = m0 >> 10;
        const size_t rowv = ((size_t)(bq*NH + hh)*64 + d)*512;
        const int tbase = (m0 & 1023) + half*64;
#pragma unroll
        for (int j = 0; j < 8; j++) {
            float x[8];
#pragma unroll
            for (int e = 0; e < 8; e++) x[e] = stg[(half*64 + j*8 + e)*132 + nl];
            size_t o = rowv + (size_t)(tbase + j*8)/2;
            *(uint4*)&vt16[o] = make_uint4(pack_h2(x[0],x[1]), pack_h2(x[2],x[3]),
                                           pack_h2(x[4],x[5]), pack_h2(x[6],x[7]));
        }
    }
}

// ============= mm_fin: final projection (2-term: ot hi/lo, Wo single) ========
__global__ void __launch_bounds__(256,1) mm_fin(
    const uint32_t* __restrict__ Ah, const uint32_t* __restrict__ Al,
    const uint32_t* __restrict__ B16,
    float* __restrict__ Yf, const float* __restrict__ bias)
{
    extern __shared__ char smem[];
    const uint32_t sb = smem_u32(smem);
    const int tid = threadIdx.x, lid = tid & 31, wid = tid >> 5;
    const int m0 = blockIdx.x*128, n0 = blockIdx.y*128;
    WARP_COORDS();
    ACC_INIT();

    G2_ISSUE(0, Ah, Al, B16);
    G2_ISSUE(1, Ah, Al, B16);
    for (int s = 0; s < 16; s++) {
        if (s <= 13) { G2_ISSUE(s+2, Ah, Al, B16); cp_wait2(); }
        else if (s == 14) cp_wait1();
        else cp_wait0();
        __syncthreads();
        G2_COMPUTE((uint32_t)(s % 3)*49152u);
        __syncthreads();
    }

    float* stg = (float*)smem;
    STAGE_ACC();
    __syncthreads();
#pragma unroll
    for (int i = 0; i < 16; i++) {
        int f = tid + i*256;
        int r = f >> 5, c4 = f & 31;
        float4 val = *(float4*)&stg[r*132 + c4*4];
        int m = m0 + r, n = n0 + c4*4;
        float4 bb = *(const float4*)&bias[n];
        val.x += bb.x; val.y += bb.y; val.z += bb.z; val.w += bb.w;
        *(float4*)&Yf[(size_t)m*1024 + n] = val;
    }
}

// ============= flash3: scores 3-term (qe,k hi/lo), PV 2-term =================
// smem: Qh@0 16K | Ql@16384 | stages@32768 + (s%3)*24576: { Kh 8K | Kl 8K | V 8K }
__global__ void __launch_bounds__(256,1) flash3(
    const uint32_t* __restrict__ qeh, const uint32_t* __restrict__ qel,
    const uint32_t* __restrict__ kh16, const uint32_t* __restrict__ kl16,
    const uint32_t* __restrict__ vt16,
    uint32_t* __restrict__ oth16, uint32_t* __restrict__ otl16)
{
    extern __shared__ char smem[];
    const uint32_t sb = smem_u32(smem);
    const int tid = threadIdx.x, lid = tid & 31, wid = tid >> 5;
    const int l0 = blockIdx.x*128, bh = blockIdx.y;
    const int m0w = wid*16;

    const int a_row = (lid & 7) + ((lid >> 3) & 1)*8;
    const int a_kb  = (lid >> 4)*16;
    const int b_row = (lid & 7) + ((lid >> 4) & 1)*8;
    const int b_kb  = ((lid >> 3) & 1)*16;

    // Q tiles (hi/lo)
#pragma unroll
    for (int i = 0; i < 4; i++) {
        int f = tid + i*256;
        int row = f >> 3, c = f & 7;
        uint32_t swo = SW128((uint32_t)(row*128 + c*16));
        size_t src = (size_t)(bh*NL + l0 + row)*32 + c*4;
        *(uint4*)(smem + swo)         = *(const uint4*)(qeh + src);
        *(uint4*)(smem + 16384 + swo) = *(const uint4*)(qel + src);
    }

#define FL3_ISSUE(s) do { \
    const uint32_t base_ = 32768u + (uint32_t)((s) % 3)*24576u; \
    const int s0h_ = (s)*32; \
    _Pragma("unroll") \
    for (int i_ = 0; i_ < 2; i_++) { \
        int f_ = tid + i_*256; \
        int row_ = f_ >> 3, c_ = f_ & 7; \
        uint32_t swo_ = SW128((uint32_t)(row_*128 + c_*16)); \
        size_t ks_ = (size_t)(bh*NS + (s)*64 + row_)*32 + c_*4; \
        cpa16(sb + base_ + swo_,         kh16 + ks_); \
        cpa16(sb + base_ + 8192 + swo_,  kl16 + ks_); \
        cpa16(sb + base_ + 16384 + swo_, vt16 + ((size_t)bh*64 + row_)*512 + s0h_ + c_*4); \
    } \
    cp_commit(); \
} while(0)

    float o[8][4];
#pragma unroll
    for (int nt = 0; nt < 8; nt++)
#pragma unroll
        for (int e = 0; e < 4; e++) o[nt][e] = 0.f;
    float m_a = -1e30f, m_b = -1e30f, l_a = 0.f, l_b = 0.f;

    FL3_ISSUE(0);
    FL3_ISSUE(1);
    for (int s = 0; s < 16; s++) {
        if (s <= 13) { FL3_ISSUE(s+2); cp_wait2(); }
        else if (s == 14) cp_wait1();
        else cp_wait0();
        __syncthreads();
        const uint32_t base = 32768u + (uint32_t)(s % 3)*24576u;

        // ---- scores: 3-term ----
        float sc[8][4];
#pragma unroll
        for (int nt = 0; nt < 8; nt++)
#pragma unroll
            for (int e = 0; e < 4; e++) sc[nt][e] = 0.f;
#pragma unroll
        for (int kk = 0; kk < 64; kk += 16) {
            uint32_t ahf[4], alf[4];
            uint32_t offA = SW128((uint32_t)((m0w + a_row)*128 + kk*2 + a_kb));
            ldsm4(ahf, sb + offA);
            ldsm4(alf, sb + 16384 + offA);
#pragma unroll
            for (int np = 0; np < 4; np++) {
                uint32_t offB = SW128((uint32_t)((np*16 + b_row)*128 + kk*2 + b_kb));
                uint32_t th[4], tl[4];
                ldsm4(th, sb + base + offB);
                ldsm4(tl, sb + base + 8192 + offB);
                uint32_t bh0[2] = {th[0], th[1]}, bh1[2] = {th[2], th[3]};
                uint32_t bl0[2] = {tl[0], tl[1]}, bl1[2] = {tl[2], tl[3]};
                mma_fp16(sc[2*np],   ahf, bh0);
                mma_fp16(sc[2*np+1], ahf, bh1);
                mma_fp16(sc[2*np],   ahf, bl0);
                mma_fp16(sc[2*np+1], ahf, bl1);
                mma_fp16(sc[2*np],   alf, bh0);
                mma_fp16(sc[2*np+1], alf, bh1);
            }
        }

        // ---- online softmax (log2 domain) ----
        float mxa = -1e30f, mxb = -1e30f;
#pragma unroll
        for (int nt = 0; nt < 8; nt++) {
            mxa = fmaxf(mxa, fmaxf(sc[nt][0], sc[nt][1]));
            mxb = fmaxf(mxb, fmaxf(sc[nt][2], sc[nt][3]));
        }
        mxa = fmaxf(mxa, __shfl_xor_sync(0xffffffffu, mxa, 1));
        mxa = fmaxf(mxa, __shfl_xor_sync(0xffffffffu, mxa, 2));
        mxb = fmaxf(mxb, __shfl_xor_sync(0xffffffffu, mxb, 1));
        mxb = fmaxf(mxb, __shfl_xor_sync(0xffffffffu, mxb, 2));
        float na = fmaxf(m_a, mxa), nb = fmaxf(m_b, mxb);
        float fa = ex2f(m_a - na), fb = ex2f(m_b - nb);
        m_a = na; m_b = nb;
        float sa = 0.f, sbv = 0.f;
#pragma unroll
        for (int nt = 0; nt < 8; nt++) {
            sc[nt][0] = ex2f(sc[nt][0] - na);
            sc[nt][1] = ex2f(sc[nt][1] - na);
            sc[nt][2] = ex2f(sc[nt][2] - nb);
            sc[nt][3] = ex2f(sc[nt][3] - nb);
            sa  += sc[nt][0] + sc[nt][1];
            sbv += sc[nt][2] + sc[nt][3];
        }
        sa  += __shfl_xor_sync(0xffffffffu, sa, 1);
        sa  += __shfl_xor_sync(0xffffffffu, sa, 2);
        sbv += __shfl_xor_sync(0xffffffffu, sbv, 1);
        sbv += __shfl_xor_sync(0xffffffffu, sbv, 2);
        l_a = l_a*fa + sa;
        l_b = l_b*fb + sbv;
#pragma unroll
        for (int nt = 0; nt < 8; nt++) {
            o[nt][0] *= fa; o[nt][1] *= fa;
            o[nt][2] *= fb; o[nt][3] *= fb;
        }

        // ---- PV: 2-term (P hi/lo in regs, V single) ----
#pragma unroll
        for (int j = 0; j < 4; j++) {
            uint32_t pah[4], pal[4];
            split2h(sc[2*j][0],   sc[2*j][1],   pah[0], pal[0]);
            split2h(sc[2*j][2],   sc[2*j][3],   pah[1], pal[1]);
            split2h(sc[2*j+1][0], sc[2*j+1][1], pah[2], pal[2]);
            split2h(sc[2*j+1][2], sc[2*j+1][3], pah[3], pal[3]);
#pragma unroll
            for (int ng = 0; ng < 4; ng++) {
                uint32_t t[4];
                ldsm4(t, sb + base + 16384 +
                      SW128((uint32_t)((ng*16 + b_row)*128 + j*32 + b_kb)));
                uint32_t v0[2] = {t[0], t[1]}, v1[2] = {t[2], t[3]};
                mma_fp16(o[2*ng],   pah, v0);
                mma_fp16(o[2*ng+1], pah, v1);
                mma_fp16(o[2*ng],   pal, v0);
                mma_fp16(o[2*ng+1], pal, v1);
            }
        }
        __syncthreads();
    }

    // ---- epilogue: normalize, stage (pitch 66), hi/lo transposed write ----
    float* stg = (float*)smem;
    {
        float inva = 1.f / l_a, invb = 1.f / l_b;
        const int g = lid >> 2, tg = lid & 3;
#pragma unroll
        for (int nt = 0; nt < 8; nt++) {
            int r = m0w + g, c = nt*8 + tg*2;
            *(float2*)&stg[r*66 + c]     = make_float2(o[nt][0]*inva, o[nt][1]*inva);
            *(float2*)&stg[(r+8)*66 + c] = make_float2(o[nt][2]*invb, o[nt][3]*invb);
        }
    }
    __syncthreads();
    {
        const int d = tid & 63, quarter = tid >> 6;
        const size_t rowo = ((size_t)bh*64 + d)*512;
        const int lbase = l0 + quarter*32;
#pragma unroll
        for (int j = 0; j < 4; j++) {
            float x[8];
#pragma unroll
            for (int e = 0; e < 8; e++) x[e] = stg[(quarter*32 + j*8 + e)*66 + d];
            uint32_t h[4], l[4];
            split2h(x[0],x[1],h[0],l[0]); split2h(x[2],x[3],h[1],l[1]);
            split2h(x[4],x[5],h[2],l[2]); split2h(x[6],x[7],h[3],l[3]);
            size_t oo = rowo + (size_t)(lbase + j*8)/2;
            *(uint4*)&oth16[oo] = make_uint4(h[0],h[1],h[2],h[3]);
            *(uint4*)&otl16[oo] = make_uint4(l[0],l[1],l[2],l[3]);
        }
    }
}

// ---------------- small fp32 kernels -----------------------------------------
__global__ void __launch_bounds__(256) wep_kernel(
    const float* __restrict__ rq, const float* __restrict__ rk,
    float* __restrict__ wep)
{
    __shared__ float sq[64][65];
    __shared__ float sk[64][65];
    const int bh = blockIdx.x;
    const float* rqb = rq + (bh << 12);
    const float* rkb = rk + (bh << 12);
    const int tid = threadIdx.x;
#pragma unroll
    for (int i = 0; i < 4; i++) {
        int idx = (tid + i*256) << 2;
        int r = idx >> 6, c = idx & 63;
        float4 a = *(const float4*)&rqb[idx];
        float4 b = *(const float4*)&rkb[idx];
        sq[r][c] = a.x; sq[r][c+1] = a.y; sq[r][c+2] = a.z; sq[r][c+3] = a.w;
        sk[r][c] = b.x; sk[r][c+1] = b.y; sk[r][c+2] = b.z; sk[r][c+3] = b.w;
    }
    __syncthreads();
    const int tx = tid & 15, ty = tid >> 4;
    float acc[4][4];
#pragma unroll
    for (int i = 0; i < 4; i++)
#pragma unroll
        for (int j = 0; j < 4; j++) acc[i][j] = 0.f;
    for (int g = 0; g < 64; g++) {
        float a[4], b[4];
#pragma unroll
        for (int i = 0; i < 4; i++) a[i] = sq[g][ty*4+i];
#pragma unroll
        for (int j = 0; j < 4; j++) b[j] = sk[g][tx*4+j];
#pragma unroll
        for (int i = 0; i < 4; i++)
#pragma unroll
            for (int j = 0; j < 4; j++)
                acc[i][j] = fmaf(a[i], b[j], acc[i][j]);
    }
    const float scale = 0.125f * 1.4426950408889634f;  // 1/sqrt(64) * log2(e)
#pragma unroll
    for (int i = 0; i < 4; i++) {
        float4 r4 = make_float4(acc[i][0]*scale, acc[i][1]*scale,
                                acc[i][2]*scale, acc[i][3]*scale);
        *(float4*)&wep[(bh << 12) + (ty*4+i)*64 + tx*4] = r4;
    }
}

// qe = q @ W_ep (fp32), output hi/lo fp16
__global__ void __launch_bounds__(256) qfold_b(
    const float* __restrict__ q, const float* __restrict__ wep,
    uint32_t* __restrict__ qeh, uint32_t* __restrict__ qel)
{
    __shared__ float sq[64][65];
    __shared__ float sw[64][68];
    const int bh = blockIdx.y;
    const int l0 = blockIdx.x * 64;
    const float* qb = q + (((size_t)bh * NL + l0) << 6);
    const float* wb = wep + (bh << 12);
    const int tid = threadIdx.x;
#pragma unroll
    for (int i = 0; i < 4; i++) {
        int idx = (tid + i*256) << 2;
        int r = idx >> 6, c = idx & 63;
        float4 vq = *(const float4*)&qb[idx];
        sq[r][c] = vq.x; sq[r][c+1] = vq.y; sq[r][c+2] = vq.z; sq[r][c+3] = vq.w;
        *(float4*)&sw[r][c] = *(const float4*)&wb[idx];
    }
    __syncthreads();
    const int tx = tid & 15, ty = tid >> 4;
    float acc[4][4];
#pragma unroll
    for (int i = 0; i < 4; i++)
#pragma unroll
        for (int j = 0; j < 4; j++) acc[i][j] = 0.f;
    for (int d = 0; d < 64; d++) {
        float a[4];
#pragma unroll
        for (int i = 0; i < 4; i++) a[i] = sq[ty*4+i][d];
        float4 wv = *(float4*)&sw[d][tx*4];
#pragma unroll
        for (int i = 0; i < 4; i++) {
            acc[i][0] = fmaf(a[i], wv.x, acc[i][0]);
            acc[i][1] = fmaf(a[i], wv.y, acc[i][1]);
            acc[i][2] = fmaf(a[i], wv.z, acc[i][2]);
            acc[i][3] = fmaf(a[i], wv.w, acc[i][3]);
        }
    }
#pragma unroll
    for (int i = 0; i < 4; i++) {
        uint32_t h0,l0v,h1,l1v;
        split2h(acc[i][0],acc[i][1],h0,l0v);
        split2h(acc[i][2],acc[i][3],h1,l1v);
        size_t row = (size_t)bh*NL + l0 + ty*4 + i;
        *(uint2*)&qeh[row*32 + tx*2] = make_uint2(h0,h1);
        *(uint2*)&qel[row*32 + tx*2] = make_uint2(l0v,l1v);
    }
}

// ---------------- launch -----------------------------------------------------
extern "C" void kernel_launch(void* const* d_in, const int* in_sizes, int n_in,
                              void* d_out, int out_size)
{
    const float* queries = (const float*)d_in[0];
    const float* keys    = (const float*)d_in[1];
    const float* values  = (const float*)d_in[2];
    const float* routers = (const float*)d_in[3];
    const float* Wq  = (const float*)d_in[4];
    const float* Wk  = (const float*)d_in[5];
    const float* Wv  = (const float*)d_in[6];
    const float* Wlq = (const float*)d_in[7];
    const float* Wlk = (const float*)d_in[8];
    const float* Wo  = (const float*)d_in[9];
    const float* bo  = (const float*)d_in[10];

    float *q, *rq, *rk, *wep;
    uint32_t *ah, *al, *v1, *rh, *rl, *wh, *wl, *w1;
    uint32_t *qeh, *qel, *kh16, *kl16, *vt16, *oth16, *otl16;
    cudaGetSymbolAddress((void**)&q,     g_q);
    cudaGetSymbolAddress((void**)&rq,    g_rq);
    cudaGetSymbolAddress((void**)&rk,    g_rk);
    cudaGetSymbolAddress((void**)&wep,   g_wep);
    cudaGetSymbolAddress((void**)&ah,    g_ah);
    cudaGetSymbolAddress((void**)&al,    g_al);
    cudaGetSymbolAddress((void**)&v1,    g_v1);
    cudaGetSymbolAddress((void**)&rh,    g_rh);
    cudaGetSymbolAddress((void**)&rl,    g_rl);
    cudaGetSymbolAddress((void**)&wh,    g_wh);
    cudaGetSymbolAddress((void**)&wl,    g_wl);
    cudaGetSymbolAddress((void**)&w1,    g_w1);
    cudaGetSymbolAddress((void**)&qeh,   g_qeh);
    cudaGetSymbolAddress((void**)&qel,   g_qel);
    cudaGetSymbolAddress((void**)&kh16,  g_kh16);
    cudaGetSymbolAddress((void**)&kl16,  g_kl16);
    cudaGetSymbolAddress((void**)&vt16,  g_vt16);
    cudaGetSymbolAddress((void**)&oth16, g_oth16);
    cudaGetSymbolAddress((void**)&otl16, g_otl16);

    static int attr_done = 0;
    if (!attr_done) {
        cudaFuncSetAttribute(mm_qk,  cudaFuncAttributeMaxDynamicSharedMemorySize, 196608);
        cudaFuncSetAttribute(mm_rt,  cudaFuncAttributeMaxDynamicSharedMemorySize, 196608);
        cudaFuncSetAttribute(mm_v,   cudaFuncAttributeMaxDynamicSharedMemorySize, 98304);
        cudaFuncSetAttribute(mm_fin, cudaFuncAttributeMaxDynamicSharedMemorySize, 147456);
        cudaFuncSetAttribute(flash3, cudaFuncAttributeMaxDynamicSharedMemorySize, 106496);
        attr_done = 1;
    }

    dim3 blk(256);
    const int n8_big = NB*NL*ND/8;
    const int n8_rt  = NB*NG*ND/8;

    split_qk<<<dim3(n8_big/256, 2), blk>>>(queries, keys, ah, al, n8_big);
    split_v <<<n8_big/256, blk>>>(values, v1, n8_big);
    split_r <<<n8_rt/256, blk>>>(routers, rh, rl, n8_rt);
    split_w4<<<dim3(32, 32, 4), blk>>>(Wq, Wk, Wlq, Wlk, wh, wl);
    split_w2<<<dim3(32, 32, 2), blk>>>(Wv, Wo, w1);

    mm_qk<<<dim3(64, 8, 2), blk, 196608>>>(ah, al, wh, wl, q, kh16, kl16);
    mm_v <<<dim3(64, 8),    blk, 98304>>>(v1, w1, vt16);
    mm_rt<<<dim3(4, 8, 2),  blk, 196608>>>(rh, rl, wh, wl, rq, rk);

    wep_kernel<<<128, blk>>>(rq, rk, wep);
    qfold_b<<<dim3(16, 128), blk>>>(q, wep, qeh, qel);

    flash3<<<dim3(8, 128), blk, 106496>>>(qeh, qel, kh16, kl16, vt16, oth16, otl16);

    mm_fin<<<dim3(64, 8), blk, 147456>>>(oth16, otl16, w1 + (size_t)WOFS,
                                         (float*)d_out, bo);
}